// round 6
// baseline (speedup 1.0000x reference)
#include <cuda_runtime.h>
#include <cuda_bf16.h>
#include <math.h>
#include <stdint.h>

// ---------------- problem constants ----------------
#define BATCH 2
#define CDIM 96
#define HEADS 2
#define CH 48
#define QKV 288
#define HID 255
#define HIDP 256
#define H2 510
#define NPIX 131072

typedef __nv_bfloat16 bf16;

// ---------------- device scratch ----------------
__device__ __align__(256) bf16 g_t0[(size_t)NPIX * QKV];
__device__ __align__(256) bf16 g_t1[(size_t)NPIX * QKV];
__device__ __align__(256) bf16 g_h1[(size_t)NPIX * HIDP];  // ffn hidden x1 (stride 256)
__device__ __align__(256) bf16 g_h2[(size_t)NPIX * HIDP];  // ffn hidden x2 (stride 256)
__device__ __align__(256) bf16 g_gt[(size_t)NPIX * HIDP];  // gated (stride 256)
__device__ __align__(256) bf16 g_ybf[(size_t)NPIX * CDIM];
__device__ __align__(256) float g_x2[(size_t)NPIX * CDIM];
__device__ float g_nrm[2 * BATCH * CDIM];
__device__ float g_att[BATCH * HEADS * CH * CH];
__device__ __align__(256) bf16 g_wq[CDIM * QKV];
__device__ __align__(256) bf16 g_wa[CDIM * CDIM];
__device__ __align__(256) bf16 g_wi[CDIM * H2];
__device__ __align__(256) bf16 g_wo[HID * CDIM];
__device__ __align__(256) float g_kw1[9 * 256];   // dwgate weights x1, padded/aligned
__device__ __align__(256) float g_kw2[9 * 256];   // dwgate weights x2

// ---------------- helpers ----------------
__device__ __forceinline__ float gelu_exact(float v) {
    return 0.5f * v * (1.0f + erff(v * 0.70710678118654752f));
}
__device__ __forceinline__ void ldsm_x4(uint32_t* r, uint32_t addr) {
    asm volatile("ldmatrix.sync.aligned.m8n8.x4.shared.b16 {%0,%1,%2,%3}, [%4];"
        : "=r"(r[0]), "=r"(r[1]), "=r"(r[2]), "=r"(r[3]) : "r"(addr));
}
__device__ __forceinline__ void ldsm_x4_t(uint32_t* r, uint32_t addr) {
    asm volatile("ldmatrix.sync.aligned.m8n8.x4.trans.shared.b16 {%0,%1,%2,%3}, [%4];"
        : "=r"(r[0]), "=r"(r[1]), "=r"(r[2]), "=r"(r[3]) : "r"(addr));
}
__device__ __forceinline__ void mma_bf16(float* c, const uint32_t* a, const uint32_t* b) {
    asm volatile("mma.sync.aligned.m16n8k16.row.col.f32.bf16.bf16.f32 "
        "{%0,%1,%2,%3}, {%4,%5,%6,%7}, {%8,%9}, {%0,%1,%2,%3};\n"
        : "+f"(c[0]), "+f"(c[1]), "+f"(c[2]), "+f"(c[3])
        : "r"(a[0]), "r"(a[1]), "r"(a[2]), "r"(a[3]), "r"(b[0]), "r"(b[1]));
}
__device__ __forceinline__ uint32_t pack_bf2(float a, float b) {
    __nv_bfloat162 h = __floats2bfloat162_rn(a, b);
    return *(uint32_t*)&h;
}

// ---------------- weight convert + dwgate weight remap + accumulator init ----------------
__global__ void cvt_all_kernel(const float* wq, const float* wa, const float* wi, const float* wo,
                               const float* fdw,
                               bf16* dq, bf16* da, bf16* di, bf16* dxo,
                               float* kw1, float* kw2, float* nrm, float* attn) {
    int i = blockIdx.x * blockDim.x + threadIdx.x;
    const int s0 = CDIM * QKV, s1 = s0 + CDIM * CDIM, s2 = s1 + CDIM * H2, s3 = s2 + HID * CDIM;
    if (i < s0) dq[i] = __float2bfloat16_rn(wq[i]);
    else if (i < s1) da[i - s0] = __float2bfloat16_rn(wa[i - s0]);
    else if (i < s2) di[i - s1] = __float2bfloat16_rn(wi[i - s1]);
    else if (i < s3) dxo[i - s2] = __float2bfloat16_rn(wo[i - s2]);
    if (i < 9 * 256) {
        int dydx = i >> 8, j = i & 255;
        kw1[i] = (j < HID) ? fdw[dydx * H2 + j] : 0.f;
        kw2[i] = (j < HID) ? fdw[dydx * H2 + HID + j] : 0.f;
    }
    if (i < 2 * BATCH * CDIM) nrm[i] = 0.f;
    if (i < BATCH * HEADS * CH * CH) attn[i] = 0.f;
}

// ---------------- per-pixel LayerNorm -> bf16 ----------------
__global__ void ln_kernel(const float* __restrict__ in, const float* __restrict__ gamma,
                          const float* __restrict__ beta, bf16* __restrict__ out) {
    int warp = blockIdx.x * (blockDim.x >> 5) + (threadIdx.x >> 5);
    int lane = threadIdx.x & 31;
    int nwarps = gridDim.x * (blockDim.x >> 5);
    float g0 = gamma[lane], g1 = gamma[lane + 32], g2 = gamma[lane + 64];
    float b0 = beta[lane],  b1 = beta[lane + 32],  b2 = beta[lane + 64];
    for (int p = warp; p < NPIX; p += nwarps) {
        const float* xp = in + (size_t)p * CDIM;
        float v0 = xp[lane], v1 = xp[lane + 32], v2 = xp[lane + 64];
        float s  = v0 + v1 + v2;
        float ss = v0 * v0 + v1 * v1 + v2 * v2;
        #pragma unroll
        for (int o = 16; o > 0; o >>= 1) {
            s  += __shfl_xor_sync(0xffffffffu, s,  o);
            ss += __shfl_xor_sync(0xffffffffu, ss, o);
        }
        float mu = s * (1.f / 96.f);
        float var = ss * (1.f / 96.f) - mu * mu;
        float rstd = rsqrtf(var + 1e-5f);
        bf16* yp = out + (size_t)p * CDIM;
        yp[lane]      = __float2bfloat16_rn((v0 - mu) * rstd * g0 + b0);
        yp[lane + 32] = __float2bfloat16_rn((v1 - mu) * rstd * g1 + b1);
        yp[lane + 64] = __float2bfloat16_rn((v2 - mu) * rstd * g2 + b2);
    }
}

// ---------------- bf16 tensor-core GEMM ----------------
// OUTMODE: 0 = f32 out, 1 = bf16 out, 2 = split bf16 (cols<255 -> C, cols>=255 -> C2, stride 256)
template<int NT, int BK, int KITER, int OUTMODE>
__global__ void __launch_bounds__(256)
gemm_k(const bf16* __restrict__ A, const bf16* __restrict__ Bw,
       const float* __restrict__ R, void* __restrict__ Cout, bf16* __restrict__ C2,
       int Ka, int Kb, int N) {
    constexpr int BN = NT * 16;
    constexpr int PA = BK + 8;
    constexpr int PB = BN + 8;
    __shared__ __align__(16) bf16 As[128][PA];
    __shared__ __align__(16) bf16 Bs[BK][PB];

    int tid = threadIdx.x;
    int m0 = blockIdx.y * 128;
    int n0 = blockIdx.x * BN;
    int lane = tid & 31, warp = tid >> 5;
    int g = lane >> 2, tg = lane & 3;
    int warpM = warp & 3, warpN = warp >> 2;
    int mbase = warpM * 32, nbase = warpN * (NT * 8);

    float acc[2][NT][4];
    #pragma unroll
    for (int mt = 0; mt < 2; mt++)
        #pragma unroll
        for (int nt = 0; nt < NT; nt++)
            #pragma unroll
            for (int i = 0; i < 4; i++) acc[mt][nt][i] = 0.f;

    uint32_t a_addr[2], b_addr[NT / 2];
    {
        int arow = lane & 15;
        int acol = (lane >> 4) << 3;
        #pragma unroll
        for (int mt = 0; mt < 2; mt++)
            a_addr[mt] = (uint32_t)__cvta_generic_to_shared(&As[mbase + mt * 16 + arow][acol]);
        int krow = ((lane >> 3) & 1) * 8 + (lane & 7);
        int coff = (lane >> 4) << 3;
        #pragma unroll
        for (int nh = 0; nh < NT / 2; nh++)
            b_addr[nh] = (uint32_t)__cvta_generic_to_shared(&Bs[krow][nbase + nh * 16 + coff]);
    }

    #pragma unroll
    for (int kit = 0; kit < KITER; kit++) {
        int k0 = kit * BK;
        constexpr int AC = BK / 8;
        constexpr int AL = 128 * AC / 256;
        #pragma unroll
        for (int l = 0; l < AL; l++) {
            int idx = tid + l * 256;
            int row = idx / AC, c8 = idx % AC;
            *(uint4*)&As[row][c8 * 8] =
                *(const uint4*)(A + (size_t)(m0 + row) * Ka + k0 + c8 * 8);
        }
        constexpr int BC = BN / 2;
        constexpr int BL = BK * BC / 256;
        #pragma unroll
        for (int l = 0; l < BL; l++) {
            int idx = tid + l * 256;
            int row = idx / BC, nu = idx % BC;
            int kk = k0 + row, col = n0 + nu * 2;
            uint32_t v = 0;
            if (kk < Kb && col < N) v = *(const uint32_t*)(Bw + (size_t)kk * N + col);
            *(uint32_t*)&Bs[row][nu * 2] = v;
        }
        __syncthreads();
        #pragma unroll
        for (int ks = 0; ks < BK / 16; ks++) {
            uint32_t af[2][4];
            #pragma unroll
            for (int mt = 0; mt < 2; mt++)
                ldsm_x4(af[mt], a_addr[mt] + ks * 32);
            #pragma unroll
            for (int nh = 0; nh < NT / 2; nh++) {
                uint32_t bq[4];
                ldsm_x4_t(bq, b_addr[nh] + ks * 16 * (PB * 2));
                #pragma unroll
                for (int mt = 0; mt < 2; mt++) {
                    mma_bf16(acc[mt][nh * 2 + 0], af[mt], &bq[0]);
                    mma_bf16(acc[mt][nh * 2 + 1], af[mt], &bq[2]);
                }
            }
        }
        if (kit + 1 < KITER) __syncthreads();
    }

    #pragma unroll
    for (int mt = 0; mt < 2; mt++) {
        #pragma unroll
        for (int nt = 0; nt < NT; nt++) {
            int col = n0 + nbase + nt * 8 + tg * 2;
            if (col >= N) continue;
            #pragma unroll
            for (int h = 0; h < 2; h++) {
                int row = m0 + mbase + mt * 16 + g + h * 8;
                float v0 = acc[mt][nt][h * 2 + 0];
                float v1 = acc[mt][nt][h * 2 + 1];
                if (OUTMODE == 2) {
                    bf16* d0 = (col < HID) ? (bf16*)Cout + (size_t)row * HIDP + col
                                           : C2 + (size_t)row * HIDP + (col - HID);
                    bf16* d1 = (col + 1 < HID) ? (bf16*)Cout + (size_t)row * HIDP + col + 1
                                               : C2 + (size_t)row * HIDP + (col + 1 - HID);
                    *d0 = __float2bfloat16_rn(v0);
                    *d1 = __float2bfloat16_rn(v1);
                } else {
                    size_t o = (size_t)row * N + col;
                    if (R) {
                        float2 r2 = *(const float2*)(R + o);
                        v0 += r2.x; v1 += r2.y;
                    }
                    if (OUTMODE == 1) *(uint32_t*)((bf16*)Cout + o) = pack_bf2(v0, v1);
                    else *(float2*)((float*)Cout + o) = make_float2(v0, v1);
                }
            }
        }
    }
}

// ---------------- depthwise 3x3, C=288 bf16, 8-ch chunks, 2-wide x strip ----------------
__global__ void dwconv288_kernel(const bf16* __restrict__ in, const float* __restrict__ kern,
                                 bf16* __restrict__ out) {
    const int C8 = QKV / 8; // 36
    int idx = blockIdx.x * blockDim.x + threadIdx.x;
    if (idx >= (NPIX / 2) * C8) return;
    int c8 = idx % C8;
    int strip = idx / C8;
    int xs = (strip & 127) * 2;
    int y  = (strip >> 7) & 255;
    int b  = strip >> 15;

    float acc[2][8];
    #pragma unroll
    for (int ox = 0; ox < 2; ox++)
        #pragma unroll
        for (int e = 0; e < 8; e++) acc[ox][e] = 0.f;

    #pragma unroll
    for (int dy = -1; dy <= 1; dy++) {
        int yy = y + dy;
        if (yy < 0 || yy > 255) continue;
        const bf16* rowp = in + ((size_t)((b << 8) + yy) << 8) * QKV;
        float v[4][8];
        #pragma unroll
        for (int j = 0; j < 4; j++) {
            int xx = xs - 1 + j;
            if (xx >= 0 && xx <= 255) {
                uint4 u = *(const uint4*)(rowp + (size_t)xx * QKV + c8 * 8);
                const __nv_bfloat162* p2 = (const __nv_bfloat162*)&u;
                #pragma unroll
                for (int q = 0; q < 4; q++) {
                    float2 f = __bfloat1622float2(p2[q]);
                    v[j][q * 2] = f.x; v[j][q * 2 + 1] = f.y;
                }
            } else {
                #pragma unroll
                for (int e = 0; e < 8; e++) v[j][e] = 0.f;
            }
        }
        #pragma unroll
        for (int dx = 0; dx < 3; dx++) {
            const float* kp = kern + (size_t)((dy + 1) * 3 + dx) * QKV + c8 * 8;
            float kv[8];
            *(float4*)&kv[0] = *(const float4*)kp;
            *(float4*)&kv[4] = *(const float4*)(kp + 4);
            #pragma unroll
            for (int ox = 0; ox < 2; ox++)
                #pragma unroll
                for (int e = 0; e < 8; e++) acc[ox][e] += v[ox + dx][e] * kv[e];
        }
    }
    bf16* op = out + ((size_t)((b << 16) + (y << 8) + xs)) * QKV + c8 * 8;
    #pragma unroll
    for (int ox = 0; ox < 2; ox++) {
        uint4 u;
        uint32_t* w = (uint32_t*)&u;
        #pragma unroll
        for (int q = 0; q < 4; q++) w[q] = pack_bf2(acc[ox][q * 2], acc[ox][q * 2 + 1]);
        *(uint4*)(op + (size_t)ox * QKV) = u;
    }
}

// ---------------- q*k^T accumulation + fused q/k sum-of-squares ----------------
__global__ void qkt_kernel(const bf16* __restrict__ t1, float* __restrict__ attn,
                           float* __restrict__ nrm) {
    __shared__ float qs[16][48];
    __shared__ float ks[16][48];
    __shared__ float nq[48], nk[48];
    int bh = blockIdx.y;
    int b = bh >> 1, hd = bh & 1;
    int s0 = blockIdx.x * 2048;
    int tid = threadIdx.x;
    if (tid < 48) { nq[tid] = 0.f; nk[tid] = 0.f; }
    int tx = tid & 15, ty = tid >> 4;
    float acc[3][3];
    #pragma unroll
    for (int r = 0; r < 3; r++)
        #pragma unroll
        for (int c = 0; c < 3; c++) acc[r][c] = 0.f;
    float sqq[3] = {0.f, 0.f, 0.f}, sqk[3] = {0.f, 0.f, 0.f};

    const bf16* qbase = t1 + ((size_t)(b << 16)) * QKV + hd * CH;
    const bf16* kbase = qbase + CDIM;
    for (int st = 0; st < 2048; st += 16) {
        #pragma unroll
        for (int l = 0; l < 3; l++) {
            int idx = tid + l * 256;
            int si = idx / 48, e = idx % 48;
            size_t off = (size_t)(s0 + st + si) * QKV + e;
            float qv = __bfloat162float(qbase[off]);
            float kv = __bfloat162float(kbase[off]);
            qs[si][e] = qv; ks[si][e] = kv;
            sqq[l] += qv * qv; sqk[l] += kv * kv;
        }
        __syncthreads();
        #pragma unroll
        for (int si = 0; si < 16; si++) {
            float qv[3], kv[3];
            #pragma unroll
            for (int r = 0; r < 3; r++) qv[r] = qs[si][ty * 3 + r];
            #pragma unroll
            for (int c = 0; c < 3; c++) kv[c] = ks[si][tx * 3 + c];
            #pragma unroll
            for (int r = 0; r < 3; r++)
                #pragma unroll
                for (int c = 0; c < 3; c++) acc[r][c] += qv[r] * kv[c];
        }
        __syncthreads();
    }
    #pragma unroll
    for (int l = 0; l < 3; l++) {
        int e = (tid + l * 256) % 48;
        atomicAdd(&nq[e], sqq[l]);
        atomicAdd(&nk[e], sqk[l]);
    }
    float* ab = attn + (size_t)bh * CH * CH;
    #pragma unroll
    for (int r = 0; r < 3; r++)
        #pragma unroll
        for (int c = 0; c < 3; c++)
            atomicAdd(&ab[(ty * 3 + r) * CH + (tx * 3 + c)], acc[r][c]);
    __syncthreads();
    if (tid < 48) {
        atomicAdd(&nrm[b * 192 + hd * CH + tid], nq[tid]);
        atomicAdd(&nrm[b * 192 + CDIM + hd * CH + tid], nk[tid]);
    }
}

// ---------------- normalize + temperature + softmax ----------------
__global__ void softmax_kernel(float* __restrict__ attn, const float* __restrict__ nrm,
                               const float* __restrict__ temp) {
    int bh = blockIdx.x;
    int b = bh >> 1, hd = bh & 1;
    int d = threadIdx.x;
    if (d >= CH) return;
    float t = temp[hd];
    float rq = rsqrtf(nrm[b * 192 + hd * CH + d]);
    float* row = attn + (size_t)bh * CH * CH + d * CH;
    float vals[CH];
    float mx = -1e30f;
    #pragma unroll
    for (int e = 0; e < CH; e++) {
        float rk = rsqrtf(nrm[b * 192 + CDIM + hd * CH + e]);
        float v = row[e] * rq * rk * t;
        vals[e] = v;
        mx = fmaxf(mx, v);
    }
    float s = 0.f;
    #pragma unroll
    for (int e = 0; e < CH; e++) { vals[e] = expf(vals[e] - mx); s += vals[e]; }
    float inv = 1.f / s;
    #pragma unroll
    for (int e = 0; e < CH; e++) row[e] = vals[e] * inv;
}

// ---------------- o = attn @ v (float4 vectorized) ----------------
__global__ void attnapply_kernel(const bf16* __restrict__ t1, const float* __restrict__ attn,
                                 bf16* __restrict__ o) {
    __shared__ float at[HEADS * CH * CH];
    __shared__ float vs[32][CDIM];
    int b = blockIdx.y;
    int p0 = blockIdx.x * 32;
    int tid = threadIdx.x;
    for (int i = tid; i < HEADS * CH * CH; i += 256) at[i] = attn[(size_t)b * HEADS * CH * CH + i];
    const bf16* vbase = t1 + ((size_t)((b << 16) + p0)) * QKV + 2 * CDIM;
    #pragma unroll
    for (int l = 0; l < 6; l++) {
        int idx = tid + l * 256;
        int p = idx / 48, cu = idx % 48;
        uint32_t u = *(const uint32_t*)(vbase + (size_t)p * QKV + cu * 2);
        float2 f = __bfloat1622float2(*(__nv_bfloat162*)&u);
        vs[p][cu * 2] = f.x; vs[p][cu * 2 + 1] = f.y;
    }
    __syncthreads();
    bf16* obase = o + ((size_t)((b << 16) + p0)) * CDIM;
    #pragma unroll
    for (int l = 0; l < 12; l++) {
        int idx = tid + l * 256;
        int p = idx / CDIM, c = idx % CDIM;
        int hd = c / CH, cm = c % CH;
        const float4* a4 = (const float4*)&at[(hd * CH + cm) * CH];
        const float4* v4 = (const float4*)&vs[p][hd * CH];
        float s = 0.f;
        #pragma unroll
        for (int e = 0; e < 12; e++) {
            float4 av = a4[e], vv = v4[e];
            s += av.x * vv.x + av.y * vv.y + av.z * vv.z + av.w * vv.w;
        }
        obase[(size_t)p * CDIM + c] = __float2bfloat16_rn(s);
    }
}

// ---------------- depthwise 3x3 + GELU gate, split buffers, 4ch x 2px per thread ----------------
__global__ void dwgate_kernel(const bf16* __restrict__ h1, const bf16* __restrict__ h2,
                              const float* __restrict__ kw1, const float* __restrict__ kw2,
                              bf16* __restrict__ out) {
    int idx = blockIdx.x * blockDim.x + threadIdx.x;
    if (idx >= (NPIX / 2) * 64) return;
    int c4 = idx & 63;
    int strip = idx >> 6;
    int xs = (strip & 127) * 2;
    int y  = (strip >> 7) & 255;
    int b  = strip >> 15;

    float accA[2][4], accB[2][4];
    #pragma unroll
    for (int ox = 0; ox < 2; ox++)
        #pragma unroll
        for (int e = 0; e < 4; e++) { accA[ox][e] = 0.f; accB[ox][e] = 0.f; }

    #pragma unroll
    for (int dy = -1; dy <= 1; dy++) {
        int yy = y + dy;
        if (yy < 0 || yy > 255) continue;
        size_t rowbase = ((size_t)((b << 8) + yy) << 8) * HIDP + c4 * 4;
        float va[4][4], vb[4][4];
        #pragma unroll
        for (int j = 0; j < 4; j++) {
            int xx = xs - 1 + j;
            if (xx >= 0 && xx <= 255) {
                uint2 u1 = *(const uint2*)(h1 + rowbase + (size_t)xx * HIDP);
                uint2 u2 = *(const uint2*)(h2 + rowbase + (size_t)xx * HIDP);
                float2 a0 = __bfloat1622float2(((const __nv_bfloat162*)&u1)[0]);
                float2 a1 = __bfloat1622float2(((const __nv_bfloat162*)&u1)[1]);
                float2 b0 = __bfloat1622float2(((const __nv_bfloat162*)&u2)[0]);
                float2 b1 = __bfloat1622float2(((const __nv_bfloat162*)&u2)[1]);
                va[j][0] = a0.x; va[j][1] = a0.y; va[j][2] = a1.x; va[j][3] = a1.y;
                vb[j][0] = b0.x; vb[j][1] = b0.y; vb[j][2] = b1.x; vb[j][3] = b1.y;
            } else {
                #pragma unroll
                for (int e = 0; e < 4; e++) { va[j][e] = 0.f; vb[j][e] = 0.f; }
            }
        }
        #pragma unroll
        for (int dx = 0; dx < 3; dx++) {
            int ki = (dy + 1) * 3 + dx;
            float4 k1 = *(const float4*)(kw1 + ki * 256 + c4 * 4);
            float4 k2 = *(const float4*)(kw2 + ki * 256 + c4 * 4);
            float ka[4] = {k1.x, k1.y, k1.z, k1.w};
            float kb[4] = {k2.x, k2.y, k2.z, k2.w};
            #pragma unroll
            for (int ox = 0; ox < 2; ox++)
                #pragma unroll
                for (int e = 0; e < 4; e++) {
                    accA[ox][e] += va[ox + dx][e] * ka[e];
                    accB[ox][e] += vb[ox + dx][e] * kb[e];
                }
        }
    }
    size_t pbase = (size_t)((b << 16) + (y << 8) + xs);
    #pragma unroll
    for (int ox = 0; ox < 2; ox++) {
        uint2 u;
        uint32_t* w = (uint32_t*)&u;
        float g0 = gelu_exact(accA[ox][0]) * accB[ox][0];
        float g1 = gelu_exact(accA[ox][1]) * accB[ox][1];
        float g2 = gelu_exact(accA[ox][2]) * accB[ox][2];
        float g3 = gelu_exact(accA[ox][3]) * accB[ox][3];
        w[0] = pack_bf2(g0, g1);
        w[1] = pack_bf2(g2, g3);
        *(uint2*)(out + (pbase + ox) * HIDP + c4 * 4) = u;
    }
}

// ---------------- launcher ----------------
extern "C" void kernel_launch(void* const* d_in, const int* in_sizes, int n_in,
                              void* d_out, int out_size) {
    const float* x     = (const float*)d_in[0];
    const float* ln1g  = (const float*)d_in[1];
    const float* ln1b  = (const float*)d_in[2];
    const float* ln2g  = (const float*)d_in[3];
    const float* ln2b  = (const float*)d_in[4];
    const float* qkvw  = (const float*)d_in[5];
    const float* qkvdw = (const float*)d_in[6];
    const float* temp  = (const float*)d_in[7];
    const float* aow   = (const float*)d_in[8];
    const float* fiw   = (const float*)d_in[9];
    const float* fdw   = (const float*)d_in[10];
    const float* fow   = (const float*)d_in[11];
    float* out = (float*)d_out;

    bf16 *t0, *t1, *h1, *h2, *gt, *ybf, *wq, *wa, *wi, *wo;
    float *x2, *nrm, *att, *kw1, *kw2;
    cudaGetSymbolAddress((void**)&t0,  g_t0);
    cudaGetSymbolAddress((void**)&t1,  g_t1);
    cudaGetSymbolAddress((void**)&h1,  g_h1);
    cudaGetSymbolAddress((void**)&h2,  g_h2);
    cudaGetSymbolAddress((void**)&gt,  g_gt);
    cudaGetSymbolAddress((void**)&ybf, g_ybf);
    cudaGetSymbolAddress((void**)&x2,  g_x2);
    cudaGetSymbolAddress((void**)&nrm, g_nrm);
    cudaGetSymbolAddress((void**)&att, g_att);
    cudaGetSymbolAddress((void**)&wq,  g_wq);
    cudaGetSymbolAddress((void**)&wa,  g_wa);
    cudaGetSymbolAddress((void**)&wi,  g_wi);
    cudaGetSymbolAddress((void**)&wo,  g_wo);
    cudaGetSymbolAddress((void**)&kw1, g_kw1);
    cudaGetSymbolAddress((void**)&kw2, g_kw2);

    const int cvt_total = CDIM * QKV + CDIM * CDIM + CDIM * H2 + HID * CDIM;
    cvt_all_kernel<<<(cvt_total + 255) / 256, 256>>>(qkvw, aow, fiw, fow, fdw,
                                                     wq, wa, wi, wo, kw1, kw2, nrm, att);

    // attention branch
    ln_kernel<<<2048, 256>>>(x, ln1g, ln1b, ybf);
    gemm_k<6, 96, 1, 1><<<dim3(3, 1024), 256>>>(ybf, wq, nullptr, t0, nullptr, CDIM, CDIM, QKV);
    dwconv288_kernel<<<(NPIX / 2) * 36 / 256, 256>>>(t0, qkvdw, t1);
    qkt_kernel<<<dim3(32, 4), 256>>>(t1, att, nrm);
    softmax_kernel<<<4, 64>>>(att, nrm, temp);
    attnapply_kernel<<<dim3(2048, 2), 256>>>(t1, att, ybf);
    gemm_k<6, 96, 1, 0><<<dim3(1, 1024), 256>>>(ybf, wa, x, x2, nullptr, CDIM, CDIM, CDIM);

    // FFN branch
    ln_kernel<<<2048, 256>>>(x2, ln2g, ln2b, ybf);
    gemm_k<6, 96, 1, 2><<<dim3(6, 1024), 256>>>(ybf, wi, nullptr, h1, h2, CDIM, CDIM, H2);
    dwgate_kernel<<<(NPIX / 2) * 64 / 256, 256>>>(h1, h2, kw1, kw2, gt);
    gemm_k<6, 64, 4, 0><<<dim3(1, 1024), 256>>>(gt, wo, x2, out, nullptr, HIDP, HID, CDIM);
}

// round 7
// speedup vs baseline: 1.0961x; 1.0961x over previous
#include <cuda_runtime.h>
#include <cuda_bf16.h>
#include <math.h>
#include <stdint.h>

// ---------------- problem constants ----------------
#define BATCH 2
#define CDIM 96
#define HEADS 2
#define CH 48
#define QKV 288
#define HID 255
#define HIDP 256
#define H2 510
#define NPIX 131072

typedef __nv_bfloat16 bf16;

// ---------------- device scratch ----------------
__device__ __align__(256) bf16 g_t0[(size_t)NPIX * QKV];
__device__ __align__(256) bf16 g_t1[(size_t)NPIX * QKV];
__device__ __align__(256) bf16 g_t2[(size_t)NPIX * H2];
__device__ __align__(256) bf16 g_gt[(size_t)NPIX * HIDP];
__device__ __align__(256) bf16 g_ybf[(size_t)NPIX * CDIM];
__device__ __align__(256) float g_x2[(size_t)NPIX * CDIM];
__device__ float g_nrm[2 * BATCH * CDIM];
__device__ float g_att[BATCH * HEADS * CH * CH];
__device__ __align__(256) bf16 g_wq[CDIM * QKV];
__device__ __align__(256) bf16 g_wa[CDIM * CDIM];
__device__ __align__(256) bf16 g_wi[CDIM * H2];
__device__ __align__(256) bf16 g_wo[HID * CDIM];

// ---------------- helpers ----------------
__device__ __forceinline__ float gelu_exact(float v) {
    return 0.5f * v * (1.0f + erff(v * 0.70710678118654752f));
}
__device__ __forceinline__ void ldsm_x4(uint32_t* r, uint32_t addr) {
    asm volatile("ldmatrix.sync.aligned.m8n8.x4.shared.b16 {%0,%1,%2,%3}, [%4];"
        : "=r"(r[0]), "=r"(r[1]), "=r"(r[2]), "=r"(r[3]) : "r"(addr));
}
__device__ __forceinline__ void ldsm_x4_t(uint32_t* r, uint32_t addr) {
    asm volatile("ldmatrix.sync.aligned.m8n8.x4.trans.shared.b16 {%0,%1,%2,%3}, [%4];"
        : "=r"(r[0]), "=r"(r[1]), "=r"(r[2]), "=r"(r[3]) : "r"(addr));
}
__device__ __forceinline__ void mma_bf16(float* c, const uint32_t* a, const uint32_t* b) {
    asm volatile("mma.sync.aligned.m16n8k16.row.col.f32.bf16.bf16.f32 "
        "{%0,%1,%2,%3}, {%4,%5,%6,%7}, {%8,%9}, {%0,%1,%2,%3};\n"
        : "+f"(c[0]), "+f"(c[1]), "+f"(c[2]), "+f"(c[3])
        : "r"(a[0]), "r"(a[1]), "r"(a[2]), "r"(a[3]), "r"(b[0]), "r"(b[1]));
}
__device__ __forceinline__ uint32_t pack_bf2(float a, float b) {
    __nv_bfloat162 h = __floats2bfloat162_rn(a, b);
    return *(uint32_t*)&h;
}

// ---------------- weight convert + accumulator init ----------------
__global__ void cvt_all_kernel(const float* wq, const float* wa, const float* wi, const float* wo,
                               bf16* dq, bf16* da, bf16* di, bf16* dxo,
                               float* nrm, float* attn) {
    int i = blockIdx.x * blockDim.x + threadIdx.x;
    const int s0 = CDIM * QKV, s1 = s0 + CDIM * CDIM, s2 = s1 + CDIM * H2, s3 = s2 + HID * CDIM;
    if (i < s0) dq[i] = __float2bfloat16_rn(wq[i]);
    else if (i < s1) da[i - s0] = __float2bfloat16_rn(wa[i - s0]);
    else if (i < s2) di[i - s1] = __float2bfloat16_rn(wi[i - s1]);
    else if (i < s3) dxo[i - s2] = __float2bfloat16_rn(wo[i - s2]);
    if (i < 2 * BATCH * CDIM) nrm[i] = 0.f;
    if (i < BATCH * HEADS * CH * CH) attn[i] = 0.f;
}

// ---------------- per-pixel LayerNorm -> bf16 ----------------
__global__ void ln_kernel(const float* __restrict__ in, const float* __restrict__ gamma,
                          const float* __restrict__ beta, bf16* __restrict__ out) {
    int warp = blockIdx.x * (blockDim.x >> 5) + (threadIdx.x >> 5);
    int lane = threadIdx.x & 31;
    int nwarps = gridDim.x * (blockDim.x >> 5);
    float g0 = gamma[lane], g1 = gamma[lane + 32], g2 = gamma[lane + 64];
    float b0 = beta[lane],  b1 = beta[lane + 32],  b2 = beta[lane + 64];
    for (int p = warp; p < NPIX; p += nwarps) {
        const float* xp = in + (size_t)p * CDIM;
        float v0 = xp[lane], v1 = xp[lane + 32], v2 = xp[lane + 64];
        float s  = v0 + v1 + v2;
        float ss = v0 * v0 + v1 * v1 + v2 * v2;
        #pragma unroll
        for (int o = 16; o > 0; o >>= 1) {
            s  += __shfl_xor_sync(0xffffffffu, s,  o);
            ss += __shfl_xor_sync(0xffffffffu, ss, o);
        }
        float mu = s * (1.f / 96.f);
        float var = ss * (1.f / 96.f) - mu * mu;
        float rstd = rsqrtf(var + 1e-5f);
        bf16* yp = out + (size_t)p * CDIM;
        yp[lane]      = __float2bfloat16_rn((v0 - mu) * rstd * g0 + b0);
        yp[lane + 32] = __float2bfloat16_rn((v1 - mu) * rstd * g1 + b1);
        yp[lane + 64] = __float2bfloat16_rn((v2 - mu) * rstd * g2 + b2);
    }
}

// ---------------- templated bf16 tensor-core GEMM (R4 version) ----------------
template<int NT, int BK, int KITER, bool BF16OUT>
__global__ void __launch_bounds__(256)
gemm_k(const bf16* __restrict__ A, const bf16* __restrict__ Bw,
       const float* __restrict__ R, void* __restrict__ Cout,
       int Ka, int Kb, int N) {
    constexpr int BN = NT * 16;
    constexpr int PA = BK + 8;
    constexpr int PB = BN + 8;
    __shared__ __align__(16) bf16 As[128][PA];
    __shared__ __align__(16) bf16 Bs[BK][PB];

    int tid = threadIdx.x;
    int m0 = blockIdx.y * 128;
    int n0 = blockIdx.x * BN;
    int lane = tid & 31, warp = tid >> 5;
    int g = lane >> 2, tg = lane & 3;
    int warpM = warp & 3, warpN = warp >> 2;
    int mbase = warpM * 32, nbase = warpN * (NT * 8);

    float acc[2][NT][4];
    #pragma unroll
    for (int mt = 0; mt < 2; mt++)
        #pragma unroll
        for (int nt = 0; nt < NT; nt++)
            #pragma unroll
            for (int i = 0; i < 4; i++) acc[mt][nt][i] = 0.f;

    uint32_t a_addr[2], b_addr[NT / 2];
    {
        int arow = lane & 15;
        int acol = (lane >> 4) << 3;
        #pragma unroll
        for (int mt = 0; mt < 2; mt++)
            a_addr[mt] = (uint32_t)__cvta_generic_to_shared(&As[mbase + mt * 16 + arow][acol]);
        int krow = ((lane >> 3) & 1) * 8 + (lane & 7);
        int coff = (lane >> 4) << 3;
        #pragma unroll
        for (int nh = 0; nh < NT / 2; nh++)
            b_addr[nh] = (uint32_t)__cvta_generic_to_shared(&Bs[krow][nbase + nh * 16 + coff]);
    }

    #pragma unroll
    for (int kit = 0; kit < KITER; kit++) {
        int k0 = kit * BK;
        constexpr int AC = BK / 8;
        constexpr int AL = 128 * AC / 256;
        #pragma unroll
        for (int l = 0; l < AL; l++) {
            int idx = tid + l * 256;
            int row = idx / AC, c8 = idx % AC;
            *(uint4*)&As[row][c8 * 8] =
                *(const uint4*)(A + (size_t)(m0 + row) * Ka + k0 + c8 * 8);
        }
        constexpr int BC = BN / 2;
        constexpr int BL = BK * BC / 256;
        #pragma unroll
        for (int l = 0; l < BL; l++) {
            int idx = tid + l * 256;
            int row = idx / BC, nu = idx % BC;
            int kk = k0 + row, col = n0 + nu * 2;
            uint32_t v = 0;
            if (kk < Kb && col < N) v = *(const uint32_t*)(Bw + (size_t)kk * N + col);
            *(uint32_t*)&Bs[row][nu * 2] = v;
        }
        __syncthreads();
        #pragma unroll
        for (int ks = 0; ks < BK / 16; ks++) {
            uint32_t af[2][4];
            #pragma unroll
            for (int mt = 0; mt < 2; mt++)
                ldsm_x4(af[mt], a_addr[mt] + ks * 32);
            #pragma unroll
            for (int nh = 0; nh < NT / 2; nh++) {
                uint32_t bq[4];
                ldsm_x4_t(bq, b_addr[nh] + ks * 16 * (PB * 2));
                #pragma unroll
                for (int mt = 0; mt < 2; mt++) {
                    mma_bf16(acc[mt][nh * 2 + 0], af[mt], &bq[0]);
                    mma_bf16(acc[mt][nh * 2 + 1], af[mt], &bq[2]);
                }
            }
        }
        if (kit + 1 < KITER) __syncthreads();
    }

    #pragma unroll
    for (int mt = 0; mt < 2; mt++) {
        #pragma unroll
        for (int nt = 0; nt < NT; nt++) {
            int col = n0 + nbase + nt * 8 + tg * 2;
            if (col >= N) continue;
            #pragma unroll
            for (int h = 0; h < 2; h++) {
                int row = m0 + mbase + mt * 16 + g + h * 8;
                size_t o = (size_t)row * N + col;
                float v0 = acc[mt][nt][h * 2 + 0];
                float v1 = acc[mt][nt][h * 2 + 1];
                if (R) {
                    float2 r2 = *(const float2*)(R + o);
                    v0 += r2.x; v1 += r2.y;
                }
                if (BF16OUT) *(uint32_t*)((bf16*)Cout + o) = pack_bf2(v0, v1);
                else *(float2*)((float*)Cout + o) = make_float2(v0, v1);
            }
        }
    }
}

// ---------------- depthwise 3x3, C=288 bf16, 8-ch chunks, 4-wide x strip (R4) ----------------
__global__ void dwconv288_kernel(const bf16* __restrict__ in, const float* __restrict__ kern,
                                 bf16* __restrict__ out) {
    const int C8 = QKV / 8;
    int idx = blockIdx.x * blockDim.x + threadIdx.x;
    if (idx >= (NPIX / 4) * C8) return;
    int c8 = idx % C8;
    int strip = idx / C8;
    int xs = (strip & 63) * 4;
    int y  = (strip >> 6) & 255;
    int b  = strip >> 14;

    float acc[4][8];
    #pragma unroll
    for (int ox = 0; ox < 4; ox++)
        #pragma unroll
        for (int e = 0; e < 8; e++) acc[ox][e] = 0.f;

    #pragma unroll
    for (int dy = -1; dy <= 1; dy++) {
        int yy = y + dy;
        if (yy < 0 || yy > 255) continue;
        const bf16* rowp = in + ((size_t)((b << 8) + yy) << 8) * QKV;
        float v[6][8];
        #pragma unroll
        for (int j = 0; j < 6; j++) {
            int xx = xs - 1 + j;
            if (xx >= 0 && xx <= 255) {
                uint4 u = *(const uint4*)(rowp + (size_t)xx * QKV + c8 * 8);
                const __nv_bfloat162* p2 = (const __nv_bfloat162*)&u;
                #pragma unroll
                for (int q = 0; q < 4; q++) {
                    float2 f = __bfloat1622float2(p2[q]);
                    v[j][q * 2] = f.x; v[j][q * 2 + 1] = f.y;
                }
            } else {
                #pragma unroll
                for (int e = 0; e < 8; e++) v[j][e] = 0.f;
            }
        }
        #pragma unroll
        for (int dx = 0; dx < 3; dx++) {
            const float* kp = kern + (size_t)((dy + 1) * 3 + dx) * QKV + c8 * 8;
            float kv[8];
            *(float4*)&kv[0] = *(const float4*)kp;
            *(float4*)&kv[4] = *(const float4*)(kp + 4);
            #pragma unroll
            for (int ox = 0; ox < 4; ox++)
                #pragma unroll
                for (int e = 0; e < 8; e++) acc[ox][e] += v[ox + dx][e] * kv[e];
        }
    }
    bf16* op = out + ((size_t)((b << 16) + (y << 8) + xs)) * QKV + c8 * 8;
    #pragma unroll
    for (int ox = 0; ox < 4; ox++) {
        uint4 u;
        uint32_t* w = (uint32_t*)&u;
        #pragma unroll
        for (int q = 0; q < 4; q++) w[q] = pack_bf2(acc[ox][q * 2], acc[ox][q * 2 + 1]);
        *(uint4*)(op + (size_t)ox * QKV) = u;
    }
}

// ---------------- q*k^T accumulation + fused q/k sum-of-squares ----------------
__global__ void qkt_kernel(const bf16* __restrict__ t1, float* __restrict__ attn,
                           float* __restrict__ nrm) {
    __shared__ float qs[16][48];
    __shared__ float ks[16][48];
    __shared__ float nq[48], nk[48];
    int bh = blockIdx.y;
    int b = bh >> 1, hd = bh & 1;
    int s0 = blockIdx.x * 2048;
    int tid = threadIdx.x;
    if (tid < 48) { nq[tid] = 0.f; nk[tid] = 0.f; }
    int tx = tid & 15, ty = tid >> 4;
    float acc[3][3];
    #pragma unroll
    for (int r = 0; r < 3; r++)
        #pragma unroll
        for (int c = 0; c < 3; c++) acc[r][c] = 0.f;
    float sqq[3] = {0.f, 0.f, 0.f}, sqk[3] = {0.f, 0.f, 0.f};

    const bf16* qbase = t1 + ((size_t)(b << 16)) * QKV + hd * CH;
    const bf16* kbase = qbase + CDIM;
    for (int st = 0; st < 2048; st += 16) {
        #pragma unroll
        for (int l = 0; l < 3; l++) {
            int idx = tid + l * 256;
            int si = idx / 48, e = idx % 48;
            size_t off = (size_t)(s0 + st + si) * QKV + e;
            float qv = __bfloat162float(qbase[off]);
            float kv = __bfloat162float(kbase[off]);
            qs[si][e] = qv; ks[si][e] = kv;
            sqq[l] += qv * qv; sqk[l] += kv * kv;
        }
        __syncthreads();
        #pragma unroll
        for (int si = 0; si < 16; si++) {
            float qv[3], kv[3];
            #pragma unroll
            for (int r = 0; r < 3; r++) qv[r] = qs[si][ty * 3 + r];
            #pragma unroll
            for (int c = 0; c < 3; c++) kv[c] = ks[si][tx * 3 + c];
            #pragma unroll
            for (int r = 0; r < 3; r++)
                #pragma unroll
                for (int c = 0; c < 3; c++) acc[r][c] += qv[r] * kv[c];
        }
        __syncthreads();
    }
    #pragma unroll
    for (int l = 0; l < 3; l++) {
        int e = (tid + l * 256) % 48;
        atomicAdd(&nq[e], sqq[l]);
        atomicAdd(&nk[e], sqk[l]);
    }
    float* ab = attn + (size_t)bh * CH * CH;
    #pragma unroll
    for (int r = 0; r < 3; r++)
        #pragma unroll
        for (int c = 0; c < 3; c++)
            atomicAdd(&ab[(ty * 3 + r) * CH + (tx * 3 + c)], acc[r][c]);
    __syncthreads();
    if (tid < 48) {
        atomicAdd(&nrm[b * 192 + hd * CH + tid], nq[tid]);
        atomicAdd(&nrm[b * 192 + CDIM + hd * CH + tid], nk[tid]);
    }
}

// ---------------- normalize + temperature + softmax ----------------
__global__ void softmax_kernel(float* __restrict__ attn, const float* __restrict__ nrm,
                               const float* __restrict__ temp) {
    int bh = blockIdx.x;
    int b = bh >> 1, hd = bh & 1;
    int d = threadIdx.x;
    if (d >= CH) return;
    float t = temp[hd];
    float rq = rsqrtf(nrm[b * 192 + hd * CH + d]);
    float* row = attn + (size_t)bh * CH * CH + d * CH;
    float vals[CH];
    float mx = -1e30f;
    #pragma unroll
    for (int e = 0; e < CH; e++) {
        float rk = rsqrtf(nrm[b * 192 + CDIM + hd * CH + e]);
        float v = row[e] * rq * rk * t;
        vals[e] = v;
        mx = fmaxf(mx, v);
    }
    float s = 0.f;
    #pragma unroll
    for (int e = 0; e < CH; e++) { vals[e] = expf(vals[e] - mx); s += vals[e]; }
    float inv = 1.f / s;
    #pragma unroll
    for (int e = 0; e < CH; e++) row[e] = vals[e] * inv;
}

// ---------------- o = attn @ v (float4 vectorized) ----------------
__global__ void attnapply_kernel(const bf16* __restrict__ t1, const float* __restrict__ attn,
                                 bf16* __restrict__ o) {
    __shared__ float at[HEADS * CH * CH];
    __shared__ float vs[32][CDIM];
    int b = blockIdx.y;
    int p0 = blockIdx.x * 32;
    int tid = threadIdx.x;
    for (int i = tid; i < HEADS * CH * CH; i += 256) at[i] = attn[(size_t)b * HEADS * CH * CH + i];
    const bf16* vbase = t1 + ((size_t)((b << 16) + p0)) * QKV + 2 * CDIM;
    #pragma unroll
    for (int l = 0; l < 6; l++) {
        int idx = tid + l * 256;
        int p = idx / 48, cu = idx % 48;
        uint32_t u = *(const uint32_t*)(vbase + (size_t)p * QKV + cu * 2);
        float2 f = __bfloat1622float2(*(__nv_bfloat162*)&u);
        vs[p][cu * 2] = f.x; vs[p][cu * 2 + 1] = f.y;
    }
    __syncthreads();
    bf16* obase = o + ((size_t)((b << 16) + p0)) * CDIM;
    #pragma unroll
    for (int l = 0; l < 12; l++) {
        int idx = tid + l * 256;
        int p = idx / CDIM, c = idx % CDIM;
        int hd = c / CH, cm = c % CH;
        const float4* a4 = (const float4*)&at[(hd * CH + cm) * CH];
        const float4* v4 = (const float4*)&vs[p][hd * CH];
        float s = 0.f;
        #pragma unroll
        for (int e = 0; e < 12; e++) {
            float4 av = a4[e], vv = v4[e];
            s += av.x * vv.x + av.y * vv.y + av.z * vv.z + av.w * vv.w;
        }
        obase[(size_t)p * CDIM + c] = __float2bfloat16_rn(s);
    }
}

// ---------------- depthwise 3x3 on 510ch bf16 + GELU gate -> bf16 (stride 256) (R4) ----------------
__global__ void dwgate_kernel(const bf16* __restrict__ in, const float* __restrict__ kern,
                              bf16* __restrict__ out) {
    int idx = blockIdx.x * blockDim.x + threadIdx.x;
    if (idx >= (NPIX / 4) * HID) return;
    int c = idx % HID;
    int strip = idx / HID;
    int xs = (strip & 63) * 4;
    int y  = (strip >> 6) & 255;
    int b  = strip >> 14;

    float accA[4] = {0.f, 0.f, 0.f, 0.f};
    float accB[4] = {0.f, 0.f, 0.f, 0.f};

    #pragma unroll
    for (int dy = -1; dy <= 1; dy++) {
        int yy = y + dy;
        if (yy < 0 || yy > 255) continue;
        const bf16* rowp = in + ((size_t)((b << 8) + yy) << 8) * H2;
        float va[6], vb[6];
        #pragma unroll
        for (int j = 0; j < 6; j++) {
            int xx = xs - 1 + j;
            if (xx >= 0 && xx <= 255) {
                const bf16* pp = rowp + (size_t)xx * H2;
                va[j] = __bfloat162float(pp[c]);
                vb[j] = __bfloat162float(pp[c + HID]);
            } else {
                va[j] = 0.f; vb[j] = 0.f;
            }
        }
        #pragma unroll
        for (int dx = 0; dx < 3; dx++) {
            size_t koff = (size_t)((dy + 1) * 3 + dx) * H2;
            float ka = kern[koff + c];
            float kb = kern[koff + c + HID];
            #pragma unroll
            for (int ox = 0; ox < 4; ox++) {
                accA[ox] += va[ox + dx] * ka;
                accB[ox] += vb[ox + dx] * kb;
            }
        }
    }
    size_t pbase = (size_t)((b << 16) + (y << 8) + xs);
    #pragma unroll
    for (int ox = 0; ox < 4; ox++)
        out[(pbase + ox) * HIDP + c] = __float2bfloat16_rn(gelu_exact(accA[ox]) * accB[ox]);
    if (c == 0) {
        #pragma unroll
        for (int ox = 0; ox < 4; ox++) out[(pbase + ox) * HIDP + 255] = __float2bfloat16_rn(0.f);
    }
}

// ---------------- launcher ----------------
extern "C" void kernel_launch(void* const* d_in, const int* in_sizes, int n_in,
                              void* d_out, int out_size) {
    const float* x     = (const float*)d_in[0];
    const float* ln1g  = (const float*)d_in[1];
    const float* ln1b  = (const float*)d_in[2];
    const float* ln2g  = (const float*)d_in[3];
    const float* ln2b  = (const float*)d_in[4];
    const float* qkvw  = (const float*)d_in[5];
    const float* qkvdw = (const float*)d_in[6];
    const float* temp  = (const float*)d_in[7];
    const float* aow   = (const float*)d_in[8];
    const float* fiw   = (const float*)d_in[9];
    const float* fdw   = (const float*)d_in[10];
    const float* fow   = (const float*)d_in[11];
    float* out = (float*)d_out;

    bf16 *t0, *t1, *t2, *gt, *ybf, *wq, *wa, *wi, *wo;
    float *x2, *nrm, *att;
    cudaGetSymbolAddress((void**)&t0,  g_t0);
    cudaGetSymbolAddress((void**)&t1,  g_t1);
    cudaGetSymbolAddress((void**)&t2,  g_t2);
    cudaGetSymbolAddress((void**)&gt,  g_gt);
    cudaGetSymbolAddress((void**)&ybf, g_ybf);
    cudaGetSymbolAddress((void**)&x2,  g_x2);
    cudaGetSymbolAddress((void**)&nrm, g_nrm);
    cudaGetSymbolAddress((void**)&att, g_att);
    cudaGetSymbolAddress((void**)&wq,  g_wq);
    cudaGetSymbolAddress((void**)&wa,  g_wa);
    cudaGetSymbolAddress((void**)&wi,  g_wi);
    cudaGetSymbolAddress((void**)&wo,  g_wo);

    const int cvt_total = CDIM * QKV + CDIM * CDIM + CDIM * H2 + HID * CDIM;
    cvt_all_kernel<<<(cvt_total + 255) / 256, 256>>>(qkvw, aow, fiw, fow,
                                                     wq, wa, wi, wo, nrm, att);

    // attention branch
    ln_kernel<<<2048, 256>>>(x, ln1g, ln1b, ybf);
    gemm_k<6, 96, 1, true><<<dim3(3, 1024), 256>>>(ybf, wq, nullptr, t0, CDIM, CDIM, QKV);
    dwconv288_kernel<<<(NPIX / 4) * 36 / 256, 256>>>(t0, qkvdw, t1);
    qkt_kernel<<<dim3(32, 4), 256>>>(t1, att, nrm);
    softmax_kernel<<<4, 64>>>(att, nrm, temp);
    attnapply_kernel<<<dim3(2048, 2), 256>>>(t1, att, ybf);
    gemm_k<6, 96, 1, false><<<dim3(1, 1024), 256>>>(ybf, wa, x, x2, CDIM, CDIM, CDIM);

    // FFN branch
    ln_kernel<<<2048, 256>>>(x2, ln2g, ln2b, ybf);
    gemm_k<4, 96, 1, true><<<dim3(8, 1024), 256>>>(ybf, wi, nullptr, t2, CDIM, CDIM, H2);
    dwgate_kernel<<<((NPIX / 4) * HID + 255) / 256, 256>>>(t2, fdw, gt);
    gemm_k<6, 64, 4, false><<<dim3(1, 1024), 256>>>(gt, wo, x2, out, HIDP, HID, CDIM);
}

// round 8
// speedup vs baseline: 1.1013x; 1.0047x over previous
#include <cuda_runtime.h>
#include <cuda_bf16.h>
#include <math.h>
#include <stdint.h>

// ---------------- problem constants ----------------
#define BATCH 2
#define CDIM 96
#define HEADS 2
#define CH 48
#define QKV 288
#define HID 255
#define HIDP 256
#define H2 510
#define NPIX 131072

typedef __nv_bfloat16 bf16;

// ---------------- device scratch ----------------
__device__ __align__(256) bf16 g_t0[(size_t)NPIX * QKV];
__device__ __align__(256) bf16 g_t1[(size_t)NPIX * QKV];
__device__ __align__(256) bf16 g_t2[(size_t)NPIX * H2];
__device__ __align__(256) bf16 g_gt[(size_t)NPIX * HIDP];
__device__ __align__(256) bf16 g_ybf[(size_t)NPIX * CDIM];
__device__ __align__(256) float g_x2[(size_t)NPIX * CDIM];
__device__ float g_nrm[2 * BATCH * CDIM];
__device__ float g_att[BATCH * HEADS * CH * CH];
__device__ __align__(256) bf16 g_wq[CDIM * QKV];
__device__ __align__(256) bf16 g_wa[CDIM * CDIM];
__device__ __align__(256) bf16 g_wi[CDIM * H2];
__device__ __align__(256) bf16 g_wo[HID * CDIM];

// ---------------- helpers ----------------
__device__ __forceinline__ float gelu_exact(float v) {
    return 0.5f * v * (1.0f + erff(v * 0.70710678118654752f));
}
__device__ __forceinline__ void ldsm_x4(uint32_t* r, uint32_t addr) {
    asm volatile("ldmatrix.sync.aligned.m8n8.x4.shared.b16 {%0,%1,%2,%3}, [%4];"
        : "=r"(r[0]), "=r"(r[1]), "=r"(r[2]), "=r"(r[3]) : "r"(addr));
}
__device__ __forceinline__ void ldsm_x4_t(uint32_t* r, uint32_t addr) {
    asm volatile("ldmatrix.sync.aligned.m8n8.x4.trans.shared.b16 {%0,%1,%2,%3}, [%4];"
        : "=r"(r[0]), "=r"(r[1]), "=r"(r[2]), "=r"(r[3]) : "r"(addr));
}
__device__ __forceinline__ void mma_bf16(float* c, const uint32_t* a, const uint32_t* b) {
    asm volatile("mma.sync.aligned.m16n8k16.row.col.f32.bf16.bf16.f32 "
        "{%0,%1,%2,%3}, {%4,%5,%6,%7}, {%8,%9}, {%0,%1,%2,%3};\n"
        : "+f"(c[0]), "+f"(c[1]), "+f"(c[2]), "+f"(c[3])
        : "r"(a[0]), "r"(a[1]), "r"(a[2]), "r"(a[3]), "r"(b[0]), "r"(b[1]));
}
__device__ __forceinline__ uint32_t pack_bf2(float a, float b) {
    __nv_bfloat162 h = __floats2bfloat162_rn(a, b);
    return *(uint32_t*)&h;
}

// ---------------- weight convert + accumulator init ----------------
__global__ void cvt_all_kernel(const float* wq, const float* wa, const float* wi, const float* wo,
                               bf16* dq, bf16* da, bf16* di, bf16* dxo,
                               float* nrm, float* attn) {
    int i = blockIdx.x * blockDim.x + threadIdx.x;
    const int s0 = CDIM * QKV, s1 = s0 + CDIM * CDIM, s2 = s1 + CDIM * H2, s3 = s2 + HID * CDIM;
    if (i < s0) dq[i] = __float2bfloat16_rn(wq[i]);
    else if (i < s1) da[i - s0] = __float2bfloat16_rn(wa[i - s0]);
    else if (i < s2) di[i - s1] = __float2bfloat16_rn(wi[i - s1]);
    else if (i < s3) dxo[i - s2] = __float2bfloat16_rn(wo[i - s2]);
    if (i < 2 * BATCH * CDIM) nrm[i] = 0.f;
    if (i < BATCH * HEADS * CH * CH) attn[i] = 0.f;
}

// ---------------- per-pixel LayerNorm -> bf16 ----------------
__global__ void ln_kernel(const float* __restrict__ in, const float* __restrict__ gamma,
                          const float* __restrict__ beta, bf16* __restrict__ out) {
    int warp = blockIdx.x * (blockDim.x >> 5) + (threadIdx.x >> 5);
    int lane = threadIdx.x & 31;
    int nwarps = gridDim.x * (blockDim.x >> 5);
    float g0 = gamma[lane], g1 = gamma[lane + 32], g2 = gamma[lane + 64];
    float b0 = beta[lane],  b1 = beta[lane + 32],  b2 = beta[lane + 64];
    for (int p = warp; p < NPIX; p += nwarps) {
        const float* xp = in + (size_t)p * CDIM;
        float v0 = xp[lane], v1 = xp[lane + 32], v2 = xp[lane + 64];
        float s  = v0 + v1 + v2;
        float ss = v0 * v0 + v1 * v1 + v2 * v2;
        #pragma unroll
        for (int o = 16; o > 0; o >>= 1) {
            s  += __shfl_xor_sync(0xffffffffu, s,  o);
            ss += __shfl_xor_sync(0xffffffffu, ss, o);
        }
        float mu = s * (1.f / 96.f);
        float var = ss * (1.f / 96.f) - mu * mu;
        float rstd = rsqrtf(var + 1e-5f);
        bf16* yp = out + (size_t)p * CDIM;
        yp[lane]      = __float2bfloat16_rn((v0 - mu) * rstd * g0 + b0);
        yp[lane + 32] = __float2bfloat16_rn((v1 - mu) * rstd * g1 + b1);
        yp[lane + 64] = __float2bfloat16_rn((v2 - mu) * rstd * g2 + b2);
    }
}

// ---------------- templated bf16 tensor-core GEMM (R4 version) ----------------
template<int NT, int BK, int KITER, bool BF16OUT>
__global__ void __launch_bounds__(256)
gemm_k(const bf16* __restrict__ A, const bf16* __restrict__ Bw,
       const float* __restrict__ R, void* __restrict__ Cout,
       int Ka, int Kb, int N) {
    constexpr int BN = NT * 16;
    constexpr int PA = BK + 8;
    constexpr int PB = BN + 8;
    __shared__ __align__(16) bf16 As[128][PA];
    __shared__ __align__(16) bf16 Bs[BK][PB];

    int tid = threadIdx.x;
    int m0 = blockIdx.y * 128;
    int n0 = blockIdx.x * BN;
    int lane = tid & 31, warp = tid >> 5;
    int g = lane >> 2, tg = lane & 3;
    int warpM = warp & 3, warpN = warp >> 2;
    int mbase = warpM * 32, nbase = warpN * (NT * 8);

    float acc[2][NT][4];
    #pragma unroll
    for (int mt = 0; mt < 2; mt++)
        #pragma unroll
        for (int nt = 0; nt < NT; nt++)
            #pragma unroll
            for (int i = 0; i < 4; i++) acc[mt][nt][i] = 0.f;

    uint32_t a_addr[2], b_addr[NT / 2];
    {
        int arow = lane & 15;
        int acol = (lane >> 4) << 3;
        #pragma unroll
        for (int mt = 0; mt < 2; mt++)
            a_addr[mt] = (uint32_t)__cvta_generic_to_shared(&As[mbase + mt * 16 + arow][acol]);
        int krow = ((lane >> 3) & 1) * 8 + (lane & 7);
        int coff = (lane >> 4) << 3;
        #pragma unroll
        for (int nh = 0; nh < NT / 2; nh++)
            b_addr[nh] = (uint32_t)__cvta_generic_to_shared(&Bs[krow][nbase + nh * 16 + coff]);
    }

    #pragma unroll
    for (int kit = 0; kit < KITER; kit++) {
        int k0 = kit * BK;
        constexpr int AC = BK / 8;
        constexpr int AL = 128 * AC / 256;
        #pragma unroll
        for (int l = 0; l < AL; l++) {
            int idx = tid + l * 256;
            int row = idx / AC, c8 = idx % AC;
            *(uint4*)&As[row][c8 * 8] =
                *(const uint4*)(A + (size_t)(m0 + row) * Ka + k0 + c8 * 8);
        }
        constexpr int BC = BN / 2;
        constexpr int BL = BK * BC / 256;
        #pragma unroll
        for (int l = 0; l < BL; l++) {
            int idx = tid + l * 256;
            int row = idx / BC, nu = idx % BC;
            int kk = k0 + row, col = n0 + nu * 2;
            uint32_t v = 0;
            if (kk < Kb && col < N) v = *(const uint32_t*)(Bw + (size_t)kk * N + col);
            *(uint32_t*)&Bs[row][nu * 2] = v;
        }
        __syncthreads();
        #pragma unroll
        for (int ks = 0; ks < BK / 16; ks++) {
            uint32_t af[2][4];
            #pragma unroll
            for (int mt = 0; mt < 2; mt++)
                ldsm_x4(af[mt], a_addr[mt] + ks * 32);
            #pragma unroll
            for (int nh = 0; nh < NT / 2; nh++) {
                uint32_t bq[4];
                ldsm_x4_t(bq, b_addr[nh] + ks * 16 * (PB * 2));
                #pragma unroll
                for (int mt = 0; mt < 2; mt++) {
                    mma_bf16(acc[mt][nh * 2 + 0], af[mt], &bq[0]);
                    mma_bf16(acc[mt][nh * 2 + 1], af[mt], &bq[2]);
                }
            }
        }
        if (kit + 1 < KITER) __syncthreads();
    }

    #pragma unroll
    for (int mt = 0; mt < 2; mt++) {
        #pragma unroll
        for (int nt = 0; nt < NT; nt++) {
            int col = n0 + nbase + nt * 8 + tg * 2;
            if (col >= N) continue;
            #pragma unroll
            for (int h = 0; h < 2; h++) {
                int row = m0 + mbase + mt * 16 + g + h * 8;
                size_t o = (size_t)row * N + col;
                float v0 = acc[mt][nt][h * 2 + 0];
                float v1 = acc[mt][nt][h * 2 + 1];
                if (R) {
                    float2 r2 = *(const float2*)(R + o);
                    v0 += r2.x; v1 += r2.y;
                }
                if (BF16OUT) *(uint32_t*)((bf16*)Cout + o) = pack_bf2(v0, v1);
                else *(float2*)((float*)Cout + o) = make_float2(v0, v1);
            }
        }
    }
}

// ---------------- attn_out GEMM (N=96, K=96) with fused residual + LayerNorm2 ----------------
// x2out = A@B + x ; yout = LN(x2out) in one pass. One column block covers all 96 cols.
__global__ void __launch_bounds__(256)
gemm_attnout_ln(const bf16* __restrict__ A, const bf16* __restrict__ Bw,
                const float* __restrict__ R, float* __restrict__ x2out,
                bf16* __restrict__ yout,
                const float* __restrict__ gamma, const float* __restrict__ beta) {
    constexpr int PA = 104, PB = 104;
    __shared__ __align__(16) char buf[49152];
    bf16* As = (bf16*)buf;                 // [128][PA] = 26624 B
    bf16* Bs = (bf16*)buf + 128 * PA;      // [96][PB]  = 19968 B (total 46592)

    int tid = threadIdx.x, lane = tid & 31, warp = tid >> 5;
    int m0 = blockIdx.x * 128;
    int g = lane >> 2, tg = lane & 3;
    int warpM = warp & 3, warpN = warp >> 2;
    int mbase = warpM * 32, nbase = warpN * 48;

    // A tile 128x96
    #pragma unroll
    for (int l = 0; l < 6; l++) {
        int idx = tid + l * 256;
        int row = idx / 12, c8 = idx % 12;
        *(uint4*)&As[row * PA + c8 * 8] = *(const uint4*)(A + (size_t)(m0 + row) * 96 + c8 * 8);
    }
    // B 96x96 (full, unguarded)
    #pragma unroll
    for (int l = 0; l < 18; l++) {
        int idx = tid + l * 256;
        int row = idx / 48, nu = idx % 48;
        *(uint32_t*)&Bs[row * PB + nu * 2] = *(const uint32_t*)(Bw + (size_t)row * 96 + nu * 2);
    }
    __syncthreads();

    uint32_t a_addr[2], b_addr[3];
    {
        int arow = lane & 15, acol = (lane >> 4) << 3;
        #pragma unroll
        for (int mt = 0; mt < 2; mt++)
            a_addr[mt] = (uint32_t)__cvta_generic_to_shared(&As[(mbase + mt * 16 + arow) * PA + acol]);
        int krow = ((lane >> 3) & 1) * 8 + (lane & 7);
        int coff = (lane >> 4) << 3;
        #pragma unroll
        for (int nh = 0; nh < 3; nh++)
            b_addr[nh] = (uint32_t)__cvta_generic_to_shared(&Bs[krow * PB + nbase + nh * 16 + coff]);
    }

    float acc[2][6][4];
    #pragma unroll
    for (int mt = 0; mt < 2; mt++)
        #pragma unroll
        for (int nt = 0; nt < 6; nt++)
            #pragma unroll
            for (int i = 0; i < 4; i++) acc[mt][nt][i] = 0.f;

    #pragma unroll
    for (int ks = 0; ks < 6; ks++) {
        uint32_t af[2][4];
        ldsm_x4(af[0], a_addr[0] + ks * 32);
        ldsm_x4(af[1], a_addr[1] + ks * 32);
        #pragma unroll
        for (int nh = 0; nh < 3; nh++) {
            uint32_t bq[4];
            ldsm_x4_t(bq, b_addr[nh] + ks * 16 * (PB * 2));
            #pragma unroll
            for (int mt = 0; mt < 2; mt++) {
                mma_bf16(acc[mt][nh * 2 + 0], af[mt], &bq[0]);
                mma_bf16(acc[mt][nh * 2 + 1], af[mt], &bq[2]);
            }
        }
    }
    __syncthreads();   // done with As/Bs; reuse buf as f32 stage

    float* sx = (float*)buf;   // [128][96], cols swizzled by ((row&3)<<3)
    #pragma unroll
    for (int mt = 0; mt < 2; mt++) {
        #pragma unroll
        for (int nt = 0; nt < 6; nt++) {
            int col = nbase + nt * 8 + tg * 2;
            #pragma unroll
            for (int h = 0; h < 2; h++) {
                int rl = mbase + mt * 16 + g + h * 8;
                size_t o = (size_t)(m0 + rl) * 96 + col;
                float2 r2 = *(const float2*)(R + o);
                float v0 = acc[mt][nt][h * 2 + 0] + r2.x;
                float v1 = acc[mt][nt][h * 2 + 1] + r2.y;
                *(float2*)(x2out + o) = make_float2(v0, v1);
                int t = (rl & 3) << 3;
                *(float2*)(sx + rl * 96 + (col ^ t)) = make_float2(v0, v1);
            }
        }
    }
    __syncthreads();

    // LayerNorm from smem: warp w handles rows w*16 .. w*16+15
    float ga0 = gamma[lane], ga1 = gamma[lane + 32], ga2 = gamma[lane + 64];
    float be0 = beta[lane],  be1 = beta[lane + 32],  be2 = beta[lane + 64];
    #pragma unroll
    for (int i = 0; i < 16; i++) {
        int wr = warp * 16 + i;
        int t = (wr & 3) << 3;
        int c0 = lane ^ t;
        float v0 = sx[wr * 96 + c0];
        float v1 = sx[wr * 96 + c0 + 32];
        float v2 = sx[wr * 96 + c0 + 64];
        float s  = v0 + v1 + v2;
        float ss = v0 * v0 + v1 * v1 + v2 * v2;
        #pragma unroll
        for (int o = 16; o > 0; o >>= 1) {
            s  += __shfl_xor_sync(0xffffffffu, s,  o);
            ss += __shfl_xor_sync(0xffffffffu, ss, o);
        }
        float mu = s * (1.f / 96.f);
        float var = ss * (1.f / 96.f) - mu * mu;
        float rstd = rsqrtf(var + 1e-5f);
        bf16* yp = yout + (size_t)(m0 + wr) * 96;
        yp[lane]      = __float2bfloat16_rn((v0 - mu) * rstd * ga0 + be0);
        yp[lane + 32] = __float2bfloat16_rn((v1 - mu) * rstd * ga1 + be1);
        yp[lane + 64] = __float2bfloat16_rn((v2 - mu) * rstd * ga2 + be2);
    }
}

// ---------------- depthwise 3x3, C=288 bf16, 4-ch chunks, 4-wide x strip ----------------
__global__ void dwconv288_kernel(const bf16* __restrict__ in, const float* __restrict__ kern,
                                 bf16* __restrict__ out) {
    const int C4 = QKV / 4; // 72
    int idx = blockIdx.x * blockDim.x + threadIdx.x;
    if (idx >= (NPIX / 4) * C4) return;
    int c4 = idx % C4;
    int strip = idx / C4;
    int xs = (strip & 63) * 4;
    int y  = (strip >> 6) & 255;
    int b  = strip >> 14;

    float acc[4][4];
    #pragma unroll
    for (int ox = 0; ox < 4; ox++)
        #pragma unroll
        for (int e = 0; e < 4; e++) acc[ox][e] = 0.f;

    #pragma unroll
    for (int dy = -1; dy <= 1; dy++) {
        int yy = y + dy;
        if (yy < 0 || yy > 255) continue;
        const bf16* rowp = in + ((size_t)((b << 8) + yy) << 8) * QKV;
        float v[6][4];
        #pragma unroll
        for (int j = 0; j < 6; j++) {
            int xx = xs - 1 + j;
            if (xx >= 0 && xx <= 255) {
                uint2 u = *(const uint2*)(rowp + (size_t)xx * QKV + c4 * 4);
                float2 f0 = __bfloat1622float2(((const __nv_bfloat162*)&u)[0]);
                float2 f1 = __bfloat1622float2(((const __nv_bfloat162*)&u)[1]);
                v[j][0] = f0.x; v[j][1] = f0.y; v[j][2] = f1.x; v[j][3] = f1.y;
            } else {
                #pragma unroll
                for (int e = 0; e < 4; e++) v[j][e] = 0.f;
            }
        }
        #pragma unroll
        for (int dx = 0; dx < 3; dx++) {
            float4 kv = *(const float4*)(kern + (size_t)((dy + 1) * 3 + dx) * QKV + c4 * 4);
            float kk[4] = {kv.x, kv.y, kv.z, kv.w};
            #pragma unroll
            for (int ox = 0; ox < 4; ox++)
                #pragma unroll
                for (int e = 0; e < 4; e++) acc[ox][e] += v[ox + dx][e] * kk[e];
        }
    }
    bf16* op = out + ((size_t)((b << 16) + (y << 8) + xs)) * QKV + c4 * 4;
    #pragma unroll
    for (int ox = 0; ox < 4; ox++) {
        uint2 u;
        ((uint32_t*)&u)[0] = pack_bf2(acc[ox][0], acc[ox][1]);
        ((uint32_t*)&u)[1] = pack_bf2(acc[ox][2], acc[ox][3]);
        *(uint2*)(op + (size_t)ox * QKV) = u;
    }
}

// ---------------- q*k^T accumulation + fused q/k sum-of-squares ----------------
__global__ void qkt_kernel(const bf16* __restrict__ t1, float* __restrict__ attn,
                           float* __restrict__ nrm) {
    __shared__ float qs[16][48];
    __shared__ float ks[16][48];
    __shared__ float nq[48], nk[48];
    int bh = blockIdx.y;
    int b = bh >> 1, hd = bh & 1;
    int s0 = blockIdx.x * 2048;
    int tid = threadIdx.x;
    if (tid < 48) { nq[tid] = 0.f; nk[tid] = 0.f; }
    int tx = tid & 15, ty = tid >> 4;
    float acc[3][3];
    #pragma unroll
    for (int r = 0; r < 3; r++)
        #pragma unroll
        for (int c = 0; c < 3; c++) acc[r][c] = 0.f;
    float sqq[3] = {0.f, 0.f, 0.f}, sqk[3] = {0.f, 0.f, 0.f};

    const bf16* qbase = t1 + ((size_t)(b << 16)) * QKV + hd * CH;
    const bf16* kbase = qbase + CDIM;
    for (int st = 0; st < 2048; st += 16) {
        #pragma unroll
        for (int l = 0; l < 3; l++) {
            int idx = tid + l * 256;
            int si = idx / 48, e = idx % 48;
            size_t off = (size_t)(s0 + st + si) * QKV + e;
            float qv = __bfloat162float(qbase[off]);
            float kv = __bfloat162float(kbase[off]);
            qs[si][e] = qv; ks[si][e] = kv;
            sqq[l] += qv * qv; sqk[l] += kv * kv;
        }
        __syncthreads();
        #pragma unroll
        for (int si = 0; si < 16; si++) {
            float qv[3], kv[3];
            #pragma unroll
            for (int r = 0; r < 3; r++) qv[r] = qs[si][ty * 3 + r];
            #pragma unroll
            for (int c = 0; c < 3; c++) kv[c] = ks[si][tx * 3 + c];
            #pragma unroll
            for (int r = 0; r < 3; r++)
                #pragma unroll
                for (int c = 0; c < 3; c++) acc[r][c] += qv[r] * kv[c];
        }
        __syncthreads();
    }
    #pragma unroll
    for (int l = 0; l < 3; l++) {
        int e = (tid + l * 256) % 48;
        atomicAdd(&nq[e], sqq[l]);
        atomicAdd(&nk[e], sqk[l]);
    }
    float* ab = attn + (size_t)bh * CH * CH;
    #pragma unroll
    for (int r = 0; r < 3; r++)
        #pragma unroll
        for (int c = 0; c < 3; c++)
            atomicAdd(&ab[(ty * 3 + r) * CH + (tx * 3 + c)], acc[r][c]);
    __syncthreads();
    if (tid < 48) {
        atomicAdd(&nrm[b * 192 + hd * CH + tid], nq[tid]);
        atomicAdd(&nrm[b * 192 + CDIM + hd * CH + tid], nk[tid]);
    }
}

// ---------------- normalize + temperature + softmax ----------------
__global__ void softmax_kernel(float* __restrict__ attn, const float* __restrict__ nrm,
                               const float* __restrict__ temp) {
    int bh = blockIdx.x;
    int b = bh >> 1, hd = bh & 1;
    int d = threadIdx.x;
    if (d >= CH) return;
    float t = temp[hd];
    float rq = rsqrtf(nrm[b * 192 + hd * CH + d]);
    float* row = attn + (size_t)bh * CH * CH + d * CH;
    float vals[CH];
    float mx = -1e30f;
    #pragma unroll
    for (int e = 0; e < CH; e++) {
        float rk = rsqrtf(nrm[b * 192 + CDIM + hd * CH + e]);
        float v = row[e] * rq * rk * t;
        vals[e] = v;
        mx = fmaxf(mx, v);
    }
    float s = 0.f;
    #pragma unroll
    for (int e = 0; e < CH; e++) { vals[e] = expf(vals[e] - mx); s += vals[e]; }
    float inv = 1.f / s;
    #pragma unroll
    for (int e = 0; e < CH; e++) row[e] = vals[e] * inv;
}

// ---------------- o = attn @ v (float4 vectorized) ----------------
__global__ void attnapply_kernel(const bf16* __restrict__ t1, const float* __restrict__ attn,
                                 bf16* __restrict__ o) {
    __shared__ float at[HEADS * CH * CH];
    __shared__ float vs[32][CDIM];
    int b = blockIdx.y;
    int p0 = blockIdx.x * 32;
    int tid = threadIdx.x;
    for (int i = tid; i < HEADS * CH * CH; i += 256) at[i] = attn[(size_t)b * HEADS * CH * CH + i];
    const bf16* vbase = t1 + ((size_t)((b << 16) + p0)) * QKV + 2 * CDIM;
    #pragma unroll
    for (int l = 0; l < 6; l++) {
        int idx = tid + l * 256;
        int p = idx / 48, cu = idx % 48;
        uint32_t u = *(const uint32_t*)(vbase + (size_t)p * QKV + cu * 2);
        float2 f = __bfloat1622float2(*(__nv_bfloat162*)&u);
        vs[p][cu * 2] = f.x; vs[p][cu * 2 + 1] = f.y;
    }
    __syncthreads();
    bf16* obase = o + ((size_t)((b << 16) + p0)) * CDIM;
    #pragma unroll
    for (int l = 0; l < 12; l++) {
        int idx = tid + l * 256;
        int p = idx / CDIM, c = idx % CDIM;
        int hd = c / CH, cm = c % CH;
        const float4* a4 = (const float4*)&at[(hd * CH + cm) * CH];
        const float4* v4 = (const float4*)&vs[p][hd * CH];
        float s = 0.f;
        #pragma unroll
        for (int e = 0; e < 12; e++) {
            float4 av = a4[e], vv = v4[e];
            s += av.x * vv.x + av.y * vv.y + av.z * vv.z + av.w * vv.w;
        }
        obase[(size_t)p * CDIM + c] = __float2bfloat16_rn(s);
    }
}

// ---------------- depthwise 3x3 on 510ch bf16 + GELU gate -> bf16 (stride 256) ----------------
__global__ void dwgate_kernel(const bf16* __restrict__ in, const float* __restrict__ kern,
                              bf16* __restrict__ out) {
    int idx = blockIdx.x * blockDim.x + threadIdx.x;
    if (idx >= (NPIX / 4) * HID) return;
    int c = idx % HID;
    int strip = idx / HID;
    int xs = (strip & 63) * 4;
    int y  = (strip >> 6) & 255;
    int b  = strip >> 14;

    float accA[4] = {0.f, 0.f, 0.f, 0.f};
    float accB[4] = {0.f, 0.f, 0.f, 0.f};

    #pragma unroll
    for (int dy = -1; dy <= 1; dy++) {
        int yy = y + dy;
        if (yy < 0 || yy > 255) continue;
        const bf16* rowp = in + ((size_t)((b << 8) + yy) << 8) * H2;
        float va[6], vb[6];
        #pragma unroll
        for (int j = 0; j < 6; j++) {
            int xx = xs - 1 + j;
            if (xx >= 0 && xx <= 255) {
                const bf16* pp = rowp + (size_t)xx * H2;
                va[j] = __bfloat162float(pp[c]);
                vb[j] = __bfloat162float(pp[c + HID]);
            } else {
                va[j] = 0.f; vb[j] = 0.f;
            }
        }
        #pragma unroll
        for (int dx = 0; dx < 3; dx++) {
            size_t koff = (size_t)((dy + 1) * 3 + dx) * H2;
            float ka = kern[koff + c];
            float kb = kern[koff + c + HID];
            #pragma unroll
            for (int ox = 0; ox < 4; ox++) {
                accA[ox] += va[ox + dx] * ka;
                accB[ox] += vb[ox + dx] * kb;
            }
        }
    }
    size_t pbase = (size_t)((b << 16) + (y << 8) + xs);
    #pragma unroll
    for (int ox = 0; ox < 4; ox++)
        out[(pbase + ox) * HIDP + c] = __float2bfloat16_rn(gelu_exact(accA[ox]) * accB[ox]);
    if (c == 0) {
        #pragma unroll
        for (int ox = 0; ox < 4; ox++) out[(pbase + ox) * HIDP + 255] = __float2bfloat16_rn(0.f);
    }
}

// ---------------- launcher ----------------
extern "C" void kernel_launch(void* const* d_in, const int* in_sizes, int n_in,
                              void* d_out, int out_size) {
    const float* x     = (const float*)d_in[0];
    const float* ln1g  = (const float*)d_in[1];
    const float* ln1b  = (const float*)d_in[2];
    const float* ln2g  = (const float*)d_in[3];
    const float* ln2b  = (const float*)d_in[4];
    const float* qkvw  = (const float*)d_in[5];
    const float* qkvdw = (const float*)d_in[6];
    const float* temp  = (const float*)d_in[7];
    const float* aow   = (const float*)d_in[8];
    const float* fiw   = (const float*)d_in[9];
    const float* fdw   = (const float*)d_in[10];
    const float* fow   = (const float*)d_in[11];
    float* out = (float*)d_out;

    bf16 *t0, *t1, *t2, *gt, *ybf, *wq, *wa, *wi, *wo;
    float *x2, *nrm, *att;
    cudaGetSymbolAddress((void**)&t0,  g_t0);
    cudaGetSymbolAddress((void**)&t1,  g_t1);
    cudaGetSymbolAddress((void**)&t2,  g_t2);
    cudaGetSymbolAddress((void**)&gt,  g_gt);
    cudaGetSymbolAddress((void**)&ybf, g_ybf);
    cudaGetSymbolAddress((void**)&x2,  g_x2);
    cudaGetSymbolAddress((void**)&nrm, g_nrm);
    cudaGetSymbolAddress((void**)&att, g_att);
    cudaGetSymbolAddress((void**)&wq,  g_wq);
    cudaGetSymbolAddress((void**)&wa,  g_wa);
    cudaGetSymbolAddress((void**)&wi,  g_wi);
    cudaGetSymbolAddress((void**)&wo,  g_wo);

    const int cvt_total = CDIM * QKV + CDIM * CDIM + CDIM * H2 + HID * CDIM;
    cvt_all_kernel<<<(cvt_total + 255) / 256, 256>>>(qkvw, aow, fiw, fow,
                                                     wq, wa, wi, wo, nrm, att);

    // attention branch
    ln_kernel<<<2048, 256>>>(x, ln1g, ln1b, ybf);
    gemm_k<6, 96, 1, true><<<dim3(3, 1024), 256>>>(ybf, wq, nullptr, t0, CDIM, CDIM, QKV);
    dwconv288_kernel<<<(NPIX / 4) * 72 / 256, 256>>>(t0, qkvdw, t1);
    qkt_kernel<<<dim3(32, 4), 256>>>(t1, att, nrm);
    softmax_kernel<<<4, 64>>>(att, nrm, temp);
    attnapply_kernel<<<dim3(2048, 2), 256>>>(t1, att, ybf);
    // fused: x2 = ybf@wa + x ; ybf = LN2(x2)
    gemm_attnout_ln<<<1024, 256>>>(ybf, wa, x, x2, ybf, ln2g, ln2b);

    // FFN branch
    gemm_k<6, 96, 1, true><<<dim3(6, 1024), 256>>>(ybf, wi, nullptr, t2, CDIM, CDIM, H2);
    dwgate_kernel<<<((NPIX / 4) * HID + 255) / 256, 256>>>(t2, fdw, gt);
    gemm_k<6, 64, 4, false><<<dim3(1, 1024), 256>>>(gt, wo, x2, out, HIDP, HID, CDIM);
}

// round 9
// speedup vs baseline: 1.4435x; 1.3107x over previous
#include <cuda_runtime.h>
#include <cuda_bf16.h>
#include <math.h>
#include <stdint.h>

// ---------------- problem constants ----------------
#define BATCH 2
#define CDIM 96
#define HEADS 2
#define CH 48
#define QKV 288
#define HID 255
#define HIDP 256
#define H2 510
#define NPIX 131072

typedef __nv_bfloat16 bf16;

// ---------------- device scratch ----------------
__device__ __align__(256) bf16 g_t0[(size_t)NPIX * QKV];
__device__ __align__(256) bf16 g_t1[(size_t)NPIX * QKV];
__device__ __align__(256) bf16 g_t2[(size_t)NPIX * H2];
__device__ __align__(256) bf16 g_gt[(size_t)NPIX * HIDP];
__device__ __align__(256) bf16 g_ybf[(size_t)NPIX * CDIM];
__device__ __align__(256) float g_x2[(size_t)NPIX * CDIM];
__device__ float g_nrm[2 * BATCH * CDIM];
__device__ float g_att[BATCH * HEADS * CH * CH];
__device__ __align__(256) bf16 g_wq[CDIM * QKV];
__device__ __align__(256) bf16 g_wa[CDIM * CDIM];
__device__ __align__(256) bf16 g_wi[CDIM * H2];
__device__ __align__(256) bf16 g_wo2[HIDP * CDIM];   // padded: row 255 = 0

// ---------------- helpers ----------------
__device__ __forceinline__ float gelu_exact(float v) {
    return 0.5f * v * (1.0f + erff(v * 0.70710678118654752f));
}
__device__ __forceinline__ void ldsm_x4(uint32_t* r, uint32_t addr) {
    asm volatile("ldmatrix.sync.aligned.m8n8.x4.shared.b16 {%0,%1,%2,%3}, [%4];"
        : "=r"(r[0]), "=r"(r[1]), "=r"(r[2]), "=r"(r[3]) : "r"(addr));
}
__device__ __forceinline__ void ldsm_x4_t(uint32_t* r, uint32_t addr) {
    asm volatile("ldmatrix.sync.aligned.m8n8.x4.trans.shared.b16 {%0,%1,%2,%3}, [%4];"
        : "=r"(r[0]), "=r"(r[1]), "=r"(r[2]), "=r"(r[3]) : "r"(addr));
}
__device__ __forceinline__ void mma_bf16(float* c, const uint32_t* a, const uint32_t* b) {
    asm volatile("mma.sync.aligned.m16n8k16.row.col.f32.bf16.bf16.f32 "
        "{%0,%1,%2,%3}, {%4,%5,%6,%7}, {%8,%9}, {%0,%1,%2,%3};\n"
        : "+f"(c[0]), "+f"(c[1]), "+f"(c[2]), "+f"(c[3])
        : "r"(a[0]), "r"(a[1]), "r"(a[2]), "r"(a[3]), "r"(b[0]), "r"(b[1]));
}
__device__ __forceinline__ uint32_t pack_bf2(float a, float b) {
    __nv_bfloat162 h = __floats2bfloat162_rn(a, b);
    return *(uint32_t*)&h;
}
__device__ __forceinline__ void cp16(uint32_t dst, const void* src) {
    asm volatile("cp.async.ca.shared.global [%0], [%1], 16;" :: "r"(dst), "l"(src));
}
#define CP_COMMIT() asm volatile("cp.async.commit_group;")
__device__ __forceinline__ void cp_wait0() { asm volatile("cp.async.wait_group 0;"); }
__device__ __forceinline__ void cp_wait1() { asm volatile("cp.async.wait_group 1;"); }

// ---------------- weight convert + accumulator init ----------------
__global__ void cvt_all_kernel(const float* wq, const float* wa, const float* wi, const float* wo,
                               bf16* dq, bf16* da, bf16* di, bf16* dxo2,
                               float* nrm, float* attn) {
    int i = blockIdx.x * blockDim.x + threadIdx.x;
    const int s0 = CDIM * QKV, s1 = s0 + CDIM * CDIM, s2 = s1 + CDIM * H2;
    if (i < s0) dq[i] = __float2bfloat16_rn(wq[i]);
    else if (i < s1) da[i - s0] = __float2bfloat16_rn(wa[i - s0]);
    else if (i < s2) di[i - s1] = __float2bfloat16_rn(wi[i - s1]);
    if (i < HIDP * CDIM) {
        int r = i / CDIM;
        dxo2[i] = (r < HID) ? __float2bfloat16_rn(wo[i]) : __float2bfloat16_rn(0.f);
    }
    if (i < 2 * BATCH * CDIM) nrm[i] = 0.f;
    if (i < BATCH * HEADS * CH * CH) attn[i] = 0.f;
}

// ---------------- per-pixel LayerNorm -> bf16 ----------------
__global__ void ln_kernel(const float* __restrict__ in, const float* __restrict__ gamma,
                          const float* __restrict__ beta, bf16* __restrict__ out) {
    int warp = blockIdx.x * (blockDim.x >> 5) + (threadIdx.x >> 5);
    int lane = threadIdx.x & 31;
    int nwarps = gridDim.x * (blockDim.x >> 5);
    float g0 = gamma[lane], g1 = gamma[lane + 32], g2 = gamma[lane + 64];
    float b0 = beta[lane],  b1 = beta[lane + 32],  b2 = beta[lane + 64];
    for (int p = warp; p < NPIX; p += nwarps) {
        const float* xp = in + (size_t)p * CDIM;
        float v0 = xp[lane], v1 = xp[lane + 32], v2 = xp[lane + 64];
        float s  = v0 + v1 + v2;
        float ss = v0 * v0 + v1 * v1 + v2 * v2;
        #pragma unroll
        for (int o = 16; o > 0; o >>= 1) {
            s  += __shfl_xor_sync(0xffffffffu, s,  o);
            ss += __shfl_xor_sync(0xffffffffu, ss, o);
        }
        float mu = s * (1.f / 96.f);
        float var = ss * (1.f / 96.f) - mu * mu;
        float rstd = rsqrtf(var + 1e-5f);
        bf16* yp = out + (size_t)p * CDIM;
        yp[lane]      = __float2bfloat16_rn((v0 - mu) * rstd * g0 + b0);
        yp[lane + 32] = __float2bfloat16_rn((v1 - mu) * rstd * g1 + b1);
        yp[lane + 64] = __float2bfloat16_rn((v2 - mu) * rstd * g2 + b2);
    }
}

// ---------------- templated bf16 tensor-core GEMM (single-K-shot) ----------------
template<int NT, int BK, int KITER, bool BF16OUT>
__global__ void __launch_bounds__(256)
gemm_k(const bf16* __restrict__ A, const bf16* __restrict__ Bw,
       const float* __restrict__ R, void* __restrict__ Cout,
       int Ka, int Kb, int N) {
    constexpr int BN = NT * 16;
    constexpr int PA = BK + 8;
    constexpr int PB = BN + 8;
    __shared__ __align__(16) bf16 As[128][PA];
    __shared__ __align__(16) bf16 Bs[BK][PB];

    int tid = threadIdx.x;
    int m0 = blockIdx.y * 128;
    int n0 = blockIdx.x * BN;
    int lane = tid & 31, warp = tid >> 5;
    int g = lane >> 2, tg = lane & 3;
    int warpM = warp & 3, warpN = warp >> 2;
    int mbase = warpM * 32, nbase = warpN * (NT * 8);

    float acc[2][NT][4];
    #pragma unroll
    for (int mt = 0; mt < 2; mt++)
        #pragma unroll
        for (int nt = 0; nt < NT; nt++)
            #pragma unroll
            for (int i = 0; i < 4; i++) acc[mt][nt][i] = 0.f;

    uint32_t a_addr[2], b_addr[NT / 2];
    {
        int arow = lane & 15;
        int acol = (lane >> 4) << 3;
        #pragma unroll
        for (int mt = 0; mt < 2; mt++)
            a_addr[mt] = (uint32_t)__cvta_generic_to_shared(&As[mbase + mt * 16 + arow][acol]);
        int krow = ((lane >> 3) & 1) * 8 + (lane & 7);
        int coff = (lane >> 4) << 3;
        #pragma unroll
        for (int nh = 0; nh < NT / 2; nh++)
            b_addr[nh] = (uint32_t)__cvta_generic_to_shared(&Bs[krow][nbase + nh * 16 + coff]);
    }

    #pragma unroll
    for (int kit = 0; kit < KITER; kit++) {
        int k0 = kit * BK;
        constexpr int AC = BK / 8;
        constexpr int AL = 128 * AC / 256;
        #pragma unroll
        for (int l = 0; l < AL; l++) {
            int idx = tid + l * 256;
            int row = idx / AC, c8 = idx % AC;
            *(uint4*)&As[row][c8 * 8] =
                *(const uint4*)(A + (size_t)(m0 + row) * Ka + k0 + c8 * 8);
        }
        constexpr int BC = BN / 2;
        constexpr int BL = BK * BC / 256;
        #pragma unroll
        for (int l = 0; l < BL; l++) {
            int idx = tid + l * 256;
            int row = idx / BC, nu = idx % BC;
            int kk = k0 + row, col = n0 + nu * 2;
            uint32_t v = 0;
            if (kk < Kb && col < N) v = *(const uint32_t*)(Bw + (size_t)kk * N + col);
            *(uint32_t*)&Bs[row][nu * 2] = v;
        }
        __syncthreads();
        #pragma unroll
        for (int ks = 0; ks < BK / 16; ks++) {
            uint32_t af[2][4];
            #pragma unroll
            for (int mt = 0; mt < 2; mt++)
                ldsm_x4(af[mt], a_addr[mt] + ks * 32);
            #pragma unroll
            for (int nh = 0; nh < NT / 2; nh++) {
                uint32_t bq[4];
                ldsm_x4_t(bq, b_addr[nh] + ks * 16 * (PB * 2));
                #pragma unroll
                for (int mt = 0; mt < 2; mt++) {
                    mma_bf16(acc[mt][nh * 2 + 0], af[mt], &bq[0]);
                    mma_bf16(acc[mt][nh * 2 + 1], af[mt], &bq[2]);
                }
            }
        }
        if (kit + 1 < KITER) __syncthreads();
    }

    #pragma unroll
    for (int mt = 0; mt < 2; mt++) {
        #pragma unroll
        for (int nt = 0; nt < NT; nt++) {
            int col = n0 + nbase + nt * 8 + tg * 2;
            if (col >= N) continue;
            #pragma unroll
            for (int h = 0; h < 2; h++) {
                int row = m0 + mbase + mt * 16 + g + h * 8;
                size_t o = (size_t)row * N + col;
                float v0 = acc[mt][nt][h * 2 + 0];
                float v1 = acc[mt][nt][h * 2 + 1];
                if (R) {
                    float2 r2 = *(const float2*)(R + o);
                    v0 += r2.x; v1 += r2.y;
                }
                if (BF16OUT) *(uint32_t*)((bf16*)Cout + o) = pack_bf2(v0, v1);
                else *(float2*)((float*)Cout + o) = make_float2(v0, v1);
            }
        }
    }
}

// ---------------- dedicated ffn_out GEMM: K=256 (padded), B resident, A pipelined ----------------
__global__ void __launch_bounds__(256)
gemm_ffnout(const bf16* __restrict__ A, const bf16* __restrict__ Bw,
            const float* __restrict__ R, float* __restrict__ C) {
    constexpr int PA = 72, PB = 104;
    constexpr int ABUF = 128 * PA * 2;     // bytes per A buffer
    extern __shared__ char smraw[];
    uint32_t as_base = (uint32_t)__cvta_generic_to_shared(smraw);
    uint32_t bs_base = as_base + 2 * ABUF;
    bf16* Bsm = (bf16*)(smraw + 2 * ABUF);

    int tid = threadIdx.x, lane = tid & 31, warp = tid >> 5;
    int m0 = blockIdx.x * 128;
    int g = lane >> 2, tg = lane & 3;
    int warpM = warp & 3, warpN = warp >> 2;
    int mbase = warpM * 32, nbase = warpN * 48;

    // B resident: 256 x 96 -> 256 x PB
    #pragma unroll
    for (int l = 0; l < 48; l++) {
        int idx = tid + l * 256;           // 256*48 uint32
        int row = idx / 48, nu = idx % 48;
        *(uint32_t*)&Bsm[row * PB + nu * 2] = *(const uint32_t*)(Bw + (size_t)row * CDIM + nu * 2);
    }

    uint32_t a_addr[2], b_addr[3];
    {
        int arow = lane & 15, acol = (lane >> 4) << 3;
        a_addr[0] = as_base + (uint32_t)(((mbase + arow) * PA + acol) * 2);
        a_addr[1] = as_base + (uint32_t)(((mbase + 16 + arow) * PA + acol) * 2);
        int krow = ((lane >> 3) & 1) * 8 + (lane & 7);
        int coff = (lane >> 4) << 3;
        #pragma unroll
        for (int nh = 0; nh < 3; nh++)
            b_addr[nh] = bs_base + (uint32_t)((krow * PB + nbase + nh * 16 + coff) * 2);
    }

    // prefetch A chunk 0 (128 x 64)
    #pragma unroll
    for (int l = 0; l < 4; l++) {
        int idx = tid + l * 256;           // 1024 x 16B
        int row = idx >> 3, c8 = idx & 7;
        cp16(as_base + (uint32_t)((row * PA + c8 * 8) * 2),
             A + (size_t)(m0 + row) * HIDP + c8 * 8);
    }
    CP_COMMIT();

    float acc[2][6][4];
    #pragma unroll
    for (int a = 0; a < 2; a++)
        #pragma unroll
        for (int b = 0; b < 6; b++)
            #pragma unroll
            for (int c = 0; c < 4; c++) acc[a][b][c] = 0.f;

    int bufc = 0;
    #pragma unroll
    for (int kit = 0; kit < 4; kit++) {
        if (kit < 3) {
            int k0n = (kit + 1) * 64;
            uint32_t dstb = as_base + (uint32_t)((bufc ^ 1) * ABUF);
            #pragma unroll
            for (int l = 0; l < 4; l++) {
                int idx = tid + l * 256;
                int row = idx >> 3, c8 = idx & 7;
                cp16(dstb + (uint32_t)((row * PA + c8 * 8) * 2),
                     A + (size_t)(m0 + row) * HIDP + k0n + c8 * 8);
            }
            CP_COMMIT();
            cp_wait1();
        } else {
            cp_wait0();
        }
        __syncthreads();
        uint32_t abuf = (uint32_t)(bufc * ABUF);
        #pragma unroll
        for (int ks = 0; ks < 4; ks++) {
            uint32_t af[2][4];
            ldsm_x4(af[0], a_addr[0] + abuf + ks * 32);
            ldsm_x4(af[1], a_addr[1] + abuf + ks * 32);
            int kglob = kit * 64 + ks * 16;
            #pragma unroll
            for (int nh = 0; nh < 3; nh++) {
                uint32_t bq[4];
                ldsm_x4_t(bq, b_addr[nh] + kglob * (PB * 2));
                mma_bf16(acc[0][nh * 2 + 0], af[0], &bq[0]);
                mma_bf16(acc[0][nh * 2 + 1], af[0], &bq[2]);
                mma_bf16(acc[1][nh * 2 + 0], af[1], &bq[0]);
                mma_bf16(acc[1][nh * 2 + 1], af[1], &bq[2]);
            }
        }
        __syncthreads();
        bufc ^= 1;
    }

    #pragma unroll
    for (int mt = 0; mt < 2; mt++) {
        #pragma unroll
        for (int nt = 0; nt < 6; nt++) {
            int col = nbase + nt * 8 + tg * 2;
            #pragma unroll
            for (int h = 0; h < 2; h++) {
                int row = m0 + mbase + mt * 16 + g + h * 8;
                size_t o = (size_t)row * CDIM + col;
                float2 r2 = *(const float2*)(R + o);
                *(float2*)(C + o) = make_float2(acc[mt][nt][h * 2 + 0] + r2.x,
                                                acc[mt][nt][h * 2 + 1] + r2.y);
            }
        }
    }
}

// ---------------- attn_out GEMM (N=96, K=96) with fused residual + LayerNorm2 ----------------
__global__ void __launch_bounds__(256)
gemm_attnout_ln(const bf16* __restrict__ A, const bf16* __restrict__ Bw,
                const float* __restrict__ R, float* __restrict__ x2out,
                bf16* __restrict__ yout,
                const float* __restrict__ gamma, const float* __restrict__ beta) {
    constexpr int PA = 104, PB = 104;
    __shared__ __align__(16) char buf[49152];
    bf16* As = (bf16*)buf;
    bf16* Bs = (bf16*)buf + 128 * PA;

    int tid = threadIdx.x, lane = tid & 31, warp = tid >> 5;
    int m0 = blockIdx.x * 128;
    int g = lane >> 2, tg = lane & 3;
    int warpM = warp & 3, warpN = warp >> 2;
    int mbase = warpM * 32, nbase = warpN * 48;

    #pragma unroll
    for (int l = 0; l < 6; l++) {
        int idx = tid + l * 256;
        int row = idx / 12, c8 = idx % 12;
        *(uint4*)&As[row * PA + c8 * 8] = *(const uint4*)(A + (size_t)(m0 + row) * 96 + c8 * 8);
    }
    #pragma unroll
    for (int l = 0; l < 18; l++) {
        int idx = tid + l * 256;
        int row = idx / 48, nu = idx % 48;
        *(uint32_t*)&Bs[row * PB + nu * 2] = *(const uint32_t*)(Bw + (size_t)row * 96 + nu * 2);
    }
    __syncthreads();

    uint32_t a_addr[2], b_addr[3];
    {
        int arow = lane & 15, acol = (lane >> 4) << 3;
        #pragma unroll
        for (int mt = 0; mt < 2; mt++)
            a_addr[mt] = (uint32_t)__cvta_generic_to_shared(&As[(mbase + mt * 16 + arow) * PA + acol]);
        int krow = ((lane >> 3) & 1) * 8 + (lane & 7);
        int coff = (lane >> 4) << 3;
        #pragma unroll
        for (int nh = 0; nh < 3; nh++)
            b_addr[nh] = (uint32_t)__cvta_generic_to_shared(&Bs[krow * PB + nbase + nh * 16 + coff]);
    }

    float acc[2][6][4];
    #pragma unroll
    for (int mt = 0; mt < 2; mt++)
        #pragma unroll
        for (int nt = 0; nt < 6; nt++)
            #pragma unroll
            for (int i = 0; i < 4; i++) acc[mt][nt][i] = 0.f;

    #pragma unroll
    for (int ks = 0; ks < 6; ks++) {
        uint32_t af[2][4];
        ldsm_x4(af[0], a_addr[0] + ks * 32);
        ldsm_x4(af[1], a_addr[1] + ks * 32);
        #pragma unroll
        for (int nh = 0; nh < 3; nh++) {
            uint32_t bq[4];
            ldsm_x4_t(bq, b_addr[nh] + ks * 16 * (PB * 2));
            #pragma unroll
            for (int mt = 0; mt < 2; mt++) {
                mma_bf16(acc[mt][nh * 2 + 0], af[mt], &bq[0]);
                mma_bf16(acc[mt][nh * 2 + 1], af[mt], &bq[2]);
            }
        }
    }
    __syncthreads();

    float* sx = (float*)buf;
    #pragma unroll
    for (int mt = 0; mt < 2; mt++) {
        #pragma unroll
        for (int nt = 0; nt < 6; nt++) {
            int col = nbase + nt * 8 + tg * 2;
            #pragma unroll
            for (int h = 0; h < 2; h++) {
                int rl = mbase + mt * 16 + g + h * 8;
                size_t o = (size_t)(m0 + rl) * 96 + col;
                float2 r2 = *(const float2*)(R + o);
                float v0 = acc[mt][nt][h * 2 + 0] + r2.x;
                float v1 = acc[mt][nt][h * 2 + 1] + r2.y;
                *(float2*)(x2out + o) = make_float2(v0, v1);
                int t = (rl & 3) << 3;
                *(float2*)(sx + rl * 96 + (col ^ t)) = make_float2(v0, v1);
            }
        }
    }
    __syncthreads();

    float ga0 = gamma[lane], ga1 = gamma[lane + 32], ga2 = gamma[lane + 64];
    float be0 = beta[lane],  be1 = beta[lane + 32],  be2 = beta[lane + 64];
    #pragma unroll
    for (int i = 0; i < 16; i++) {
        int wr = warp * 16 + i;
        int t = (wr & 3) << 3;
        int c0 = lane ^ t;
        float v0 = sx[wr * 96 + c0];
        float v1 = sx[wr * 96 + c0 + 32];
        float v2 = sx[wr * 96 + c0 + 64];
        float s  = v0 + v1 + v2;
        float ss = v0 * v0 + v1 * v1 + v2 * v2;
        #pragma unroll
        for (int o = 16; o > 0; o >>= 1) {
            s  += __shfl_xor_sync(0xffffffffu, s,  o);
            ss += __shfl_xor_sync(0xffffffffu, ss, o);
        }
        float mu = s * (1.f / 96.f);
        float var = ss * (1.f / 96.f) - mu * mu;
        float rstd = rsqrtf(var + 1e-5f);
        bf16* yp = yout + (size_t)(m0 + wr) * 96;
        yp[lane]      = __float2bfloat16_rn((v0 - mu) * rstd * ga0 + be0);
        yp[lane + 32] = __float2bfloat16_rn((v1 - mu) * rstd * ga1 + be1);
        yp[lane + 64] = __float2bfloat16_rn((v2 - mu) * rstd * ga2 + be2);
    }
}

// ---------------- depthwise 3x3, C=288 bf16, 4-ch chunks, 4-wide x strip ----------------
__global__ void dwconv288_kernel(const bf16* __restrict__ in, const float* __restrict__ kern,
                                 bf16* __restrict__ out) {
    const int C4 = QKV / 4;
    int idx = blockIdx.x * blockDim.x + threadIdx.x;
    if (idx >= (NPIX / 4) * C4) return;
    int c4 = idx % C4;
    int strip = idx / C4;
    int xs = (strip & 63) * 4;
    int y  = (strip >> 6) & 255;
    int b  = strip >> 14;

    float acc[4][4];
    #pragma unroll
    for (int ox = 0; ox < 4; ox++)
        #pragma unroll
        for (int e = 0; e < 4; e++) acc[ox][e] = 0.f;

    #pragma unroll
    for (int dy = -1; dy <= 1; dy++) {
        int yy = y + dy;
        if (yy < 0 || yy > 255) continue;
        const bf16* rowp = in + ((size_t)((b << 8) + yy) << 8) * QKV;
        float v[6][4];
        #pragma unroll
        for (int j = 0; j < 6; j++) {
            int xx = xs - 1 + j;
            if (xx >= 0 && xx <= 255) {
                uint2 u = *(const uint2*)(rowp + (size_t)xx * QKV + c4 * 4);
                float2 f0 = __bfloat1622float2(((const __nv_bfloat162*)&u)[0]);
                float2 f1 = __bfloat1622float2(((const __nv_bfloat162*)&u)[1]);
                v[j][0] = f0.x; v[j][1] = f0.y; v[j][2] = f1.x; v[j][3] = f1.y;
            } else {
                #pragma unroll
                for (int e = 0; e < 4; e++) v[j][e] = 0.f;
            }
        }
        #pragma unroll
        for (int dx = 0; dx < 3; dx++) {
            float4 kv = *(const float4*)(kern + (size_t)((dy + 1) * 3 + dx) * QKV + c4 * 4);
            float kk[4] = {kv.x, kv.y, kv.z, kv.w};
            #pragma unroll
            for (int ox = 0; ox < 4; ox++)
                #pragma unroll
                for (int e = 0; e < 4; e++) acc[ox][e] += v[ox + dx][e] * kk[e];
        }
    }
    bf16* op = out + ((size_t)((b << 16) + (y << 8) + xs)) * QKV + c4 * 4;
    #pragma unroll
    for (int ox = 0; ox < 4; ox++) {
        uint2 u;
        ((uint32_t*)&u)[0] = pack_bf2(acc[ox][0], acc[ox][1]);
        ((uint32_t*)&u)[1] = pack_bf2(acc[ox][2], acc[ox][3]);
        *(uint2*)(op + (size_t)ox * QKV) = u;
    }
}

// ---------------- q*k^T accumulation + fused q/k sum-of-squares ----------------
__global__ void qkt_kernel(const bf16* __restrict__ t1, float* __restrict__ attn,
                           float* __restrict__ nrm) {
    __shared__ float qs[16][48];
    __shared__ float ks[16][48];
    __shared__ float nq[48], nk[48];
    int bh = blockIdx.y;
    int b = bh >> 1, hd = bh & 1;
    int s0 = blockIdx.x * 2048;
    int tid = threadIdx.x;
    if (tid < 48) { nq[tid] = 0.f; nk[tid] = 0.f; }
    int tx = tid & 15, ty = tid >> 4;
    float acc[3][3];
    #pragma unroll
    for (int r = 0; r < 3; r++)
        #pragma unroll
        for (int c = 0; c < 3; c++) acc[r][c] = 0.f;
    float sqq[3] = {0.f, 0.f, 0.f}, sqk[3] = {0.f, 0.f, 0.f};

    const bf16* qbase = t1 + ((size_t)(b << 16)) * QKV + hd * CH;
    const bf16* kbase = qbase + CDIM;
    for (int st = 0; st < 2048; st += 16) {
        #pragma unroll
        for (int l = 0; l < 3; l++) {
            int idx = tid + l * 256;
            int si = idx / 48, e = idx % 48;
            size_t off = (size_t)(s0 + st + si) * QKV + e;
            float qv = __bfloat162float(qbase[off]);
            float kv = __bfloat162float(kbase[off]);
            qs[si][e] = qv; ks[si][e] = kv;
            sqq[l] += qv * qv; sqk[l] += kv * kv;
        }
        __syncthreads();
        #pragma unroll
        for (int si = 0; si < 16; si++) {
            float qv[3], kv[3];
            #pragma unroll
            for (int r = 0; r < 3; r++) qv[r] = qs[si][ty * 3 + r];
            #pragma unroll
            for (int c = 0; c < 3; c++) kv[c] = ks[si][tx * 3 + c];
            #pragma unroll
            for (int r = 0; r < 3; r++)
                #pragma unroll
                for (int c = 0; c < 3; c++) acc[r][c] += qv[r] * kv[c];
        }
        __syncthreads();
    }
    #pragma unroll
    for (int l = 0; l < 3; l++) {
        int e = (tid + l * 256) % 48;
        atomicAdd(&nq[e], sqq[l]);
        atomicAdd(&nk[e], sqk[l]);
    }
    float* ab = attn + (size_t)bh * CH * CH;
    #pragma unroll
    for (int r = 0; r < 3; r++)
        #pragma unroll
        for (int c = 0; c < 3; c++)
            atomicAdd(&ab[(ty * 3 + r) * CH + (tx * 3 + c)], acc[r][c]);
    __syncthreads();
    if (tid < 48) {
        atomicAdd(&nrm[b * 192 + hd * CH + tid], nq[tid]);
        atomicAdd(&nrm[b * 192 + CDIM + hd * CH + tid], nk[tid]);
    }
}

// ---------------- normalize + temperature + softmax ----------------
__global__ void softmax_kernel(float* __restrict__ attn, const float* __restrict__ nrm,
                               const float* __restrict__ temp) {
    int bh = blockIdx.x;
    int b = bh >> 1, hd = bh & 1;
    int d = threadIdx.x;
    if (d >= CH) return;
    float t = temp[hd];
    float rq = rsqrtf(nrm[b * 192 + hd * CH + d]);
    float* row = attn + (size_t)bh * CH * CH + d * CH;
    float vals[CH];
    float mx = -1e30f;
    #pragma unroll
    for (int e = 0; e < CH; e++) {
        float rk = rsqrtf(nrm[b * 192 + CDIM + hd * CH + e]);
        float v = row[e] * rq * rk * t;
        vals[e] = v;
        mx = fmaxf(mx, v);
    }
    float s = 0.f;
    #pragma unroll
    for (int e = 0; e < CH; e++) { vals[e] = expf(vals[e] - mx); s += vals[e]; }
    float inv = 1.f / s;
    #pragma unroll
    for (int e = 0; e < CH; e++) row[e] = vals[e] * inv;
}

// ---------------- o = attn @ v (transposed attn in smem, conflict-free) ----------------
__global__ void attnapply_kernel(const bf16* __restrict__ t1, const float* __restrict__ attn,
                                 bf16* __restrict__ o) {
    __shared__ float at_t[CH][2 * CH + 4];   // [e][hd*48+cm], row stride 100
    __shared__ float vs[32][CDIM];
    int b = blockIdx.y;
    int p0 = blockIdx.x * 32;
    int tid = threadIdx.x;
    for (int i = tid; i < HEADS * CH * CH; i += 256) {
        int hd = i / (CH * CH);
        int rem = i - hd * CH * CH;
        int cm = rem / CH, e = rem % CH;
        at_t[e][hd * CH + cm] = attn[(size_t)b * HEADS * CH * CH + i];
    }
    const bf16* vbase = t1 + ((size_t)((b << 16) + p0)) * QKV + 2 * CDIM;
    #pragma unroll
    for (int l = 0; l < 6; l++) {
        int idx = tid + l * 256;
        int p = idx / 48, cu = idx % 48;
        uint32_t u = *(const uint32_t*)(vbase + (size_t)p * QKV + cu * 2);
        float2 f = __bfloat1622float2(*(__nv_bfloat162*)&u);
        vs[p][cu * 2] = f.x; vs[p][cu * 2 + 1] = f.y;
    }
    __syncthreads();
    bf16* obase = o + ((size_t)((b << 16) + p0)) * CDIM;
    #pragma unroll
    for (int l = 0; l < 12; l++) {
        int idx = tid + l * 256;
        int p = idx / CDIM, c = idx % CDIM;
        int hd = c / CH;
        const float* vrow = &vs[p][hd * CH];
        float s = 0.f;
        #pragma unroll
        for (int e = 0; e < CH; e++) s += at_t[e][c] * vrow[e];
        obase[(size_t)p * CDIM + c] = __float2bfloat16_rn(s);
    }
}

// ---------------- depthwise 3x3 on 510ch bf16 + GELU gate -> bf16 (stride 256) ----------------
__global__ void dwgate_kernel(const bf16* __restrict__ in, const float* __restrict__ kern,
                              bf16* __restrict__ out) {
    int idx = blockIdx.x * blockDim.x + threadIdx.x;
    if (idx >= (NPIX / 4) * HID) return;
    int c = idx % HID;
    int strip = idx / HID;
    int xs = (strip & 63) * 4;
    int y  = (strip >> 6) & 255;
    int b  = strip >> 14;

    float accA[4] = {0.f, 0.f, 0.f, 0.f};
    float accB[4] = {0.f, 0.f, 0.f, 0.f};

    #pragma unroll
    for (int dy = -1; dy <= 1; dy++) {
        int yy = y + dy;
        if (yy < 0 || yy > 255) continue;
        const bf16* rowp = in + ((size_t)((b << 8) + yy) << 8) * H2;
        float va[6], vb[6];
        #pragma unroll
        for (int j = 0; j < 6; j++) {
            int xx = xs - 1 + j;
            if (xx >= 0 && xx <= 255) {
                const bf16* pp = rowp + (size_t)xx * H2;
                va[j] = __bfloat162float(pp[c]);
                vb[j] = __bfloat162float(pp[c + HID]);
            } else {
                va[j] = 0.f; vb[j] = 0.f;
            }
        }
        #pragma unroll
        for (int dx = 0; dx < 3; dx++) {
            size_t koff = (size_t)((dy + 1) * 3 + dx) * H2;
            float ka = kern[koff + c];
            float kb = kern[koff + c + HID];
            #pragma unroll
            for (int ox = 0; ox < 4; ox++) {
                accA[ox] += va[ox + dx] * ka;
                accB[ox] += vb[ox + dx] * kb;
            }
        }
    }
    size_t pbase = (size_t)((b << 16) + (y << 8) + xs);
    #pragma unroll
    for (int ox = 0; ox < 4; ox++)
        out[(pbase + ox) * HIDP + c] = __float2bfloat16_rn(gelu_exact(accA[ox]) * accB[ox]);
    if (c == 0) {
        #pragma unroll
        for (int ox = 0; ox < 4; ox++) out[(pbase + ox) * HIDP + 255] = __float2bfloat16_rn(0.f);
    }
}

// ---------------- launcher ----------------
extern "C" void kernel_launch(void* const* d_in, const int* in_sizes, int n_in,
                              void* d_out, int out_size) {
    const float* x     = (const float*)d_in[0];
    const float* ln1g  = (const float*)d_in[1];
    const float* ln1b  = (const float*)d_in[2];
    const float* ln2g  = (const float*)d_in[3];
    const float* ln2b  = (const float*)d_in[4];
    const float* qkvw  = (const float*)d_in[5];
    const float* qkvdw = (const float*)d_in[6];
    const float* temp  = (const float*)d_in[7];
    const float* aow   = (const float*)d_in[8];
    const float* fiw   = (const float*)d_in[9];
    const float* fdw   = (const float*)d_in[10];
    const float* fow   = (const float*)d_in[11];
    float* out = (float*)d_out;

    bf16 *t0, *t1, *t2, *gt, *ybf, *wq, *wa, *wi, *wo2;
    float *x2, *nrm, *att;
    cudaGetSymbolAddress((void**)&t0,  g_t0);
    cudaGetSymbolAddress((void**)&t1,  g_t1);
    cudaGetSymbolAddress((void**)&t2,  g_t2);
    cudaGetSymbolAddress((void**)&gt,  g_gt);
    cudaGetSymbolAddress((void**)&ybf, g_ybf);
    cudaGetSymbolAddress((void**)&x2,  g_x2);
    cudaGetSymbolAddress((void**)&nrm, g_nrm);
    cudaGetSymbolAddress((void**)&att, g_att);
    cudaGetSymbolAddress((void**)&wq,  g_wq);
    cudaGetSymbolAddress((void**)&wa,  g_wa);
    cudaGetSymbolAddress((void**)&wi,  g_wi);
    cudaGetSymbolAddress((void**)&wo2, g_wo2);

    const int SMEM_FO = 2 * 128 * 72 * 2 + 256 * 104 * 2;  // 90112
    cudaFuncSetAttribute(gemm_ffnout, cudaFuncAttributeMaxDynamicSharedMemorySize, SMEM_FO);

    const int cvt_total = CDIM * QKV + CDIM * CDIM + CDIM * H2 + HID * CDIM;
    cvt_all_kernel<<<(cvt_total + 255) / 256, 256>>>(qkvw, aow, fiw, fow,
                                                     wq, wa, wi, wo2, nrm, att);

    // attention branch
    ln_kernel<<<2048, 256>>>(x, ln1g, ln1b, ybf);
    gemm_k<6, 96, 1, true><<<dim3(3, 1024), 256>>>(ybf, wq, nullptr, t0, CDIM, CDIM, QKV);
    dwconv288_kernel<<<(NPIX / 4) * 72 / 256, 256>>>(t0, qkvdw, t1);
    qkt_kernel<<<dim3(32, 4), 256>>>(t1, att, nrm);
    softmax_kernel<<<4, 64>>>(att, nrm, temp);
    attnapply_kernel<<<dim3(2048, 2), 256>>>(t1, att, ybf);
    // fused: x2 = ybf@wa + x ; ybf = LN2(x2)
    gemm_attnout_ln<<<1024, 256>>>(ybf, wa, x, x2, ybf, ln2g, ln2b);

    // FFN branch
    gemm_k<6, 96, 1, true><<<dim3(6, 1024), 256>>>(ybf, wi, nullptr, t2, CDIM, CDIM, H2);
    dwgate_kernel<<<((NPIX / 4) * HID + 255) / 256, 256>>>(t2, fdw, gt);
    gemm_ffnout<<<1024, 256, SMEM_FO>>>(gt, wo2, x2, out);
}

// round 10
// speedup vs baseline: 1.4959x; 1.0363x over previous
#include <cuda_runtime.h>
#include <cuda_bf16.h>
#include <math.h>
#include <stdint.h>

// ---------------- problem constants ----------------
#define BATCH 2
#define CDIM 96
#define HEADS 2
#define CH 48
#define QKV 288
#define HID 255
#define HIDP 256
#define H2 510
#define H2P 512
#define NPIX 131072

typedef __nv_bfloat16 bf16;

// ---------------- device scratch ----------------
__device__ __align__(256) bf16 g_t0[(size_t)NPIX * QKV];
__device__ __align__(256) bf16 g_t1[(size_t)NPIX * QKV];
__device__ __align__(256) bf16 g_t2[(size_t)NPIX * H2P];   // ffn hidden, 512-col remapped
__device__ __align__(256) bf16 g_gt[(size_t)NPIX * HIDP];
__device__ __align__(256) bf16 g_ybf[(size_t)NPIX * CDIM];
__device__ __align__(256) float g_x2[(size_t)NPIX * CDIM];
__device__ float g_nrm[2 * BATCH * CDIM];
__device__ float g_att[BATCH * HEADS * CH * CH];
__device__ __align__(256) bf16 g_wq[CDIM * QKV];
__device__ __align__(256) bf16 g_wa[CDIM * CDIM];
__device__ __align__(256) bf16 g_wip[CDIM * H2P];          // ffn_in weights, 512-col remapped
__device__ __align__(256) bf16 g_wo2[HIDP * CDIM];         // padded: row 255 = 0
__device__ __align__(256) float g_kwp[9 * H2P];            // dwgate weights, 512-col remapped

// ---------------- helpers ----------------
__device__ __forceinline__ float gelu_exact(float v) {
    return 0.5f * v * (1.0f + erff(v * 0.70710678118654752f));
}
__device__ __forceinline__ void ldsm_x4(uint32_t* r, uint32_t addr) {
    asm volatile("ldmatrix.sync.aligned.m8n8.x4.shared.b16 {%0,%1,%2,%3}, [%4];"
        : "=r"(r[0]), "=r"(r[1]), "=r"(r[2]), "=r"(r[3]) : "r"(addr));
}
__device__ __forceinline__ void ldsm_x4_t(uint32_t* r, uint32_t addr) {
    asm volatile("ldmatrix.sync.aligned.m8n8.x4.trans.shared.b16 {%0,%1,%2,%3}, [%4];"
        : "=r"(r[0]), "=r"(r[1]), "=r"(r[2]), "=r"(r[3]) : "r"(addr));
}
__device__ __forceinline__ void mma_bf16(float* c, const uint32_t* a, const uint32_t* b) {
    asm volatile("mma.sync.aligned.m16n8k16.row.col.f32.bf16.bf16.f32 "
        "{%0,%1,%2,%3}, {%4,%5,%6,%7}, {%8,%9}, {%0,%1,%2,%3};\n"
        : "+f"(c[0]), "+f"(c[1]), "+f"(c[2]), "+f"(c[3])
        : "r"(a[0]), "r"(a[1]), "r"(a[2]), "r"(a[3]), "r"(b[0]), "r"(b[1]));
}
__device__ __forceinline__ uint32_t pack_bf2(float a, float b) {
    __nv_bfloat162 h = __floats2bfloat162_rn(a, b);
    return *(uint32_t*)&h;
}
__device__ __forceinline__ void cp16(uint32_t dst, const void* src) {
    asm volatile("cp.async.ca.shared.global [%0], [%1], 16;" :: "r"(dst), "l"(src));
}
#define CP_COMMIT() asm volatile("cp.async.commit_group;")
__device__ __forceinline__ void cp_wait0() { asm volatile("cp.async.wait_group 0;"); }
__device__ __forceinline__ void cp_wait1() { asm volatile("cp.async.wait_group 1;"); }

// ---------------- weight convert / remap + accumulator init ----------------
__global__ void cvt_all_kernel(const float* wq, const float* wa, const float* wi, const float* wo,
                               const float* fdw,
                               bf16* dq, bf16* da, bf16* dip, bf16* dxo2,
                               float* kwp, float* nrm, float* attn) {
    int i = blockIdx.x * blockDim.x + threadIdx.x;
    const int s0 = CDIM * QKV, s1 = s0 + CDIM * CDIM;
    if (i < s0) dq[i] = __float2bfloat16_rn(wq[i]);
    else if (i < s1) da[i - s0] = __float2bfloat16_rn(wa[i - s0]);
    if (i < CDIM * H2P) {
        int r = i >> 9, c = i & 511;
        float v = 0.f;
        if (c < 255) v = wi[r * H2 + c];
        else if (c >= 256 && c <= 510) v = wi[r * H2 + c - 1];
        dip[i] = __float2bfloat16_rn(v);
    }
    if (i < HIDP * CDIM) {
        int r = i / CDIM;
        dxo2[i] = (r < HID) ? __float2bfloat16_rn(wo[i]) : __float2bfloat16_rn(0.f);
    }
    if (i < 9 * H2P) {
        int d = i >> 9, c = i & 511;
        float v = 0.f;
        if (c < 255) v = fdw[d * H2 + c];
        else if (c >= 256 && c <= 510) v = fdw[d * H2 + c - 1];
        kwp[i] = v;
    }
    if (i < 2 * BATCH * CDIM) nrm[i] = 0.f;
    if (i < BATCH * HEADS * CH * CH) attn[i] = 0.f;
}

// ---------------- per-pixel LayerNorm -> bf16 ----------------
__global__ void ln_kernel(const float* __restrict__ in, const float* __restrict__ gamma,
                          const float* __restrict__ beta, bf16* __restrict__ out) {
    int warp = blockIdx.x * (blockDim.x >> 5) + (threadIdx.x >> 5);
    int lane = threadIdx.x & 31;
    int nwarps = gridDim.x * (blockDim.x >> 5);
    float g0 = gamma[lane], g1 = gamma[lane + 32], g2 = gamma[lane + 64];
    float b0 = beta[lane],  b1 = beta[lane + 32],  b2 = beta[lane + 64];
    for (int p = warp; p < NPIX; p += nwarps) {
        const float* xp = in + (size_t)p * CDIM;
        float v0 = xp[lane], v1 = xp[lane + 32], v2 = xp[lane + 64];
        float s  = v0 + v1 + v2;
        float ss = v0 * v0 + v1 * v1 + v2 * v2;
        #pragma unroll
        for (int o = 16; o > 0; o >>= 1) {
            s  += __shfl_xor_sync(0xffffffffu, s,  o);
            ss += __shfl_xor_sync(0xffffffffu, ss, o);
        }
        float mu = s * (1.f / 96.f);
        float var = ss * (1.f / 96.f) - mu * mu;
        float rstd = rsqrtf(var + 1e-5f);
        bf16* yp = out + (size_t)p * CDIM;
        yp[lane]      = __float2bfloat16_rn((v0 - mu) * rstd * g0 + b0);
        yp[lane + 32] = __float2bfloat16_rn((v1 - mu) * rstd * g1 + b1);
        yp[lane + 64] = __float2bfloat16_rn((v2 - mu) * rstd * g2 + b2);
    }
}

// ---------------- templated bf16 tensor-core GEMM (single-K-shot) ----------------
template<int NT, int BK, int KITER, bool BF16OUT>
__global__ void __launch_bounds__(256)
gemm_k(const bf16* __restrict__ A, const bf16* __restrict__ Bw,
       const float* __restrict__ R, void* __restrict__ Cout,
       int Ka, int Kb, int N) {
    constexpr int BN = NT * 16;
    constexpr int PA = BK + 8;
    constexpr int PB = BN + 8;
    __shared__ __align__(16) bf16 As[128][PA];
    __shared__ __align__(16) bf16 Bs[BK][PB];

    int tid = threadIdx.x;
    int m0 = blockIdx.y * 128;
    int n0 = blockIdx.x * BN;
    int lane = tid & 31, warp = tid >> 5;
    int g = lane >> 2, tg = lane & 3;
    int warpM = warp & 3, warpN = warp >> 2;
    int mbase = warpM * 32, nbase = warpN * (NT * 8);

    float acc[2][NT][4];
    #pragma unroll
    for (int mt = 0; mt < 2; mt++)
        #pragma unroll
        for (int nt = 0; nt < NT; nt++)
            #pragma unroll
            for (int i = 0; i < 4; i++) acc[mt][nt][i] = 0.f;

    uint32_t a_addr[2], b_addr[NT / 2];
    {
        int arow = lane & 15;
        int acol = (lane >> 4) << 3;
        #pragma unroll
        for (int mt = 0; mt < 2; mt++)
            a_addr[mt] = (uint32_t)__cvta_generic_to_shared(&As[mbase + mt * 16 + arow][acol]);
        int krow = ((lane >> 3) & 1) * 8 + (lane & 7);
        int coff = (lane >> 4) << 3;
        #pragma unroll
        for (int nh = 0; nh < NT / 2; nh++)
            b_addr[nh] = (uint32_t)__cvta_generic_to_shared(&Bs[krow][nbase + nh * 16 + coff]);
    }

    #pragma unroll
    for (int kit = 0; kit < KITER; kit++) {
        int k0 = kit * BK;
        constexpr int AC = BK / 8;
        constexpr int AL = 128 * AC / 256;
        #pragma unroll
        for (int l = 0; l < AL; l++) {
            int idx = tid + l * 256;
            int row = idx / AC, c8 = idx % AC;
            *(uint4*)&As[row][c8 * 8] =
                *(const uint4*)(A + (size_t)(m0 + row) * Ka + k0 + c8 * 8);
        }
        constexpr int BC = BN / 2;
        constexpr int BL = BK * BC / 256;
        #pragma unroll
        for (int l = 0; l < BL; l++) {
            int idx = tid + l * 256;
            int row = idx / BC, nu = idx % BC;
            int kk = k0 + row, col = n0 + nu * 2;
            uint32_t v = 0;
            if (kk < Kb && col < N) v = *(const uint32_t*)(Bw + (size_t)kk * N + col);
            *(uint32_t*)&Bs[row][nu * 2] = v;
        }
        __syncthreads();
        #pragma unroll
        for (int ks = 0; ks < BK / 16; ks++) {
            uint32_t af[2][4];
            #pragma unroll
            for (int mt = 0; mt < 2; mt++)
                ldsm_x4(af[mt], a_addr[mt] + ks * 32);
            #pragma unroll
            for (int nh = 0; nh < NT / 2; nh++) {
                uint32_t bq[4];
                ldsm_x4_t(bq, b_addr[nh] + ks * 16 * (PB * 2));
                #pragma unroll
                for (int mt = 0; mt < 2; mt++) {
                    mma_bf16(acc[mt][nh * 2 + 0], af[mt], &bq[0]);
                    mma_bf16(acc[mt][nh * 2 + 1], af[mt], &bq[2]);
                }
            }
        }
        if (kit + 1 < KITER) __syncthreads();
    }

    #pragma unroll
    for (int mt = 0; mt < 2; mt++) {
        #pragma unroll
        for (int nt = 0; nt < NT; nt++) {
            int col = n0 + nbase + nt * 8 + tg * 2;
            if (col >= N) continue;
            #pragma unroll
            for (int h = 0; h < 2; h++) {
                int row = m0 + mbase + mt * 16 + g + h * 8;
                size_t o = (size_t)row * N + col;
                float v0 = acc[mt][nt][h * 2 + 0];
                float v1 = acc[mt][nt][h * 2 + 1];
                if (R) {
                    float2 r2 = *(const float2*)(R + o);
                    v0 += r2.x; v1 += r2.y;
                }
                if (BF16OUT) *(uint32_t*)((bf16*)Cout + o) = pack_bf2(v0, v1);
                else *(float2*)((float*)Cout + o) = make_float2(v0, v1);
            }
        }
    }
}

// ---------------- dedicated ffn_out GEMM: K=256 (padded), B resident, A pipelined ----------------
__global__ void __launch_bounds__(256)
gemm_ffnout(const bf16* __restrict__ A, const bf16* __restrict__ Bw,
            const float* __restrict__ R, float* __restrict__ C) {
    constexpr int PA = 72, PB = 104;
    constexpr int ABUF = 128 * PA * 2;
    extern __shared__ char smraw[];
    uint32_t as_base = (uint32_t)__cvta_generic_to_shared(smraw);
    uint32_t bs_base = as_base + 2 * ABUF;
    bf16* Bsm = (bf16*)(smraw + 2 * ABUF);

    int tid = threadIdx.x, lane = tid & 31, warp = tid >> 5;
    int m0 = blockIdx.x * 128;
    int g = lane >> 2, tg = lane & 3;
    int warpM = warp & 3, warpN = warp >> 2;
    int mbase = warpM * 32, nbase = warpN * 48;

    #pragma unroll
    for (int l = 0; l < 48; l++) {
        int idx = tid + l * 256;
        int row = idx / 48, nu = idx % 48;
        *(uint32_t*)&Bsm[row * PB + nu * 2] = *(const uint32_t*)(Bw + (size_t)row * CDIM + nu * 2);
    }

    uint32_t a_addr[2], b_addr[3];
    {
        int arow = lane & 15, acol = (lane >> 4) << 3;
        a_addr[0] = as_base + (uint32_t)(((mbase + arow) * PA + acol) * 2);
        a_addr[1] = as_base + (uint32_t)(((mbase + 16 + arow) * PA + acol) * 2);
        int krow = ((lane >> 3) & 1) * 8 + (lane & 7);
        int coff = (lane >> 4) << 3;
        #pragma unroll
        for (int nh = 0; nh < 3; nh++)
            b_addr[nh] = bs_base + (uint32_t)((krow * PB + nbase + nh * 16 + coff) * 2);
    }

    #pragma unroll
    for (int l = 0; l < 4; l++) {
        int idx = tid + l * 256;
        int row = idx >> 3, c8 = idx & 7;
        cp16(as_base + (uint32_t)((row * PA + c8 * 8) * 2),
             A + (size_t)(m0 + row) * HIDP + c8 * 8);
    }
    CP_COMMIT();

    float acc[2][6][4];
    #pragma unroll
    for (int a = 0; a < 2; a++)
        #pragma unroll
        for (int b = 0; b < 6; b++)
            #pragma unroll
            for (int c = 0; c < 4; c++) acc[a][b][c] = 0.f;

    int bufc = 0;
    #pragma unroll
    for (int kit = 0; kit < 4; kit++) {
        if (kit < 3) {
            int k0n = (kit + 1) * 64;
            uint32_t dstb = as_base + (uint32_t)((bufc ^ 1) * ABUF);
            #pragma unroll
            for (int l = 0; l < 4; l++) {
                int idx = tid + l * 256;
                int row = idx >> 3, c8 = idx & 7;
                cp16(dstb + (uint32_t)((row * PA + c8 * 8) * 2),
                     A + (size_t)(m0 + row) * HIDP + k0n + c8 * 8);
            }
            CP_COMMIT();
            cp_wait1();
        } else {
            cp_wait0();
        }
        __syncthreads();
        uint32_t abuf = (uint32_t)(bufc * ABUF);
        #pragma unroll
        for (int ks = 0; ks < 4; ks++) {
            uint32_t af[2][4];
            ldsm_x4(af[0], a_addr[0] + abuf + ks * 32);
            ldsm_x4(af[1], a_addr[1] + abuf + ks * 32);
            int kglob = kit * 64 + ks * 16;
            #pragma unroll
            for (int nh = 0; nh < 3; nh++) {
                uint32_t bq[4];
                ldsm_x4_t(bq, b_addr[nh] + kglob * (PB * 2));
                mma_bf16(acc[0][nh * 2 + 0], af[0], &bq[0]);
                mma_bf16(acc[0][nh * 2 + 1], af[0], &bq[2]);
                mma_bf16(acc[1][nh * 2 + 0], af[1], &bq[0]);
                mma_bf16(acc[1][nh * 2 + 1], af[1], &bq[2]);
            }
        }
        __syncthreads();
        bufc ^= 1;
    }

    #pragma unroll
    for (int mt = 0; mt < 2; mt++) {
        #pragma unroll
        for (int nt = 0; nt < 6; nt++) {
            int col = nbase + nt * 8 + tg * 2;
            #pragma unroll
            for (int h = 0; h < 2; h++) {
                int row = m0 + mbase + mt * 16 + g + h * 8;
                size_t o = (size_t)row * CDIM + col;
                float2 r2 = *(const float2*)(R + o);
                *(float2*)(C + o) = make_float2(acc[mt][nt][h * 2 + 0] + r2.x,
                                                acc[mt][nt][h * 2 + 1] + r2.y);
            }
        }
    }
}

// ---------------- attn_out GEMM (N=96, K=96) with fused residual + LayerNorm2 ----------------
__global__ void __launch_bounds__(256)
gemm_attnout_ln(const bf16* __restrict__ A, const bf16* __restrict__ Bw,
                const float* __restrict__ R, float* __restrict__ x2out,
                bf16* __restrict__ yout,
                const float* __restrict__ gamma, const float* __restrict__ beta) {
    constexpr int PA = 104, PB = 104;
    __shared__ __align__(16) char buf[49152];
    bf16* As = (bf16*)buf;
    bf16* Bs = (bf16*)buf + 128 * PA;

    int tid = threadIdx.x, lane = tid & 31, warp = tid >> 5;
    int m0 = blockIdx.x * 128;
    int g = lane >> 2, tg = lane & 3;
    int warpM = warp & 3, warpN = warp >> 2;
    int mbase = warpM * 32, nbase = warpN * 48;

    #pragma unroll
    for (int l = 0; l < 6; l++) {
        int idx = tid + l * 256;
        int row = idx / 12, c8 = idx % 12;
        *(uint4*)&As[row * PA + c8 * 8] = *(const uint4*)(A + (size_t)(m0 + row) * 96 + c8 * 8);
    }
    #pragma unroll
    for (int l = 0; l < 18; l++) {
        int idx = tid + l * 256;
        int row = idx / 48, nu = idx % 48;
        *(uint32_t*)&Bs[row * PB + nu * 2] = *(const uint32_t*)(Bw + (size_t)row * 96 + nu * 2);
    }
    __syncthreads();

    uint32_t a_addr[2], b_addr[3];
    {
        int arow = lane & 15, acol = (lane >> 4) << 3;
        #pragma unroll
        for (int mt = 0; mt < 2; mt++)
            a_addr[mt] = (uint32_t)__cvta_generic_to_shared(&As[(mbase + mt * 16 + arow) * PA + acol]);
        int krow = ((lane >> 3) & 1) * 8 + (lane & 7);
        int coff = (lane >> 4) << 3;
        #pragma unroll
        for (int nh = 0; nh < 3; nh++)
            b_addr[nh] = (uint32_t)__cvta_generic_to_shared(&Bs[krow * PB + nbase + nh * 16 + coff]);
    }

    float acc[2][6][4];
    #pragma unroll
    for (int mt = 0; mt < 2; mt++)
        #pragma unroll
        for (int nt = 0; nt < 6; nt++)
            #pragma unroll
            for (int i = 0; i < 4; i++) acc[mt][nt][i] = 0.f;

    #pragma unroll
    for (int ks = 0; ks < 6; ks++) {
        uint32_t af[2][4];
        ldsm_x4(af[0], a_addr[0] + ks * 32);
        ldsm_x4(af[1], a_addr[1] + ks * 32);
        #pragma unroll
        for (int nh = 0; nh < 3; nh++) {
            uint32_t bq[4];
            ldsm_x4_t(bq, b_addr[nh] + ks * 16 * (PB * 2));
            #pragma unroll
            for (int mt = 0; mt < 2; mt++) {
                mma_bf16(acc[mt][nh * 2 + 0], af[mt], &bq[0]);
                mma_bf16(acc[mt][nh * 2 + 1], af[mt], &bq[2]);
            }
        }
    }
    __syncthreads();

    float* sx = (float*)buf;
    #pragma unroll
    for (int mt = 0; mt < 2; mt++) {
        #pragma unroll
        for (int nt = 0; nt < 6; nt++) {
            int col = nbase + nt * 8 + tg * 2;
            #pragma unroll
            for (int h = 0; h < 2; h++) {
                int rl = mbase + mt * 16 + g + h * 8;
                size_t o = (size_t)(m0 + rl) * 96 + col;
                float2 r2 = *(const float2*)(R + o);
                float v0 = acc[mt][nt][h * 2 + 0] + r2.x;
                float v1 = acc[mt][nt][h * 2 + 1] + r2.y;
                *(float2*)(x2out + o) = make_float2(v0, v1);
                int t = (rl & 3) << 3;
                *(float2*)(sx + rl * 96 + (col ^ t)) = make_float2(v0, v1);
            }
        }
    }
    __syncthreads();

    float ga0 = gamma[lane], ga1 = gamma[lane + 32], ga2 = gamma[lane + 64];
    float be0 = beta[lane],  be1 = beta[lane + 32],  be2 = beta[lane + 64];
    #pragma unroll
    for (int i = 0; i < 16; i++) {
        int wr = warp * 16 + i;
        int t = (wr & 3) << 3;
        int c0 = lane ^ t;
        float v0 = sx[wr * 96 + c0];
        float v1 = sx[wr * 96 + c0 + 32];
        float v2 = sx[wr * 96 + c0 + 64];
        float s  = v0 + v1 + v2;
        float ss = v0 * v0 + v1 * v1 + v2 * v2;
        #pragma unroll
        for (int o = 16; o > 0; o >>= 1) {
            s  += __shfl_xor_sync(0xffffffffu, s,  o);
            ss += __shfl_xor_sync(0xffffffffu, ss, o);
        }
        float mu = s * (1.f / 96.f);
        float var = ss * (1.f / 96.f) - mu * mu;
        float rstd = rsqrtf(var + 1e-5f);
        bf16* yp = yout + (size_t)(m0 + wr) * 96;
        yp[lane]      = __float2bfloat16_rn((v0 - mu) * rstd * ga0 + be0);
        yp[lane + 32] = __float2bfloat16_rn((v1 - mu) * rstd * ga1 + be1);
        yp[lane + 64] = __float2bfloat16_rn((v2 - mu) * rstd * ga2 + be2);
    }
}

// ---------------- depthwise 3x3, C=288 bf16, 4-ch chunks, 4-wide x strip ----------------
__global__ void dwconv288_kernel(const bf16* __restrict__ in, const float* __restrict__ kern,
                                 bf16* __restrict__ out) {
    const int C4 = QKV / 4;
    int idx = blockIdx.x * blockDim.x + threadIdx.x;
    if (idx >= (NPIX / 4) * C4) return;
    int c4 = idx % C4;
    int strip = idx / C4;
    int xs = (strip & 63) * 4;
    int y  = (strip >> 6) & 255;
    int b  = strip >> 14;

    float acc[4][4];
    #pragma unroll
    for (int ox = 0; ox < 4; ox++)
        #pragma unroll
        for (int e = 0; e < 4; e++) acc[ox][e] = 0.f;

    #pragma unroll
    for (int dy = -1; dy <= 1; dy++) {
        int yy = y + dy;
        if (yy < 0 || yy > 255) continue;
        const bf16* rowp = in + ((size_t)((b << 8) + yy) << 8) * QKV;
        float v[6][4];
        #pragma unroll
        for (int j = 0; j < 6; j++) {
            int xx = xs - 1 + j;
            if (xx >= 0 && xx <= 255) {
                uint2 u = *(const uint2*)(rowp + (size_t)xx * QKV + c4 * 4);
                float2 f0 = __bfloat1622float2(((const __nv_bfloat162*)&u)[0]);
                float2 f1 = __bfloat1622float2(((const __nv_bfloat162*)&u)[1]);
                v[j][0] = f0.x; v[j][1] = f0.y; v[j][2] = f1.x; v[j][3] = f1.y;
            } else {
                #pragma unroll
                for (int e = 0; e < 4; e++) v[j][e] = 0.f;
            }
        }
        #pragma unroll
        for (int dx = 0; dx < 3; dx++) {
            float4 kv = *(const float4*)(kern + (size_t)((dy + 1) * 3 + dx) * QKV + c4 * 4);
            float kk[4] = {kv.x, kv.y, kv.z, kv.w};
            #pragma unroll
            for (int ox = 0; ox < 4; ox++)
                #pragma unroll
                for (int e = 0; e < 4; e++) acc[ox][e] += v[ox + dx][e] * kk[e];
        }
    }
    bf16* op = out + ((size_t)((b << 16) + (y << 8) + xs)) * QKV + c4 * 4;
    #pragma unroll
    for (int ox = 0; ox < 4; ox++) {
        uint2 u;
        ((uint32_t*)&u)[0] = pack_bf2(acc[ox][0], acc[ox][1]);
        ((uint32_t*)&u)[1] = pack_bf2(acc[ox][2], acc[ox][3]);
        *(uint2*)(op + (size_t)ox * QKV) = u;
    }
}

// ---------------- q*k^T accumulation + fused q/k sum-of-squares ----------------
__global__ void qkt_kernel(const bf16* __restrict__ t1, float* __restrict__ attn,
                           float* __restrict__ nrm) {
    __shared__ float qs[16][48];
    __shared__ float ks[16][48];
    __shared__ float nq[48], nk[48];
    int bh = blockIdx.y;
    int b = bh >> 1, hd = bh & 1;
    int s0 = blockIdx.x * 2048;
    int tid = threadIdx.x;
    if (tid < 48) { nq[tid] = 0.f; nk[tid] = 0.f; }
    int tx = tid & 15, ty = tid >> 4;
    float acc[3][3];
    #pragma unroll
    for (int r = 0; r < 3; r++)
        #pragma unroll
        for (int c = 0; c < 3; c++) acc[r][c] = 0.f;
    float sqq[3] = {0.f, 0.f, 0.f}, sqk[3] = {0.f, 0.f, 0.f};

    const bf16* qbase = t1 + ((size_t)(b << 16)) * QKV + hd * CH;
    const bf16* kbase = qbase + CDIM;
    for (int st = 0; st < 2048; st += 16) {
        #pragma unroll
        for (int l = 0; l < 3; l++) {
            int idx = tid + l * 256;
            int si = idx / 48, e = idx % 48;
            size_t off = (size_t)(s0 + st + si) * QKV + e;
            float qv = __bfloat162float(qbase[off]);
            float kv = __bfloat162float(kbase[off]);
            qs[si][e] = qv; ks[si][e] = kv;
            sqq[l] += qv * qv; sqk[l] += kv * kv;
        }
        __syncthreads();
        #pragma unroll
        for (int si = 0; si < 16; si++) {
            float qv[3], kv[3];
            #pragma unroll
            for (int r = 0; r < 3; r++) qv[r] = qs[si][ty * 3 + r];
            #pragma unroll
            for (int c = 0; c < 3; c++) kv[c] = ks[si][tx * 3 + c];
            #pragma unroll
            for (int r = 0; r < 3; r++)
                #pragma unroll
                for (int c = 0; c < 3; c++) acc[r][c] += qv[r] * kv[c];
        }
        __syncthreads();
    }
    #pragma unroll
    for (int l = 0; l < 3; l++) {
        int e = (tid + l * 256) % 48;
        atomicAdd(&nq[e], sqq[l]);
        atomicAdd(&nk[e], sqk[l]);
    }
    float* ab = attn + (size_t)bh * CH * CH;
    #pragma unroll
    for (int r = 0; r < 3; r++)
        #pragma unroll
        for (int c = 0; c < 3; c++)
            atomicAdd(&ab[(ty * 3 + r) * CH + (tx * 3 + c)], acc[r][c]);
    __syncthreads();
    if (tid < 48) {
        atomicAdd(&nrm[b * 192 + hd * CH + tid], nq[tid]);
        atomicAdd(&nrm[b * 192 + CDIM + hd * CH + tid], nk[tid]);
    }
}

// ---------------- normalize + temperature + softmax ----------------
__global__ void softmax_kernel(float* __restrict__ attn, const float* __restrict__ nrm,
                               const float* __restrict__ temp) {
    int bh = blockIdx.x;
    int b = bh >> 1, hd = bh & 1;
    int d = threadIdx.x;
    if (d >= CH) return;
    float t = temp[hd];
    float rq = rsqrtf(nrm[b * 192 + hd * CH + d]);
    float* row = attn + (size_t)bh * CH * CH + d * CH;
    float vals[CH];
    float mx = -1e30f;
    #pragma unroll
    for (int e = 0; e < CH; e++) {
        float rk = rsqrtf(nrm[b * 192 + CDIM + hd * CH + e]);
        float v = row[e] * rq * rk * t;
        vals[e] = v;
        mx = fmaxf(mx, v);
    }
    float s = 0.f;
    #pragma unroll
    for (int e = 0; e < CH; e++) { vals[e] = expf(vals[e] - mx); s += vals[e]; }
    float inv = 1.f / s;
    #pragma unroll
    for (int e = 0; e < CH; e++) row[e] = vals[e] * inv;
}

// ---------------- o = attn @ v (transposed attn in smem, conflict-free) ----------------
__global__ void attnapply_kernel(const bf16* __restrict__ t1, const float* __restrict__ attn,
                                 bf16* __restrict__ o) {
    __shared__ float at_t[CH][2 * CH + 4];
    __shared__ float vs[32][CDIM];
    int b = blockIdx.y;
    int p0 = blockIdx.x * 32;
    int tid = threadIdx.x;
    for (int i = tid; i < HEADS * CH * CH; i += 256) {
        int hd = i / (CH * CH);
        int rem = i - hd * CH * CH;
        int cm = rem / CH, e = rem % CH;
        at_t[e][hd * CH + cm] = attn[(size_t)b * HEADS * CH * CH + i];
    }
    const bf16* vbase = t1 + ((size_t)((b << 16) + p0)) * QKV + 2 * CDIM;
    #pragma unroll
    for (int l = 0; l < 6; l++) {
        int idx = tid + l * 256;
        int p = idx / 48, cu = idx % 48;
        uint32_t u = *(const uint32_t*)(vbase + (size_t)p * QKV + cu * 2);
        float2 f = __bfloat1622float2(*(__nv_bfloat162*)&u);
        vs[p][cu * 2] = f.x; vs[p][cu * 2 + 1] = f.y;
    }
    __syncthreads();
    bf16* obase = o + ((size_t)((b << 16) + p0)) * CDIM;
    #pragma unroll
    for (int l = 0; l < 12; l++) {
        int idx = tid + l * 256;
        int p = idx / CDIM, c = idx % CDIM;
        int hd = c / CH;
        const float* vrow = &vs[p][hd * CH];
        float s = 0.f;
        #pragma unroll
        for (int e = 0; e < CH; e++) s += at_t[e][c] * vrow[e];
        obase[(size_t)p * CDIM + c] = __float2bfloat16_rn(s);
    }
}

// ---------------- depthwise 3x3 + GELU gate: 512-col layout, 2ch x 4px, all vector loads ----------------
__global__ void dwgate_kernel(const bf16* __restrict__ in, const float* __restrict__ kwp,
                              bf16* __restrict__ out) {
    int idx = blockIdx.x * blockDim.x + threadIdx.x;   // (NPIX/4) * 128
    int c2 = idx & 127;
    int strip = idx >> 7;
    int xs = (strip & 63) * 4;
    int y  = (strip >> 6) & 255;
    int b  = strip >> 14;

    float accA[4][2], accB[4][2];
    #pragma unroll
    for (int ox = 0; ox < 4; ox++) {
        accA[ox][0] = 0.f; accA[ox][1] = 0.f;
        accB[ox][0] = 0.f; accB[ox][1] = 0.f;
    }

    #pragma unroll
    for (int dy = -1; dy <= 1; dy++) {
        int yy = y + dy;
        if (yy < 0 || yy > 255) continue;
        const bf16* rowp = in + (((size_t)((b << 8) + yy) << 8) << 9);   // *512
        float va[6][2], vb[6][2];
        #pragma unroll
        for (int j = 0; j < 6; j++) {
            int xx = xs - 1 + j;
            if (xx >= 0 && xx <= 255) {
                const bf16* pp = rowp + ((size_t)xx << 9) + c2 * 2;
                uint32_t u1 = *(const uint32_t*)pp;
                uint32_t u2 = *(const uint32_t*)(pp + 256);
                float2 f1 = __bfloat1622float2(*(__nv_bfloat162*)&u1);
                float2 f2 = __bfloat1622float2(*(__nv_bfloat162*)&u2);
                va[j][0] = f1.x; va[j][1] = f1.y;
                vb[j][0] = f2.x; vb[j][1] = f2.y;
            } else {
                va[j][0] = 0.f; va[j][1] = 0.f;
                vb[j][0] = 0.f; vb[j][1] = 0.f;
            }
        }
        #pragma unroll
        for (int dx = 0; dx < 3; dx++) {
            int ki = (dy + 1) * 3 + dx;
            float2 k1 = *(const float2*)(kwp + ki * H2P + c2 * 2);
            float2 k2 = *(const float2*)(kwp + ki * H2P + 256 + c2 * 2);
            #pragma unroll
            for (int ox = 0; ox < 4; ox++) {
                accA[ox][0] += va[ox + dx][0] * k1.x;
                accA[ox][1] += va[ox + dx][1] * k1.y;
                accB[ox][0] += vb[ox + dx][0] * k2.x;
                accB[ox][1] += vb[ox + dx][1] * k2.y;
            }
        }
    }
    size_t pbase = (size_t)((b << 16) + (y << 8) + xs);
    #pragma unroll
    for (int ox = 0; ox < 4; ox++) {
        float g0 = gelu_exact(accA[ox][0]) * accB[ox][0];
        float g1 = gelu_exact(accA[ox][1]) * accB[ox][1];
        *(uint32_t*)(out + (pbase + ox) * HIDP + c2 * 2) = pack_bf2(g0, g1);
    }
}

// ---------------- launcher ----------------
extern "C" void kernel_launch(void* const* d_in, const int* in_sizes, int n_in,
                              void* d_out, int out_size) {
    const float* x     = (const float*)d_in[0];
    const float* ln1g  = (const float*)d_in[1];
    const float* ln1b  = (const float*)d_in[2];
    const float* ln2g  = (const float*)d_in[3];
    const float* ln2b  = (const float*)d_in[4];
    const float* qkvw  = (const float*)d_in[5];
    const float* qkvdw = (const float*)d_in[6];
    const float* temp  = (const float*)d_in[7];
    const float* aow   = (const float*)d_in[8];
    const float* fiw   = (const float*)d_in[9];
    const float* fdw   = (const float*)d_in[10];
    const float* fow   = (const float*)d_in[11];
    float* out = (float*)d_out;

    bf16 *t0, *t1, *t2, *gt, *ybf, *wq, *wa, *wip, *wo2;
    float *x2, *nrm, *att, *kwp;
    cudaGetSymbolAddress((void**)&t0,  g_t0);
    cudaGetSymbolAddress((void**)&t1,  g_t1);
    cudaGetSymbolAddress((void**)&t2,  g_t2);
    cudaGetSymbolAddress((void**)&gt,  g_gt);
    cudaGetSymbolAddress((void**)&ybf, g_ybf);
    cudaGetSymbolAddress((void**)&x2,  g_x2);
    cudaGetSymbolAddress((void**)&nrm, g_nrm);
    cudaGetSymbolAddress((void**)&att, g_att);
    cudaGetSymbolAddress((void**)&wq,  g_wq);
    cudaGetSymbolAddress((void**)&wa,  g_wa);
    cudaGetSymbolAddress((void**)&wip, g_wip);
    cudaGetSymbolAddress((void**)&wo2, g_wo2);
    cudaGetSymbolAddress((void**)&kwp, g_kwp);

    const int SMEM_FO = 2 * 128 * 72 * 2 + 256 * 104 * 2;  // 90112
    cudaFuncSetAttribute(gemm_ffnout, cudaFuncAttributeMaxDynamicSharedMemorySize, SMEM_FO);

    const int cvt_total = CDIM * QKV + CDIM * CDIM + CDIM * H2P + HID * CDIM;
    cvt_all_kernel<<<(cvt_total + 255) / 256, 256>>>(qkvw, aow, fiw, fow, fdw,
                                                     wq, wa, wip, wo2, kwp, nrm, att);

    // attention branch
    ln_kernel<<<2048, 256>>>(x, ln1g, ln1b, ybf);
    gemm_k<6, 96, 1, true><<<dim3(3, 1024), 256>>>(ybf, wq, nullptr, t0, CDIM, CDIM, QKV);
    dwconv288_kernel<<<(NPIX / 4) * 72 / 256, 256>>>(t0, qkvdw, t1);
    qkt_kernel<<<dim3(32, 4), 256>>>(t1, att, nrm);
    softmax_kernel<<<4, 64>>>(att, nrm, temp);
    attnapply_kernel<<<dim3(2048, 2), 256>>>(t1, att, ybf);
    // fused: x2 = ybf@wa + x ; ybf = LN2(x2)
    gemm_attnout_ln<<<1024, 256>>>(ybf, wa, x, x2, ybf, ln2g, ln2b);

    // FFN branch (512-col remapped hidden layout)
    gemm_k<6, 96, 1, true><<<dim3(6, 1024), 256>>>(ybf, wip, nullptr, t2, CDIM, CDIM, H2P);
    dwgate_kernel<<<(NPIX / 4) * 128 / 256, 256>>>(t2, kwp, gt);
    gemm_ffnout<<<1024, 256, SMEM_FO>>>(gt, wo2, x2, out);
}

// round 11
// speedup vs baseline: 1.5619x; 1.0441x over previous
#include <cuda_runtime.h>
#include <cuda_bf16.h>
#include <math.h>
#include <stdint.h>

// ---------------- problem constants ----------------
#define BATCH 2
#define CDIM 96
#define HEADS 2
#define CH 48
#define QKV 288
#define HID 255
#define HIDP 256
#define H2 510
#define H2P 512
#define NPIX 131072

typedef __nv_bfloat16 bf16;

// ---------------- device scratch ----------------
__device__ __align__(256) bf16 g_t0[(size_t)NPIX * QKV];
__device__ __align__(256) bf16 g_t1[(size_t)NPIX * QKV];
__device__ __align__(256) bf16 g_t2[(size_t)NPIX * H2P];
__device__ __align__(256) bf16 g_gt[(size_t)NPIX * HIDP];
__device__ __align__(256) bf16 g_ybf[(size_t)NPIX * CDIM];
__device__ __align__(256) float g_x2[(size_t)NPIX * CDIM];
__device__ float g_nrm[2 * BATCH * CDIM];
__device__ float g_att[BATCH * HEADS * CH * CH];
__device__ __align__(256) bf16 g_wq[CDIM * QKV];
__device__ __align__(256) bf16 g_wa[CDIM * CDIM];
__device__ __align__(256) bf16 g_wip[CDIM * H2P];
__device__ __align__(256) bf16 g_wo2[HIDP * CDIM];
__device__ __align__(256) float g_kwp[9 * H2P];

// ---------------- helpers ----------------
__device__ __forceinline__ float gelu_exact(float v) {
    return 0.5f * v * (1.0f + erff(v * 0.70710678118654752f));
}
__device__ __forceinline__ void ldsm_x4(uint32_t* r, uint32_t addr) {
    asm volatile("ldmatrix.sync.aligned.m8n8.x4.shared.b16 {%0,%1,%2,%3}, [%4];"
        : "=r"(r[0]), "=r"(r[1]), "=r"(r[2]), "=r"(r[3]) : "r"(addr));
}
__device__ __forceinline__ void ldsm_x4_t(uint32_t* r, uint32_t addr) {
    asm volatile("ldmatrix.sync.aligned.m8n8.x4.trans.shared.b16 {%0,%1,%2,%3}, [%4];"
        : "=r"(r[0]), "=r"(r[1]), "=r"(r[2]), "=r"(r[3]) : "r"(addr));
}
__device__ __forceinline__ void mma_bf16(float* c, const uint32_t* a, const uint32_t* b) {
    asm volatile("mma.sync.aligned.m16n8k16.row.col.f32.bf16.bf16.f32 "
        "{%0,%1,%2,%3}, {%4,%5,%6,%7}, {%8,%9}, {%0,%1,%2,%3};\n"
        : "+f"(c[0]), "+f"(c[1]), "+f"(c[2]), "+f"(c[3])
        : "r"(a[0]), "r"(a[1]), "r"(a[2]), "r"(a[3]), "r"(b[0]), "r"(b[1]));
}
__device__ __forceinline__ uint32_t pack_bf2(float a, float b) {
    __nv_bfloat162 h = __floats2bfloat162_rn(a, b);
    return *(uint32_t*)&h;
}
__device__ __forceinline__ void cp16(uint32_t dst, const void* src) {
    asm volatile("cp.async.ca.shared.global [%0], [%1], 16;" :: "r"(dst), "l"(src));
}
#define CP_COMMIT() asm volatile("cp.async.commit_group;")
__device__ __forceinline__ void cp_wait0() { asm volatile("cp.async.wait_group 0;"); }
__device__ __forceinline__ void cp_wait1() { asm volatile("cp.async.wait_group 1;"); }

// ---------------- weight convert / remap + accumulator init ----------------
__global__ void cvt_all_kernel(const float* wq, const float* wa, const float* wi, const float* wo,
                               const float* fdw,
                               bf16* dq, bf16* da, bf16* dip, bf16* dxo2,
                               float* kwp, float* nrm, float* attn) {
    int i = blockIdx.x * blockDim.x + threadIdx.x;
    const int s0 = CDIM * QKV, s1 = s0 + CDIM * CDIM;
    if (i < s0) dq[i] = __float2bfloat16_rn(wq[i]);
    else if (i < s1) da[i - s0] = __float2bfloat16_rn(wa[i - s0]);
    if (i < CDIM * H2P) {
        int r = i >> 9, c = i & 511;
        float v = 0.f;
        if (c < 255) v = wi[r * H2 + c];
        else if (c >= 256 && c <= 510) v = wi[r * H2 + c - 1];
        dip[i] = __float2bfloat16_rn(v);
    }
    if (i < HIDP * CDIM) {
        int r = i / CDIM;
        dxo2[i] = (r < HID) ? __float2bfloat16_rn(wo[i]) : __float2bfloat16_rn(0.f);
    }
    if (i < 9 * H2P) {
        int d = i >> 9, c = i & 511;
        float v = 0.f;
        if (c < 255) v = fdw[d * H2 + c];
        else if (c >= 256 && c <= 510) v = fdw[d * H2 + c - 1];
        kwp[i] = v;
    }
    if (i < 2 * BATCH * CDIM) nrm[i] = 0.f;
    if (i < BATCH * HEADS * CH * CH) attn[i] = 0.f;
}

// ---------------- generic B-resident GEMM, K=96, multi-pass N, optional fused LN on A ----------------
// Block computes rows [m0, m0+128) x cols [ncol0, ncol0+NPASS*NT*16).
// FUSE_LN: A tile = LayerNorm(Xf rows) computed in-kernel; else A loaded from bf16.
template<int NPASS, int NT, bool FUSE_LN>
__global__ void __launch_bounds__(256)
gemm_bres(const bf16* __restrict__ Abf, const float* __restrict__ Xf,
          const float* __restrict__ gamma, const float* __restrict__ beta,
          const bf16* __restrict__ Bw, bf16* __restrict__ Cout, int Nglob) {
    constexpr int PASSW = NT * 16;
    constexpr int BCOLS = NPASS * PASSW;
    constexpr int PA = 104;
    constexpr int PB = BCOLS + 8;
    extern __shared__ char smraw[];
    bf16* As = (bf16*)smraw;                    // 128 * PA
    bf16* Bs = (bf16*)smraw + 128 * PA;         // 96 * PB
    uint32_t as_base = (uint32_t)__cvta_generic_to_shared(smraw);
    uint32_t bs_base = as_base + 128 * PA * 2;

    int tid = threadIdx.x, lane = tid & 31, warp = tid >> 5;
    int m0 = blockIdx.y * 128;
    int ncol0 = blockIdx.x * BCOLS;
    int g = lane >> 2, tg = lane & 3;
    int warpM = warp & 3, warpN = warp >> 2;
    int mbase = warpM * 32, nbase = warpN * (NT * 8);

    // B slice load (96 x BCOLS), no guards (exact multiples)
    constexpr int BU = 96 * (BCOLS / 2);
    #pragma unroll
    for (int l = 0; l < BU / 256; l++) {
        int idx = tid + l * 256;
        int row = idx / (BCOLS / 2), nu = idx % (BCOLS / 2);
        *(uint32_t*)&Bs[row * PB + nu * 2] =
            *(const uint32_t*)(Bw + (size_t)row * Nglob + ncol0 + nu * 2);
    }

    // A tile
    if (FUSE_LN) {
        float ga0 = gamma[lane], ga1 = gamma[lane + 32], ga2 = gamma[lane + 64];
        float be0 = beta[lane],  be1 = beta[lane + 32],  be2 = beta[lane + 64];
        #pragma unroll
        for (int i = 0; i < 16; i++) {
            int row = warp * 16 + i;
            const float* xp = Xf + (size_t)(m0 + row) * CDIM;
            float v0 = xp[lane], v1 = xp[lane + 32], v2 = xp[lane + 64];
            float s  = v0 + v1 + v2;
            float ss = v0 * v0 + v1 * v1 + v2 * v2;
            #pragma unroll
            for (int o = 16; o > 0; o >>= 1) {
                s  += __shfl_xor_sync(0xffffffffu, s,  o);
                ss += __shfl_xor_sync(0xffffffffu, ss, o);
            }
            float mu = s * (1.f / 96.f);
            float var = ss * (1.f / 96.f) - mu * mu;
            float rstd = rsqrtf(var + 1e-5f);
            As[row * PA + lane]      = __float2bfloat16_rn((v0 - mu) * rstd * ga0 + be0);
            As[row * PA + lane + 32] = __float2bfloat16_rn((v1 - mu) * rstd * ga1 + be1);
            As[row * PA + lane + 64] = __float2bfloat16_rn((v2 - mu) * rstd * ga2 + be2);
        }
    } else {
        #pragma unroll
        for (int l = 0; l < 6; l++) {
            int idx = tid + l * 256;
            int row = idx / 12, c8 = idx % 12;
            *(uint4*)&As[row * PA + c8 * 8] =
                *(const uint4*)(Abf + (size_t)(m0 + row) * CDIM + c8 * 8);
        }
    }
    __syncthreads();

    uint32_t a_addr[2], b_addr0[NT / 2];
    {
        int arow = lane & 15, acol = (lane >> 4) << 3;
        a_addr[0] = as_base + (uint32_t)(((mbase + arow) * PA + acol) * 2);
        a_addr[1] = as_base + (uint32_t)(((mbase + 16 + arow) * PA + acol) * 2);
        int krow = ((lane >> 3) & 1) * 8 + (lane & 7);
        int coff = (lane >> 4) << 3;
        #pragma unroll
        for (int nh = 0; nh < NT / 2; nh++)
            b_addr0[nh] = bs_base + (uint32_t)((krow * PB + nbase + nh * 16 + coff) * 2);
    }

    #pragma unroll
    for (int pass = 0; pass < NPASS; pass++) {
        float acc[2][NT][4];
        #pragma unroll
        for (int mt = 0; mt < 2; mt++)
            #pragma unroll
            for (int nt = 0; nt < NT; nt++)
                #pragma unroll
                for (int i = 0; i < 4; i++) acc[mt][nt][i] = 0.f;

        uint32_t poff = (uint32_t)(pass * PASSW * 2);
        #pragma unroll
        for (int ks = 0; ks < 6; ks++) {
            uint32_t af[2][4];
            ldsm_x4(af[0], a_addr[0] + ks * 32);
            ldsm_x4(af[1], a_addr[1] + ks * 32);
            #pragma unroll
            for (int nh = 0; nh < NT / 2; nh++) {
                uint32_t bq[4];
                ldsm_x4_t(bq, b_addr0[nh] + poff + ks * 16 * (PB * 2));
                #pragma unroll
                for (int mt = 0; mt < 2; mt++) {
                    mma_bf16(acc[mt][nh * 2 + 0], af[mt], &bq[0]);
                    mma_bf16(acc[mt][nh * 2 + 1], af[mt], &bq[2]);
                }
            }
        }
        // epilogue (bf16, no residual)
        #pragma unroll
        for (int mt = 0; mt < 2; mt++) {
            #pragma unroll
            for (int nt = 0; nt < NT; nt++) {
                int col = ncol0 + pass * PASSW + nbase + nt * 8 + tg * 2;
                #pragma unroll
                for (int h = 0; h < 2; h++) {
                    int row = m0 + mbase + mt * 16 + g + h * 8;
                    size_t o = (size_t)row * Nglob + col;
                    *(uint32_t*)(Cout + o) = pack_bf2(acc[mt][nt][h * 2 + 0],
                                                      acc[mt][nt][h * 2 + 1]);
                }
            }
        }
    }
}

// ---------------- dedicated ffn_out GEMM: K=256 (padded), B resident, A pipelined ----------------
__global__ void __launch_bounds__(256)
gemm_ffnout(const bf16* __restrict__ A, const bf16* __restrict__ Bw,
            const float* __restrict__ R, float* __restrict__ C) {
    constexpr int PA = 72, PB = 104;
    constexpr int ABUF = 128 * PA * 2;
    extern __shared__ char smraw[];
    uint32_t as_base = (uint32_t)__cvta_generic_to_shared(smraw);
    uint32_t bs_base = as_base + 2 * ABUF;
    bf16* Bsm = (bf16*)(smraw + 2 * ABUF);

    int tid = threadIdx.x, lane = tid & 31, warp = tid >> 5;
    int m0 = blockIdx.x * 128;
    int g = lane >> 2, tg = lane & 3;
    int warpM = warp & 3, warpN = warp >> 2;
    int mbase = warpM * 32, nbase = warpN * 48;

    #pragma unroll
    for (int l = 0; l < 48; l++) {
        int idx = tid + l * 256;
        int row = idx / 48, nu = idx % 48;
        *(uint32_t*)&Bsm[row * PB + nu * 2] = *(const uint32_t*)(Bw + (size_t)row * CDIM + nu * 2);
    }

    uint32_t a_addr[2], b_addr[3];
    {
        int arow = lane & 15, acol = (lane >> 4) << 3;
        a_addr[0] = as_base + (uint32_t)(((mbase + arow) * PA + acol) * 2);
        a_addr[1] = as_base + (uint32_t)(((mbase + 16 + arow) * PA + acol) * 2);
        int krow = ((lane >> 3) & 1) * 8 + (lane & 7);
        int coff = (lane >> 4) << 3;
        #pragma unroll
        for (int nh = 0; nh < 3; nh++)
            b_addr[nh] = bs_base + (uint32_t)((krow * PB + nbase + nh * 16 + coff) * 2);
    }

    #pragma unroll
    for (int l = 0; l < 4; l++) {
        int idx = tid + l * 256;
        int row = idx >> 3, c8 = idx & 7;
        cp16(as_base + (uint32_t)((row * PA + c8 * 8) * 2),
             A + (size_t)(m0 + row) * HIDP + c8 * 8);
    }
    CP_COMMIT();

    float acc[2][6][4];
    #pragma unroll
    for (int a = 0; a < 2; a++)
        #pragma unroll
        for (int b = 0; b < 6; b++)
            #pragma unroll
            for (int c = 0; c < 4; c++) acc[a][b][c] = 0.f;

    int bufc = 0;
    #pragma unroll
    for (int kit = 0; kit < 4; kit++) {
        if (kit < 3) {
            int k0n = (kit + 1) * 64;
            uint32_t dstb = as_base + (uint32_t)((bufc ^ 1) * ABUF);
            #pragma unroll
            for (int l = 0; l < 4; l++) {
                int idx = tid + l * 256;
                int row = idx >> 3, c8 = idx & 7;
                cp16(dstb + (uint32_t)((row * PA + c8 * 8) * 2),
                     A + (size_t)(m0 + row) * HIDP + k0n + c8 * 8);
            }
            CP_COMMIT();
            cp_wait1();
        } else {
            cp_wait0();
        }
        __syncthreads();
        uint32_t abuf = (uint32_t)(bufc * ABUF);
        #pragma unroll
        for (int ks = 0; ks < 4; ks++) {
            uint32_t af[2][4];
            ldsm_x4(af[0], a_addr[0] + abuf + ks * 32);
            ldsm_x4(af[1], a_addr[1] + abuf + ks * 32);
            int kglob = kit * 64 + ks * 16;
            #pragma unroll
            for (int nh = 0; nh < 3; nh++) {
                uint32_t bq[4];
                ldsm_x4_t(bq, b_addr[nh] + kglob * (PB * 2));
                mma_bf16(acc[0][nh * 2 + 0], af[0], &bq[0]);
                mma_bf16(acc[0][nh * 2 + 1], af[0], &bq[2]);
                mma_bf16(acc[1][nh * 2 + 0], af[1], &bq[0]);
                mma_bf16(acc[1][nh * 2 + 1], af[1], &bq[2]);
            }
        }
        __syncthreads();
        bufc ^= 1;
    }

    #pragma unroll
    for (int mt = 0; mt < 2; mt++) {
        #pragma unroll
        for (int nt = 0; nt < 6; nt++) {
            int col = nbase + nt * 8 + tg * 2;
            #pragma unroll
            for (int h = 0; h < 2; h++) {
                int row = m0 + mbase + mt * 16 + g + h * 8;
                size_t o = (size_t)row * CDIM + col;
                float2 r2 = *(const float2*)(R + o);
                *(float2*)(C + o) = make_float2(acc[mt][nt][h * 2 + 0] + r2.x,
                                                acc[mt][nt][h * 2 + 1] + r2.y);
            }
        }
    }
}

// ---------------- attn_out GEMM (N=96, K=96) with fused residual + LayerNorm2 ----------------
__global__ void __launch_bounds__(256)
gemm_attnout_ln(const bf16* __restrict__ A, const bf16* __restrict__ Bw,
                const float* __restrict__ R, float* __restrict__ x2out,
                bf16* __restrict__ yout,
                const float* __restrict__ gamma, const float* __restrict__ beta) {
    constexpr int PA = 104, PB = 104;
    __shared__ __align__(16) char buf[49152];
    bf16* As = (bf16*)buf;
    bf16* Bs = (bf16*)buf + 128 * PA;

    int tid = threadIdx.x, lane = tid & 31, warp = tid >> 5;
    int m0 = blockIdx.x * 128;
    int g = lane >> 2, tg = lane & 3;
    int warpM = warp & 3, warpN = warp >> 2;
    int mbase = warpM * 32, nbase = warpN * 48;

    #pragma unroll
    for (int l = 0; l < 6; l++) {
        int idx = tid + l * 256;
        int row = idx / 12, c8 = idx % 12;
        *(uint4*)&As[row * PA + c8 * 8] = *(const uint4*)(A + (size_t)(m0 + row) * 96 + c8 * 8);
    }
    #pragma unroll
    for (int l = 0; l < 18; l++) {
        int idx = tid + l * 256;
        int row = idx / 48, nu = idx % 48;
        *(uint32_t*)&Bs[row * PB + nu * 2] = *(const uint32_t*)(Bw + (size_t)row * 96 + nu * 2);
    }
    __syncthreads();

    uint32_t a_addr[2], b_addr[3];
    {
        int arow = lane & 15, acol = (lane >> 4) << 3;
        #pragma unroll
        for (int mt = 0; mt < 2; mt++)
            a_addr[mt] = (uint32_t)__cvta_generic_to_shared(&As[(mbase + mt * 16 + arow) * PA + acol]);
        int krow = ((lane >> 3) & 1) * 8 + (lane & 7);
        int coff = (lane >> 4) << 3;
        #pragma unroll
        for (int nh = 0; nh < 3; nh++)
            b_addr[nh] = (uint32_t)__cvta_generic_to_shared(&Bs[krow * PB + nbase + nh * 16 + coff]);
    }

    float acc[2][6][4];
    #pragma unroll
    for (int mt = 0; mt < 2; mt++)
        #pragma unroll
        for (int nt = 0; nt < 6; nt++)
            #pragma unroll
            for (int i = 0; i < 4; i++) acc[mt][nt][i] = 0.f;

    #pragma unroll
    for (int ks = 0; ks < 6; ks++) {
        uint32_t af[2][4];
        ldsm_x4(af[0], a_addr[0] + ks * 32);
        ldsm_x4(af[1], a_addr[1] + ks * 32);
        #pragma unroll
        for (int nh = 0; nh < 3; nh++) {
            uint32_t bq[4];
            ldsm_x4_t(bq, b_addr[nh] + ks * 16 * (PB * 2));
            #pragma unroll
            for (int mt = 0; mt < 2; mt++) {
                mma_bf16(acc[mt][nh * 2 + 0], af[mt], &bq[0]);
                mma_bf16(acc[mt][nh * 2 + 1], af[mt], &bq[2]);
            }
        }
    }
    __syncthreads();

    float* sx = (float*)buf;
    #pragma unroll
    for (int mt = 0; mt < 2; mt++) {
        #pragma unroll
        for (int nt = 0; nt < 6; nt++) {
            int col = nbase + nt * 8 + tg * 2;
            #pragma unroll
            for (int h = 0; h < 2; h++) {
                int rl = mbase + mt * 16 + g + h * 8;
                size_t o = (size_t)(m0 + rl) * 96 + col;
                float2 r2 = *(const float2*)(R + o);
                float v0 = acc[mt][nt][h * 2 + 0] + r2.x;
                float v1 = acc[mt][nt][h * 2 + 1] + r2.y;
                *(float2*)(x2out + o) = make_float2(v0, v1);
                int t = (rl & 3) << 3;
                *(float2*)(sx + rl * 96 + (col ^ t)) = make_float2(v0, v1);
            }
        }
    }
    __syncthreads();

    float ga0 = gamma[lane], ga1 = gamma[lane + 32], ga2 = gamma[lane + 64];
    float be0 = beta[lane],  be1 = beta[lane + 32],  be2 = beta[lane + 64];
    #pragma unroll
    for (int i = 0; i < 16; i++) {
        int wr = warp * 16 + i;
        int t = (wr & 3) << 3;
        int c0 = lane ^ t;
        float v0 = sx[wr * 96 + c0];
        float v1 = sx[wr * 96 + c0 + 32];
        float v2 = sx[wr * 96 + c0 + 64];
        float s  = v0 + v1 + v2;
        float ss = v0 * v0 + v1 * v1 + v2 * v2;
        #pragma unroll
        for (int o = 16; o > 0; o >>= 1) {
            s  += __shfl_xor_sync(0xffffffffu, s,  o);
            ss += __shfl_xor_sync(0xffffffffu, ss, o);
        }
        float mu = s * (1.f / 96.f);
        float var = ss * (1.f / 96.f) - mu * mu;
        float rstd = rsqrtf(var + 1e-5f);
        bf16* yp = yout + (size_t)(m0 + wr) * 96;
        yp[lane]      = __float2bfloat16_rn((v0 - mu) * rstd * ga0 + be0);
        yp[lane + 32] = __float2bfloat16_rn((v1 - mu) * rstd * ga1 + be1);
        yp[lane + 64] = __float2bfloat16_rn((v2 - mu) * rstd * ga2 + be2);
    }
}

// ---------------- depthwise 3x3, C=288 bf16, 4-ch chunks, 4-wide x strip ----------------
__global__ void dwconv288_kernel(const bf16* __restrict__ in, const float* __restrict__ kern,
                                 bf16* __restrict__ out) {
    const int C4 = QKV / 4;
    int idx = blockIdx.x * blockDim.x + threadIdx.x;
    if (idx >= (NPIX / 4) * C4) return;
    int c4 = idx % C4;
    int strip = idx / C4;
    int xs = (strip & 63) * 4;
    int y  = (strip >> 6) & 255;
    int b  = strip >> 14;

    float acc[4][4];
    #pragma unroll
    for (int ox = 0; ox < 4; ox++)
        #pragma unroll
        for (int e = 0; e < 4; e++) acc[ox][e] = 0.f;

    #pragma unroll
    for (int dy = -1; dy <= 1; dy++) {
        int yy = y + dy;
        if (yy < 0 || yy > 255) continue;
        const bf16* rowp = in + ((size_t)((b << 8) + yy) << 8) * QKV;
        float v[6][4];
        #pragma unroll
        for (int j = 0; j < 6; j++) {
            int xx = xs - 1 + j;
            if (xx >= 0 && xx <= 255) {
                uint2 u = *(const uint2*)(rowp + (size_t)xx * QKV + c4 * 4);
                float2 f0 = __bfloat1622float2(((const __nv_bfloat162*)&u)[0]);
                float2 f1 = __bfloat1622float2(((const __nv_bfloat162*)&u)[1]);
                v[j][0] = f0.x; v[j][1] = f0.y; v[j][2] = f1.x; v[j][3] = f1.y;
            } else {
                #pragma unroll
                for (int e = 0; e < 4; e++) v[j][e] = 0.f;
            }
        }
        #pragma unroll
        for (int dx = 0; dx < 3; dx++) {
            float4 kv = *(const float4*)(kern + (size_t)((dy + 1) * 3 + dx) * QKV + c4 * 4);
            float kk[4] = {kv.x, kv.y, kv.z, kv.w};
            #pragma unroll
            for (int ox = 0; ox < 4; ox++)
                #pragma unroll
                for (int e = 0; e < 4; e++) acc[ox][e] += v[ox + dx][e] * kk[e];
        }
    }
    bf16* op = out + ((size_t)((b << 16) + (y << 8) + xs)) * QKV + c4 * 4;
    #pragma unroll
    for (int ox = 0; ox < 4; ox++) {
        uint2 u;
        ((uint32_t*)&u)[0] = pack_bf2(acc[ox][0], acc[ox][1]);
        ((uint32_t*)&u)[1] = pack_bf2(acc[ox][2], acc[ox][3]);
        *(uint2*)(op + (size_t)ox * QKV) = u;
    }
}

// ---------------- q*k^T accumulation + fused q/k sum-of-squares ----------------
__global__ void qkt_kernel(const bf16* __restrict__ t1, float* __restrict__ attn,
                           float* __restrict__ nrm) {
    __shared__ float qs[16][48];
    __shared__ float ks[16][48];
    __shared__ float nq[48], nk[48];
    int bh = blockIdx.y;
    int b = bh >> 1, hd = bh & 1;
    int s0 = blockIdx.x * 2048;
    int tid = threadIdx.x;
    if (tid < 48) { nq[tid] = 0.f; nk[tid] = 0.f; }
    int tx = tid & 15, ty = tid >> 4;
    float acc[3][3];
    #pragma unroll
    for (int r = 0; r < 3; r++)
        #pragma unroll
        for (int c = 0; c < 3; c++) acc[r][c] = 0.f;
    float sqq[3] = {0.f, 0.f, 0.f}, sqk[3] = {0.f, 0.f, 0.f};

    const bf16* qbase = t1 + ((size_t)(b << 16)) * QKV + hd * CH;
    const bf16* kbase = qbase + CDIM;
    for (int st = 0; st < 2048; st += 16) {
        #pragma unroll
        for (int l = 0; l < 3; l++) {
            int idx = tid + l * 256;
            int si = idx / 48, e = idx % 48;
            size_t off = (size_t)(s0 + st + si) * QKV + e;
            float qv = __bfloat162float(qbase[off]);
            float kv = __bfloat162float(kbase[off]);
            qs[si][e] = qv; ks[si][e] = kv;
            sqq[l] += qv * qv; sqk[l] += kv * kv;
        }
        __syncthreads();
        #pragma unroll
        for (int si = 0; si < 16; si++) {
            float qv[3], kv[3];
            #pragma unroll
            for (int r = 0; r < 3; r++) qv[r] = qs[si][ty * 3 + r];
            #pragma unroll
            for (int c = 0; c < 3; c++) kv[c] = ks[si][tx * 3 + c];
            #pragma unroll
            for (int r = 0; r < 3; r++)
                #pragma unroll
                for (int c = 0; c < 3; c++) acc[r][c] += qv[r] * kv[c];
        }
        __syncthreads();
    }
    #pragma unroll
    for (int l = 0; l < 3; l++) {
        int e = (tid + l * 256) % 48;
        atomicAdd(&nq[e], sqq[l]);
        atomicAdd(&nk[e], sqk[l]);
    }
    float* ab = attn + (size_t)bh * CH * CH;
    #pragma unroll
    for (int r = 0; r < 3; r++)
        #pragma unroll
        for (int c = 0; c < 3; c++)
            atomicAdd(&ab[(ty * 3 + r) * CH + (tx * 3 + c)], acc[r][c]);
    __syncthreads();
    if (tid < 48) {
        atomicAdd(&nrm[b * 192 + hd * CH + tid], nq[tid]);
        atomicAdd(&nrm[b * 192 + CDIM + hd * CH + tid], nk[tid]);
    }
}

// ---------------- normalize + temperature + softmax ----------------
__global__ void softmax_kernel(float* __restrict__ attn, const float* __restrict__ nrm,
                               const float* __restrict__ temp) {
    int bh = blockIdx.x;
    int b = bh >> 1, hd = bh & 1;
    int d = threadIdx.x;
    if (d >= CH) return;
    float t = temp[hd];
    float rq = rsqrtf(nrm[b * 192 + hd * CH + d]);
    float* row = attn + (size_t)bh * CH * CH + d * CH;
    float vals[CH];
    float mx = -1e30f;
    #pragma unroll
    for (int e = 0; e < CH; e++) {
        float rk = rsqrtf(nrm[b * 192 + CDIM + hd * CH + e]);
        float v = row[e] * rq * rk * t;
        vals[e] = v;
        mx = fmaxf(mx, v);
    }
    float s = 0.f;
    #pragma unroll
    for (int e = 0; e < CH; e++) { vals[e] = expf(vals[e] - mx); s += vals[e]; }
    float inv = 1.f / s;
    #pragma unroll
    for (int e = 0; e < CH; e++) row[e] = vals[e] * inv;
}

// ---------------- o = attn @ v (transposed attn in smem, conflict-free) ----------------
__global__ void attnapply_kernel(const bf16* __restrict__ t1, const float* __restrict__ attn,
                                 bf16* __restrict__ o) {
    __shared__ float at_t[CH][2 * CH + 4];
    __shared__ float vs[32][CDIM];
    int b = blockIdx.y;
    int p0 = blockIdx.x * 32;
    int tid = threadIdx.x;
    for (int i = tid; i < HEADS * CH * CH; i += 256) {
        int hd = i / (CH * CH);
        int rem = i - hd * CH * CH;
        int cm = rem / CH, e = rem % CH;
        at_t[e][hd * CH + cm] = attn[(size_t)b * HEADS * CH * CH + i];
    }
    const bf16* vbase = t1 + ((size_t)((b << 16) + p0)) * QKV + 2 * CDIM;
    #pragma unroll
    for (int l = 0; l < 6; l++) {
        int idx = tid + l * 256;
        int p = idx / 48, cu = idx % 48;
        uint32_t u = *(const uint32_t*)(vbase + (size_t)p * QKV + cu * 2);
        float2 f = __bfloat1622float2(*(__nv_bfloat162*)&u);
        vs[p][cu * 2] = f.x; vs[p][cu * 2 + 1] = f.y;
    }
    __syncthreads();
    bf16* obase = o + ((size_t)((b << 16) + p0)) * CDIM;
    #pragma unroll
    for (int l = 0; l < 12; l++) {
        int idx = tid + l * 256;
        int p = idx / CDIM, c = idx % CDIM;
        int hd = c / CH;
        const float* vrow = &vs[p][hd * CH];
        float s = 0.f;
        #pragma unroll
        for (int e = 0; e < CH; e++) s += at_t[e][c] * vrow[e];
        obase[(size_t)p * CDIM + c] = __float2bfloat16_rn(s);
    }
}

// ---------------- depthwise 3x3 + GELU gate: 512-col layout, 2ch x 4px ----------------
__global__ void dwgate_kernel(const bf16* __restrict__ in, const float* __restrict__ kwp,
                              bf16* __restrict__ out) {
    int idx = blockIdx.x * blockDim.x + threadIdx.x;
    int c2 = idx & 127;
    int strip = idx >> 7;
    int xs = (strip & 63) * 4;
    int y  = (strip >> 6) & 255;
    int b  = strip >> 14;

    float accA[4][2], accB[4][2];
    #pragma unroll
    for (int ox = 0; ox < 4; ox++) {
        accA[ox][0] = 0.f; accA[ox][1] = 0.f;
        accB[ox][0] = 0.f; accB[ox][1] = 0.f;
    }

    #pragma unroll
    for (int dy = -1; dy <= 1; dy++) {
        int yy = y + dy;
        if (yy < 0 || yy > 255) continue;
        const bf16* rowp = in + (((size_t)((b << 8) + yy) << 8) << 9);
        float va[6][2], vb[6][2];
        #pragma unroll
        for (int j = 0; j < 6; j++) {
            int xx = xs - 1 + j;
            if (xx >= 0 && xx <= 255) {
                const bf16* pp = rowp + ((size_t)xx << 9) + c2 * 2;
                uint32_t u1 = *(const uint32_t*)pp;
                uint32_t u2 = *(const uint32_t*)(pp + 256);
                float2 f1 = __bfloat1622float2(*(__nv_bfloat162*)&u1);
                float2 f2 = __bfloat1622float2(*(__nv_bfloat162*)&u2);
                va[j][0] = f1.x; va[j][1] = f1.y;
                vb[j][0] = f2.x; vb[j][1] = f2.y;
            } else {
                va[j][0] = 0.f; va[j][1] = 0.f;
                vb[j][0] = 0.f; vb[j][1] = 0.f;
            }
        }
        #pragma unroll
        for (int dx = 0; dx < 3; dx++) {
            int ki = (dy + 1) * 3 + dx;
            float2 k1 = *(const float2*)(kwp + ki * H2P + c2 * 2);
            float2 k2 = *(const float2*)(kwp + ki * H2P + 256 + c2 * 2);
            #pragma unroll
            for (int ox = 0; ox < 4; ox++) {
                accA[ox][0] += va[ox + dx][0] * k1.x;
                accA[ox][1] += va[ox + dx][1] * k1.y;
                accB[ox][0] += vb[ox + dx][0] * k2.x;
                accB[ox][1] += vb[ox + dx][1] * k2.y;
            }
        }
    }
    size_t pbase = (size_t)((b << 16) + (y << 8) + xs);
    #pragma unroll
    for (int ox = 0; ox < 4; ox++) {
        float g0 = gelu_exact(accA[ox][0]) * accB[ox][0];
        float g1 = gelu_exact(accA[ox][1]) * accB[ox][1];
        *(uint32_t*)(out + (pbase + ox) * HIDP + c2 * 2) = pack_bf2(g0, g1);
    }
}

// ---------------- launcher ----------------
extern "C" void kernel_launch(void* const* d_in, const int* in_sizes, int n_in,
                              void* d_out, int out_size) {
    const float* x     = (const float*)d_in[0];
    const float* ln1g  = (const float*)d_in[1];
    const float* ln1b  = (const float*)d_in[2];
    const float* ln2g  = (const float*)d_in[3];
    const float* ln2b  = (const float*)d_in[4];
    const float* qkvw  = (const float*)d_in[5];
    const float* qkvdw = (const float*)d_in[6];
    const float* temp  = (const float*)d_in[7];
    const float* aow   = (const float*)d_in[8];
    const float* fiw   = (const float*)d_in[9];
    const float* fdw   = (const float*)d_in[10];
    const float* fow   = (const float*)d_in[11];
    float* out = (float*)d_out;

    bf16 *t0, *t1, *t2, *gt, *ybf, *wq, *wa, *wip, *wo2;
    float *x2, *nrm, *att, *kwp;
    cudaGetSymbolAddress((void**)&t0,  g_t0);
    cudaGetSymbolAddress((void**)&t1,  g_t1);
    cudaGetSymbolAddress((void**)&t2,  g_t2);
    cudaGetSymbolAddress((void**)&gt,  g_gt);
    cudaGetSymbolAddress((void**)&ybf, g_ybf);
    cudaGetSymbolAddress((void**)&x2,  g_x2);
    cudaGetSymbolAddress((void**)&nrm, g_nrm);
    cudaGetSymbolAddress((void**)&att, g_att);
    cudaGetSymbolAddress((void**)&wq,  g_wq);
    cudaGetSymbolAddress((void**)&wa,  g_wa);
    cudaGetSymbolAddress((void**)&wip, g_wip);
    cudaGetSymbolAddress((void**)&wo2, g_wo2);
    cudaGetSymbolAddress((void**)&kwp, g_kwp);

    const int SMEM_FO = 2 * 128 * 72 * 2 + 256 * 104 * 2;            // 90112
    const int SMEM_QKV = 128 * 104 * 2 + 96 * (288 + 8) * 2;         // 83456
    const int SMEM_FFI = 128 * 104 * 2 + 96 * (256 + 8) * 2;         // 77312
    cudaFuncSetAttribute(gemm_ffnout, cudaFuncAttributeMaxDynamicSharedMemorySize, SMEM_FO);
    cudaFuncSetAttribute((gemm_bres<3, 6, true>),  cudaFuncAttributeMaxDynamicSharedMemorySize, SMEM_QKV);
    cudaFuncSetAttribute((gemm_bres<2, 8, false>), cudaFuncAttributeMaxDynamicSharedMemorySize, SMEM_FFI);

    const int cvt_total = CDIM * QKV + CDIM * CDIM + CDIM * H2P + HID * CDIM;
    cvt_all_kernel<<<(cvt_total + 255) / 256, 256>>>(qkvw, aow, fiw, fow, fdw,
                                                     wq, wa, wip, wo2, kwp, nrm, att);

    // attention branch: fused LN1 + qkv GEMM (B resident)
    gemm_bres<3, 6, true><<<dim3(1, 1024), 256, SMEM_QKV>>>(
        nullptr, x, ln1g, ln1b, wq, t0, QKV);
    dwconv288_kernel<<<(NPIX / 4) * 72 / 256, 256>>>(t0, qkvdw, t1);
    qkt_kernel<<<dim3(32, 4), 256>>>(t1, att, nrm);
    softmax_kernel<<<4, 64>>>(att, nrm, temp);
    attnapply_kernel<<<dim3(2048, 2), 256>>>(t1, att, ybf);
    // fused: x2 = ybf@wa + x ; ybf = LN2(x2)
    gemm_attnout_ln<<<1024, 256>>>(ybf, wa, x, x2, ybf, ln2g, ln2b);

    // FFN branch: B-resident ffn_in (2 column blocks of 256), remapped 512-col layout
    gemm_bres<2, 8, false><<<dim3(2, 1024), 256, SMEM_FFI>>>(
        ybf, nullptr, nullptr, nullptr, wip, t2, H2P);
    dwgate_kernel<<<(NPIX / 4) * 128 / 256, 256>>>(t2, kwp, gt);
    gemm_ffnout<<<1024, 256, SMEM_FO>>>(gt, wo2, x2, out);
}

// round 12
// speedup vs baseline: 1.8855x; 1.2072x over previous
#include <cuda_runtime.h>
#include <cuda_bf16.h>
#include <math.h>
#include <stdint.h>

// ---------------- problem constants ----------------
#define BATCH 2
#define CDIM 96
#define HEADS 2
#define CH 48
#define QKV 288
#define HID 255
#define HIDP 256
#define H2 510
#define H2P 512
#define NPIX 131072

typedef __nv_bfloat16 bf16;

// ---------------- device scratch ----------------
__device__ __align__(256) bf16 g_t0[(size_t)NPIX * QKV];
__device__ __align__(256) bf16 g_t1[(size_t)NPIX * QKV];
__device__ __align__(256) bf16 g_t2[(size_t)NPIX * H2P];
__device__ __align__(256) bf16 g_gt[(size_t)NPIX * HIDP];
__device__ __align__(256) bf16 g_ybf[(size_t)NPIX * CDIM];
__device__ __align__(256) float g_x2[(size_t)NPIX * CDIM];
__device__ float g_nrm[2 * BATCH * CDIM];
__device__ float g_att[BATCH * HEADS * CH * CH];
__device__ __align__(256) bf16 g_wq[CDIM * QKV];
__device__ __align__(256) bf16 g_wa[CDIM * CDIM];
__device__ __align__(256) bf16 g_wip[CDIM * H2P];
__device__ __align__(256) bf16 g_wo2[HIDP * CDIM];
__device__ __align__(256) float g_kwp[9 * H2P];

// ---------------- helpers ----------------
__device__ __forceinline__ float gelu_exact(float v) {
    return 0.5f * v * (1.0f + erff(v * 0.70710678118654752f));
}
__device__ __forceinline__ void ldsm_x4(uint32_t* r, uint32_t addr) {
    asm volatile("ldmatrix.sync.aligned.m8n8.x4.shared.b16 {%0,%1,%2,%3}, [%4];"
        : "=r"(r[0]), "=r"(r[1]), "=r"(r[2]), "=r"(r[3]) : "r"(addr));
}
__device__ __forceinline__ void ldsm_x4_t(uint32_t* r, uint32_t addr) {
    asm volatile("ldmatrix.sync.aligned.m8n8.x4.trans.shared.b16 {%0,%1,%2,%3}, [%4];"
        : "=r"(r[0]), "=r"(r[1]), "=r"(r[2]), "=r"(r[3]) : "r"(addr));
}
__device__ __forceinline__ void mma_bf16(float* c, const uint32_t* a, const uint32_t* b) {
    asm volatile("mma.sync.aligned.m16n8k16.row.col.f32.bf16.bf16.f32 "
        "{%0,%1,%2,%3}, {%4,%5,%6,%7}, {%8,%9}, {%0,%1,%2,%3};\n"
        : "+f"(c[0]), "+f"(c[1]), "+f"(c[2]), "+f"(c[3])
        : "r"(a[0]), "r"(a[1]), "r"(a[2]), "r"(a[3]), "r"(b[0]), "r"(b[1]));
}
__device__ __forceinline__ uint32_t pack_bf2(float a, float b) {
    __nv_bfloat162 h = __floats2bfloat162_rn(a, b);
    return *(uint32_t*)&h;
}
__device__ __forceinline__ void cp16(uint32_t dst, const void* src) {
    asm volatile("cp.async.ca.shared.global [%0], [%1], 16;" :: "r"(dst), "l"(src));
}
#define CP_COMMIT() asm volatile("cp.async.commit_group;")
__device__ __forceinline__ void cp_wait0() { asm volatile("cp.async.wait_group 0;"); }
__device__ __forceinline__ void cp_wait1() { asm volatile("cp.async.wait_group 1;"); }

// ---------------- weight convert / remap + accumulator init ----------------
__global__ void cvt_all_kernel(const float* wq, const float* wa, const float* wi, const float* wo,
                               const float* fdw,
                               bf16* dq, bf16* da, bf16* dip, bf16* dxo2,
                               float* kwp, float* nrm, float* attn) {
    int i = blockIdx.x * blockDim.x + threadIdx.x;
    const int s0 = CDIM * QKV, s1 = s0 + CDIM * CDIM;
    if (i < s0) dq[i] = __float2bfloat16_rn(wq[i]);
    else if (i < s1) da[i - s0] = __float2bfloat16_rn(wa[i - s0]);
    if (i < CDIM * H2P) {
        int r = i >> 9, c = i & 511;
        float v = 0.f;
        if (c < 255) v = wi[r * H2 + c];
        else if (c >= 256 && c <= 510) v = wi[r * H2 + c - 1];
        dip[i] = __float2bfloat16_rn(v);
    }
    if (i < HIDP * CDIM) {
        int r = i / CDIM;
        dxo2[i] = (r < HID) ? __float2bfloat16_rn(wo[i]) : __float2bfloat16_rn(0.f);
    }
    if (i < 9 * H2P) {
        int d = i >> 9, c = i & 511;
        float v = 0.f;
        if (c < 255) v = fdw[d * H2 + c];
        else if (c >= 256 && c <= 510) v = fdw[d * H2 + c - 1];
        kwp[i] = v;
    }
    if (i < 2 * BATCH * CDIM) nrm[i] = 0.f;
    if (i < BATCH * HEADS * CH * CH) attn[i] = 0.f;
}

// ---------------- generic B-resident GEMM, K=96, multi-pass N, optional fused LN on A ----------------
template<int NPASS, int NT, bool FUSE_LN>
__global__ void __launch_bounds__(256)
gemm_bres(const bf16* __restrict__ Abf, const float* __restrict__ Xf,
          const float* __restrict__ gamma, const float* __restrict__ beta,
          const bf16* __restrict__ Bw, bf16* __restrict__ Cout, int Nglob) {
    constexpr int PASSW = NT * 16;
    constexpr int BCOLS = NPASS * PASSW;
    constexpr int PA = 104;
    constexpr int PB = BCOLS + 8;
    extern __shared__ char smraw[];
    bf16* As = (bf16*)smraw;
    bf16* Bs = (bf16*)smraw + 128 * PA;
    uint32_t as_base = (uint32_t)__cvta_generic_to_shared(smraw);
    uint32_t bs_base = as_base + 128 * PA * 2;

    int tid = threadIdx.x, lane = tid & 31, warp = tid >> 5;
    int m0 = blockIdx.y * 128;
    int ncol0 = blockIdx.x * BCOLS;
    int g = lane >> 2, tg = lane & 3;
    int warpM = warp & 3, warpN = warp >> 2;
    int mbase = warpM * 32, nbase = warpN * (NT * 8);

    constexpr int BU = 96 * (BCOLS / 2);
    #pragma unroll
    for (int l = 0; l < BU / 256; l++) {
        int idx = tid + l * 256;
        int row = idx / (BCOLS / 2), nu = idx % (BCOLS / 2);
        *(uint32_t*)&Bs[row * PB + nu * 2] =
            *(const uint32_t*)(Bw + (size_t)row * Nglob + ncol0 + nu * 2);
    }

    if (FUSE_LN) {
        float ga0 = gamma[lane], ga1 = gamma[lane + 32], ga2 = gamma[lane + 64];
        float be0 = beta[lane],  be1 = beta[lane + 32],  be2 = beta[lane + 64];
        #pragma unroll
        for (int i = 0; i < 16; i++) {
            int row = warp * 16 + i;
            const float* xp = Xf + (size_t)(m0 + row) * CDIM;
            float v0 = xp[lane], v1 = xp[lane + 32], v2 = xp[lane + 64];
            float s  = v0 + v1 + v2;
            float ss = v0 * v0 + v1 * v1 + v2 * v2;
            #pragma unroll
            for (int o = 16; o > 0; o >>= 1) {
                s  += __shfl_xor_sync(0xffffffffu, s,  o);
                ss += __shfl_xor_sync(0xffffffffu, ss, o);
            }
            float mu = s * (1.f / 96.f);
            float var = ss * (1.f / 96.f) - mu * mu;
            float rstd = rsqrtf(var + 1e-5f);
            As[row * PA + lane]      = __float2bfloat16_rn((v0 - mu) * rstd * ga0 + be0);
            As[row * PA + lane + 32] = __float2bfloat16_rn((v1 - mu) * rstd * ga1 + be1);
            As[row * PA + lane + 64] = __float2bfloat16_rn((v2 - mu) * rstd * ga2 + be2);
        }
    } else {
        #pragma unroll
        for (int l = 0; l < 6; l++) {
            int idx = tid + l * 256;
            int row = idx / 12, c8 = idx % 12;
            *(uint4*)&As[row * PA + c8 * 8] =
                *(const uint4*)(Abf + (size_t)(m0 + row) * CDIM + c8 * 8);
        }
    }
    __syncthreads();

    uint32_t a_addr[2], b_addr0[NT / 2];
    {
        int arow = lane & 15, acol = (lane >> 4) << 3;
        a_addr[0] = as_base + (uint32_t)(((mbase + arow) * PA + acol) * 2);
        a_addr[1] = as_base + (uint32_t)(((mbase + 16 + arow) * PA + acol) * 2);
        int krow = ((lane >> 3) & 1) * 8 + (lane & 7);
        int coff = (lane >> 4) << 3;
        #pragma unroll
        for (int nh = 0; nh < NT / 2; nh++)
            b_addr0[nh] = bs_base + (uint32_t)((krow * PB + nbase + nh * 16 + coff) * 2);
    }

    #pragma unroll
    for (int pass = 0; pass < NPASS; pass++) {
        float acc[2][NT][4];
        #pragma unroll
        for (int mt = 0; mt < 2; mt++)
            #pragma unroll
            for (int nt = 0; nt < NT; nt++)
                #pragma unroll
                for (int i = 0; i < 4; i++) acc[mt][nt][i] = 0.f;

        uint32_t poff = (uint32_t)(pass * PASSW * 2);
        #pragma unroll
        for (int ks = 0; ks < 6; ks++) {
            uint32_t af[2][4];
            ldsm_x4(af[0], a_addr[0] + ks * 32);
            ldsm_x4(af[1], a_addr[1] + ks * 32);
            #pragma unroll
            for (int nh = 0; nh < NT / 2; nh++) {
                uint32_t bq[4];
                ldsm_x4_t(bq, b_addr0[nh] + poff + ks * 16 * (PB * 2));
                #pragma unroll
                for (int mt = 0; mt < 2; mt++) {
                    mma_bf16(acc[mt][nh * 2 + 0], af[mt], &bq[0]);
                    mma_bf16(acc[mt][nh * 2 + 1], af[mt], &bq[2]);
                }
            }
        }
        #pragma unroll
        for (int mt = 0; mt < 2; mt++) {
            #pragma unroll
            for (int nt = 0; nt < NT; nt++) {
                int col = ncol0 + pass * PASSW + nbase + nt * 8 + tg * 2;
                #pragma unroll
                for (int h = 0; h < 2; h++) {
                    int row = m0 + mbase + mt * 16 + g + h * 8;
                    size_t o = (size_t)row * Nglob + col;
                    *(uint32_t*)(Cout + o) = pack_bf2(acc[mt][nt][h * 2 + 0],
                                                      acc[mt][nt][h * 2 + 1]);
                }
            }
        }
    }
}

// ---------------- dedicated ffn_out GEMM: K=256 (padded), B resident, A pipelined ----------------
__global__ void __launch_bounds__(256)
gemm_ffnout(const bf16* __restrict__ A, const bf16* __restrict__ Bw,
            const float* __restrict__ R, float* __restrict__ C) {
    constexpr int PA = 72, PB = 104;
    constexpr int ABUF = 128 * PA * 2;
    extern __shared__ char smraw[];
    uint32_t as_base = (uint32_t)__cvta_generic_to_shared(smraw);
    uint32_t bs_base = as_base + 2 * ABUF;
    bf16* Bsm = (bf16*)(smraw + 2 * ABUF);

    int tid = threadIdx.x, lane = tid & 31, warp = tid >> 5;
    int m0 = blockIdx.x * 128;
    int g = lane >> 2, tg = lane & 3;
    int warpM = warp & 3, warpN = warp >> 2;
    int mbase = warpM * 32, nbase = warpN * 48;

    #pragma unroll
    for (int l = 0; l < 48; l++) {
        int idx = tid + l * 256;
        int row = idx / 48, nu = idx % 48;
        *(uint32_t*)&Bsm[row * PB + nu * 2] = *(const uint32_t*)(Bw + (size_t)row * CDIM + nu * 2);
    }

    uint32_t a_addr[2], b_addr[3];
    {
        int arow = lane & 15, acol = (lane >> 4) << 3;
        a_addr[0] = as_base + (uint32_t)(((mbase + arow) * PA + acol) * 2);
        a_addr[1] = as_base + (uint32_t)(((mbase + 16 + arow) * PA + acol) * 2);
        int krow = ((lane >> 3) & 1) * 8 + (lane & 7);
        int coff = (lane >> 4) << 3;
        #pragma unroll
        for (int nh = 0; nh < 3; nh++)
            b_addr[nh] = bs_base + (uint32_t)((krow * PB + nbase + nh * 16 + coff) * 2);
    }

    #pragma unroll
    for (int l = 0; l < 4; l++) {
        int idx = tid + l * 256;
        int row = idx >> 3, c8 = idx & 7;
        cp16(as_base + (uint32_t)((row * PA + c8 * 8) * 2),
             A + (size_t)(m0 + row) * HIDP + c8 * 8);
    }
    CP_COMMIT();

    float acc[2][6][4];
    #pragma unroll
    for (int a = 0; a < 2; a++)
        #pragma unroll
        for (int b = 0; b < 6; b++)
            #pragma unroll
            for (int c = 0; c < 4; c++) acc[a][b][c] = 0.f;

    int bufc = 0;
    #pragma unroll
    for (int kit = 0; kit < 4; kit++) {
        if (kit < 3) {
            int k0n = (kit + 1) * 64;
            uint32_t dstb = as_base + (uint32_t)((bufc ^ 1) * ABUF);
            #pragma unroll
            for (int l = 0; l < 4; l++) {
                int idx = tid + l * 256;
                int row = idx >> 3, c8 = idx & 7;
                cp16(dstb + (uint32_t)((row * PA + c8 * 8) * 2),
                     A + (size_t)(m0 + row) * HIDP + k0n + c8 * 8);
            }
            CP_COMMIT();
            cp_wait1();
        } else {
            cp_wait0();
        }
        __syncthreads();
        uint32_t abuf = (uint32_t)(bufc * ABUF);
        #pragma unroll
        for (int ks = 0; ks < 4; ks++) {
            uint32_t af[2][4];
            ldsm_x4(af[0], a_addr[0] + abuf + ks * 32);
            ldsm_x4(af[1], a_addr[1] + abuf + ks * 32);
            int kglob = kit * 64 + ks * 16;
            #pragma unroll
            for (int nh = 0; nh < 3; nh++) {
                uint32_t bq[4];
                ldsm_x4_t(bq, b_addr[nh] + kglob * (PB * 2));
                mma_bf16(acc[0][nh * 2 + 0], af[0], &bq[0]);
                mma_bf16(acc[0][nh * 2 + 1], af[0], &bq[2]);
                mma_bf16(acc[1][nh * 2 + 0], af[1], &bq[0]);
                mma_bf16(acc[1][nh * 2 + 1], af[1], &bq[2]);
            }
        }
        __syncthreads();
        bufc ^= 1;
    }

    #pragma unroll
    for (int mt = 0; mt < 2; mt++) {
        #pragma unroll
        for (int nt = 0; nt < 6; nt++) {
            int col = nbase + nt * 8 + tg * 2;
            #pragma unroll
            for (int h = 0; h < 2; h++) {
                int row = m0 + mbase + mt * 16 + g + h * 8;
                size_t o = (size_t)row * CDIM + col;
                float2 r2 = *(const float2*)(R + o);
                *(float2*)(C + o) = make_float2(acc[mt][nt][h * 2 + 0] + r2.x,
                                                acc[mt][nt][h * 2 + 1] + r2.y);
            }
        }
    }
}

// ---------------- attn_out GEMM (N=96, K=96) with fused residual + LayerNorm2 ----------------
__global__ void __launch_bounds__(256)
gemm_attnout_ln(const bf16* __restrict__ A, const bf16* __restrict__ Bw,
                const float* __restrict__ R, float* __restrict__ x2out,
                bf16* __restrict__ yout,
                const float* __restrict__ gamma, const float* __restrict__ beta) {
    constexpr int PA = 104, PB = 104;
    __shared__ __align__(16) char buf[49152];
    bf16* As = (bf16*)buf;
    bf16* Bs = (bf16*)buf + 128 * PA;

    int tid = threadIdx.x, lane = tid & 31, warp = tid >> 5;
    int m0 = blockIdx.x * 128;
    int g = lane >> 2, tg = lane & 3;
    int warpM = warp & 3, warpN = warp >> 2;
    int mbase = warpM * 32, nbase = warpN * 48;

    #pragma unroll
    for (int l = 0; l < 6; l++) {
        int idx = tid + l * 256;
        int row = idx / 12, c8 = idx % 12;
        *(uint4*)&As[row * PA + c8 * 8] = *(const uint4*)(A + (size_t)(m0 + row) * 96 + c8 * 8);
    }
    #pragma unroll
    for (int l = 0; l < 18; l++) {
        int idx = tid + l * 256;
        int row = idx / 48, nu = idx % 48;
        *(uint32_t*)&Bs[row * PB + nu * 2] = *(const uint32_t*)(Bw + (size_t)row * 96 + nu * 2);
    }
    __syncthreads();

    uint32_t a_addr[2], b_addr[3];
    {
        int arow = lane & 15, acol = (lane >> 4) << 3;
        #pragma unroll
        for (int mt = 0; mt < 2; mt++)
            a_addr[mt] = (uint32_t)__cvta_generic_to_shared(&As[(mbase + mt * 16 + arow) * PA + acol]);
        int krow = ((lane >> 3) & 1) * 8 + (lane & 7);
        int coff = (lane >> 4) << 3;
        #pragma unroll
        for (int nh = 0; nh < 3; nh++)
            b_addr[nh] = (uint32_t)__cvta_generic_to_shared(&Bs[krow * PB + nbase + nh * 16 + coff]);
    }

    float acc[2][6][4];
    #pragma unroll
    for (int mt = 0; mt < 2; mt++)
        #pragma unroll
        for (int nt = 0; nt < 6; nt++)
            #pragma unroll
            for (int i = 0; i < 4; i++) acc[mt][nt][i] = 0.f;

    #pragma unroll
    for (int ks = 0; ks < 6; ks++) {
        uint32_t af[2][4];
        ldsm_x4(af[0], a_addr[0] + ks * 32);
        ldsm_x4(af[1], a_addr[1] + ks * 32);
        #pragma unroll
        for (int nh = 0; nh < 3; nh++) {
            uint32_t bq[4];
            ldsm_x4_t(bq, b_addr[nh] + ks * 16 * (PB * 2));
            #pragma unroll
            for (int mt = 0; mt < 2; mt++) {
                mma_bf16(acc[mt][nh * 2 + 0], af[mt], &bq[0]);
                mma_bf16(acc[mt][nh * 2 + 1], af[mt], &bq[2]);
            }
        }
    }
    __syncthreads();

    float* sx = (float*)buf;
    #pragma unroll
    for (int mt = 0; mt < 2; mt++) {
        #pragma unroll
        for (int nt = 0; nt < 6; nt++) {
            int col = nbase + nt * 8 + tg * 2;
            #pragma unroll
            for (int h = 0; h < 2; h++) {
                int rl = mbase + mt * 16 + g + h * 8;
                size_t o = (size_t)(m0 + rl) * 96 + col;
                float2 r2 = *(const float2*)(R + o);
                float v0 = acc[mt][nt][h * 2 + 0] + r2.x;
                float v1 = acc[mt][nt][h * 2 + 1] + r2.y;
                *(float2*)(x2out + o) = make_float2(v0, v1);
                int t = (rl & 3) << 3;
                *(float2*)(sx + rl * 96 + (col ^ t)) = make_float2(v0, v1);
            }
        }
    }
    __syncthreads();

    float ga0 = gamma[lane], ga1 = gamma[lane + 32], ga2 = gamma[lane + 64];
    float be0 = beta[lane],  be1 = beta[lane + 32],  be2 = beta[lane + 64];
    #pragma unroll
    for (int i = 0; i < 16; i++) {
        int wr = warp * 16 + i;
        int t = (wr & 3) << 3;
        int c0 = lane ^ t;
        float v0 = sx[wr * 96 + c0];
        float v1 = sx[wr * 96 + c0 + 32];
        float v2 = sx[wr * 96 + c0 + 64];
        float s  = v0 + v1 + v2;
        float ss = v0 * v0 + v1 * v1 + v2 * v2;
        #pragma unroll
        for (int o = 16; o > 0; o >>= 1) {
            s  += __shfl_xor_sync(0xffffffffu, s,  o);
            ss += __shfl_xor_sync(0xffffffffu, ss, o);
        }
        float mu = s * (1.f / 96.f);
        float var = ss * (1.f / 96.f) - mu * mu;
        float rstd = rsqrtf(var + 1e-5f);
        bf16* yp = yout + (size_t)(m0 + wr) * 96;
        yp[lane]      = __float2bfloat16_rn((v0 - mu) * rstd * ga0 + be0);
        yp[lane + 32] = __float2bfloat16_rn((v1 - mu) * rstd * ga1 + be1);
        yp[lane + 64] = __float2bfloat16_rn((v2 - mu) * rstd * ga2 + be2);
    }
}

// ---------------- depthwise 3x3, C=288 bf16, 4-ch chunks, 4-wide x strip ----------------
__global__ void dwconv288_kernel(const bf16* __restrict__ in, const float* __restrict__ kern,
                                 bf16* __restrict__ out) {
    const int C4 = QKV / 4;
    int idx = blockIdx.x * blockDim.x + threadIdx.x;
    if (idx >= (NPIX / 4) * C4) return;
    int c4 = idx % C4;
    int strip = idx / C4;
    int xs = (strip & 63) * 4;
    int y  = (strip >> 6) & 255;
    int b  = strip >> 14;

    float acc[4][4];
    #pragma unroll
    for (int ox = 0; ox < 4; ox++)
        #pragma unroll
        for (int e = 0; e < 4; e++) acc[ox][e] = 0.f;

    #pragma unroll
    for (int dy = -1; dy <= 1; dy++) {
        int yy = y + dy;
        if (yy < 0 || yy > 255) continue;
        const bf16* rowp = in + ((size_t)((b << 8) + yy) << 8) * QKV;
        float v[6][4];
        #pragma unroll
        for (int j = 0; j < 6; j++) {
            int xx = xs - 1 + j;
            if (xx >= 0 && xx <= 255) {
                uint2 u = *(const uint2*)(rowp + (size_t)xx * QKV + c4 * 4);
                float2 f0 = __bfloat1622float2(((const __nv_bfloat162*)&u)[0]);
                float2 f1 = __bfloat1622float2(((const __nv_bfloat162*)&u)[1]);
                v[j][0] = f0.x; v[j][1] = f0.y; v[j][2] = f1.x; v[j][3] = f1.y;
            } else {
                #pragma unroll
                for (int e = 0; e < 4; e++) v[j][e] = 0.f;
            }
        }
        #pragma unroll
        for (int dx = 0; dx < 3; dx++) {
            float4 kv = *(const float4*)(kern + (size_t)((dy + 1) * 3 + dx) * QKV + c4 * 4);
            float kk[4] = {kv.x, kv.y, kv.z, kv.w};
            #pragma unroll
            for (int ox = 0; ox < 4; ox++)
                #pragma unroll
                for (int e = 0; e < 4; e++) acc[ox][e] += v[ox + dx][e] * kk[e];
        }
    }
    bf16* op = out + ((size_t)((b << 16) + (y << 8) + xs)) * QKV + c4 * 4;
    #pragma unroll
    for (int ox = 0; ox < 4; ox++) {
        uint2 u;
        ((uint32_t*)&u)[0] = pack_bf2(acc[ox][0], acc[ox][1]);
        ((uint32_t*)&u)[1] = pack_bf2(acc[ox][2], acc[ox][3]);
        *(uint2*)(op + (size_t)ox * QKV) = u;
    }
}

// ---------------- q*k^T accumulation + fused q/k sum-of-squares (512 blocks) ----------------
#define QKT_SPB 512   // pixels per block
__global__ void qkt_kernel(const bf16* __restrict__ t1, float* __restrict__ attn,
                           float* __restrict__ nrm) {
    __shared__ float qs[16][48];
    __shared__ float ks[16][48];
    __shared__ float nq[48], nk[48];
    int bh = blockIdx.y;
    int b = bh >> 1, hd = bh & 1;
    int s0 = blockIdx.x * QKT_SPB;
    int tid = threadIdx.x;
    if (tid < 48) { nq[tid] = 0.f; nk[tid] = 0.f; }
    int tx = tid & 15, ty = tid >> 4;
    float acc[3][3];
    #pragma unroll
    for (int r = 0; r < 3; r++)
        #pragma unroll
        for (int c = 0; c < 3; c++) acc[r][c] = 0.f;
    float sqq[3] = {0.f, 0.f, 0.f}, sqk[3] = {0.f, 0.f, 0.f};

    const bf16* qbase = t1 + ((size_t)(b << 16)) * QKV + hd * CH;
    const bf16* kbase = qbase + CDIM;
    for (int st = 0; st < QKT_SPB; st += 16) {
        #pragma unroll
        for (int l = 0; l < 3; l++) {
            int idx = tid + l * 256;
            int si = idx / 48, e = idx % 48;
            size_t off = (size_t)(s0 + st + si) * QKV + e;
            float qv = __bfloat162float(qbase[off]);
            float kv = __bfloat162float(kbase[off]);
            qs[si][e] = qv; ks[si][e] = kv;
            sqq[l] += qv * qv; sqk[l] += kv * kv;
        }
        __syncthreads();
        #pragma unroll
        for (int si = 0; si < 16; si++) {
            float qv[3], kv[3];
            #pragma unroll
            for (int r = 0; r < 3; r++) qv[r] = qs[si][ty * 3 + r];
            #pragma unroll
            for (int c = 0; c < 3; c++) kv[c] = ks[si][tx * 3 + c];
            #pragma unroll
            for (int r = 0; r < 3; r++)
                #pragma unroll
                for (int c = 0; c < 3; c++) acc[r][c] += qv[r] * kv[c];
        }
        __syncthreads();
    }
    #pragma unroll
    for (int l = 0; l < 3; l++) {
        int e = (tid + l * 256) % 48;
        atomicAdd(&nq[e], sqq[l]);
        atomicAdd(&nk[e], sqk[l]);
    }
    float* ab = attn + (size_t)bh * CH * CH;
    #pragma unroll
    for (int r = 0; r < 3; r++)
        #pragma unroll
        for (int c = 0; c < 3; c++)
            atomicAdd(&ab[(ty * 3 + r) * CH + (tx * 3 + c)], acc[r][c]);
    __syncthreads();
    if (tid < 48) {
        atomicAdd(&nrm[b * 192 + hd * CH + tid], nq[tid]);
        atomicAdd(&nrm[b * 192 + CDIM + hd * CH + tid], nk[tid]);
    }
}

// ---------------- normalize + temperature + softmax ----------------
__global__ void softmax_kernel(float* __restrict__ attn, const float* __restrict__ nrm,
                               const float* __restrict__ temp) {
    int bh = blockIdx.x;
    int b = bh >> 1, hd = bh & 1;
    int d = threadIdx.x;
    if (d >= CH) return;
    float t = temp[hd];
    float rq = rsqrtf(nrm[b * 192 + hd * CH + d]);
    float* row = attn + (size_t)bh * CH * CH + d * CH;
    float vals[CH];
    float mx = -1e30f;
    #pragma unroll
    for (int e = 0; e < CH; e++) {
        float rk = rsqrtf(nrm[b * 192 + CDIM + hd * CH + e]);
        float v = row[e] * rq * rk * t;
        vals[e] = v;
        mx = fmaxf(mx, v);
    }
    float s = 0.f;
    #pragma unroll
    for (int e = 0; e < CH; e++) { vals[e] = expf(vals[e] - mx); s += vals[e]; }
    float inv = 1.f / s;
    #pragma unroll
    for (int e = 0; e < CH; e++) row[e] = vals[e] * inv;
}

// ---------------- o = attn @ v (transposed attn in smem, conflict-free) ----------------
__global__ void attnapply_kernel(const bf16* __restrict__ t1, const float* __restrict__ attn,
                                 bf16* __restrict__ o) {
    __shared__ float at_t[CH][2 * CH + 4];
    __shared__ float vs[32][CDIM];
    int b = blockIdx.y;
    int p0 = blockIdx.x * 32;
    int tid = threadIdx.x;
    for (int i = tid; i < HEADS * CH * CH; i += 256) {
        int hd = i / (CH * CH);
        int rem = i - hd * CH * CH;
        int cm = rem / CH, e = rem % CH;
        at_t[e][hd * CH + cm] = attn[(size_t)b * HEADS * CH * CH + i];
    }
    const bf16* vbase = t1 + ((size_t)((b << 16) + p0)) * QKV + 2 * CDIM;
    #pragma unroll
    for (int l = 0; l < 6; l++) {
        int idx = tid + l * 256;
        int p = idx / 48, cu = idx % 48;
        uint32_t u = *(const uint32_t*)(vbase + (size_t)p * QKV + cu * 2);
        float2 f = __bfloat1622float2(*(__nv_bfloat162*)&u);
        vs[p][cu * 2] = f.x; vs[p][cu * 2 + 1] = f.y;
    }
    __syncthreads();
    bf16* obase = o + ((size_t)((b << 16) + p0)) * CDIM;
    #pragma unroll
    for (int l = 0; l < 12; l++) {
        int idx = tid + l * 256;
        int p = idx / CDIM, c = idx % CDIM;
        int hd = c / CH;
        const float* vrow = &vs[p][hd * CH];
        float s = 0.f;
        #pragma unroll
        for (int e = 0; e < CH; e++) s += at_t[e][c] * vrow[e];
        obase[(size_t)p * CDIM + c] = __float2bfloat16_rn(s);
    }
}

// ---------------- depthwise 3x3 + GELU gate: 512-col layout, 2ch x 4px ----------------
__global__ void dwgate_kernel(const bf16* __restrict__ in, const float* __restrict__ kwp,
                              bf16* __restrict__ out) {
    int idx = blockIdx.x * blockDim.x + threadIdx.x;
    int c2 = idx & 127;
    int strip = idx >> 7;
    int xs = (strip & 63) * 4;
    int y  = (strip >> 6) & 255;
    int b  = strip >> 14;

    float accA[4][2], accB[4][2];
    #pragma unroll
    for (int ox = 0; ox < 4; ox++) {
        accA[ox][0] = 0.f; accA[ox][1] = 0.f;
        accB[ox][0] = 0.f; accB[ox][1] = 0.f;
    }

    #pragma unroll
    for (int dy = -1; dy <= 1; dy++) {
        int yy = y + dy;
        if (yy < 0 || yy > 255) continue;
        const bf16* rowp = in + (((size_t)((b << 8) + yy) << 8) << 9);
        float va[6][2], vb[6][2];
        #pragma unroll
        for (int j = 0; j < 6; j++) {
            int xx = xs - 1 + j;
            if (xx >= 0 && xx <= 255) {
                const bf16* pp = rowp + ((size_t)xx << 9) + c2 * 2;
                uint32_t u1 = *(const uint32_t*)pp;
                uint32_t u2 = *(const uint32_t*)(pp + 256);
                float2 f1 = __bfloat1622float2(*(__nv_bfloat162*)&u1);
                float2 f2 = __bfloat1622float2(*(__nv_bfloat162*)&u2);
                va[j][0] = f1.x; va[j][1] = f1.y;
                vb[j][0] = f2.x; vb[j][1] = f2.y;
            } else {
                va[j][0] = 0.f; va[j][1] = 0.f;
                vb[j][0] = 0.f; vb[j][1] = 0.f;
            }
        }
        #pragma unroll
        for (int dx = 0; dx < 3; dx++) {
            int ki = (dy + 1) * 3 + dx;
            float2 k1 = *(const float2*)(kwp + ki * H2P + c2 * 2);
            float2 k2 = *(const float2*)(kwp + ki * H2P + 256 + c2 * 2);
            #pragma unroll
            for (int ox = 0; ox < 4; ox++) {
                accA[ox][0] += va[ox + dx][0] * k1.x;
                accA[ox][1] += va[ox + dx][1] * k1.y;
                accB[ox][0] += vb[ox + dx][0] * k2.x;
                accB[ox][1] += vb[ox + dx][1] * k2.y;
            }
        }
    }
    size_t pbase = (size_t)((b << 16) + (y << 8) + xs);
    #pragma unroll
    for (int ox = 0; ox < 4; ox++) {
        float g0 = gelu_exact(accA[ox][0]) * accB[ox][0];
        float g1 = gelu_exact(accA[ox][1]) * accB[ox][1];
        *(uint32_t*)(out + (pbase + ox) * HIDP + c2 * 2) = pack_bf2(g0, g1);
    }
}

// ---------------- launcher ----------------
extern "C" void kernel_launch(void* const* d_in, const int* in_sizes, int n_in,
                              void* d_out, int out_size) {
    const float* x     = (const float*)d_in[0];
    const float* ln1g  = (const float*)d_in[1];
    const float* ln1b  = (const float*)d_in[2];
    const float* ln2g  = (const float*)d_in[3];
    const float* ln2b  = (const float*)d_in[4];
    const float* qkvw  = (const float*)d_in[5];
    const float* qkvdw = (const float*)d_in[6];
    const float* temp  = (const float*)d_in[7];
    const float* aow   = (const float*)d_in[8];
    const float* fiw   = (const float*)d_in[9];
    const float* fdw   = (const float*)d_in[10];
    const float* fow   = (const float*)d_in[11];
    float* out = (float*)d_out;

    bf16 *t0, *t1, *t2, *gt, *ybf, *wq, *wa, *wip, *wo2;
    float *x2, *nrm, *att, *kwp;
    cudaGetSymbolAddress((void**)&t0,  g_t0);
    cudaGetSymbolAddress((void**)&t1,  g_t1);
    cudaGetSymbolAddress((void**)&t2,  g_t2);
    cudaGetSymbolAddress((void**)&gt,  g_gt);
    cudaGetSymbolAddress((void**)&ybf, g_ybf);
    cudaGetSymbolAddress((void**)&x2,  g_x2);
    cudaGetSymbolAddress((void**)&nrm, g_nrm);
    cudaGetSymbolAddress((void**)&att, g_att);
    cudaGetSymbolAddress((void**)&wq,  g_wq);
    cudaGetSymbolAddress((void**)&wa,  g_wa);
    cudaGetSymbolAddress((void**)&wip, g_wip);
    cudaGetSymbolAddress((void**)&wo2, g_wo2);
    cudaGetSymbolAddress((void**)&kwp, g_kwp);

    const int SMEM_FO = 2 * 128 * 72 * 2 + 256 * 104 * 2;            // 90112
    const int SMEM_QKV = 128 * 104 * 2 + 96 * (288 + 8) * 2;         // 83456
    const int SMEM_FFI = 128 * 104 * 2 + 96 * (256 + 8) * 2;         // 77312
    cudaFuncSetAttribute(gemm_ffnout, cudaFuncAttributeMaxDynamicSharedMemorySize, SMEM_FO);
    cudaFuncSetAttribute((gemm_bres<3, 6, true>),  cudaFuncAttributeMaxDynamicSharedMemorySize, SMEM_QKV);
    cudaFuncSetAttribute((gemm_bres<2, 8, false>), cudaFuncAttributeMaxDynamicSharedMemorySize, SMEM_FFI);

    const int cvt_total = CDIM * QKV + CDIM * CDIM + CDIM * H2P + HID * CDIM;
    cvt_all_kernel<<<(cvt_total + 255) / 256, 256>>>(qkvw, aow, fiw, fow, fdw,
                                                     wq, wa, wip, wo2, kwp, nrm, att);

    // attention branch: fused LN1 + qkv GEMM (B resident)
    gemm_bres<3, 6, true><<<dim3(1, 1024), 256, SMEM_QKV>>>(
        nullptr, x, ln1g, ln1b, wq, t0, QKV);
    dwconv288_kernel<<<(NPIX / 4) * 72 / 256, 256>>>(t0, qkvdw, t1);
    qkt_kernel<<<dim3(65536 / QKT_SPB, 4), 256>>>(t1, att, nrm);
    softmax_kernel<<<4, 64>>>(att, nrm, temp);
    attnapply_kernel<<<dim3(2048, 2), 256>>>(t1, att, ybf);
    // fused: x2 = ybf@wa + x ; ybf = LN2(x2)
    gemm_attnout_ln<<<1024, 256>>>(ybf, wa, x, x2, ybf, ln2g, ln2b);

    // FFN branch: B-resident ffn_in (2 column blocks of 256), remapped 512-col layout
    gemm_bres<2, 8, false><<<dim3(2, 1024), 256, SMEM_FFI>>>(
        ybf, nullptr, nullptr, nullptr, wip, t2, H2P);
    dwgate_kernel<<<(NPIX / 4) * 128 / 256, 256>>>(t2, kwp, gt);
    gemm_ffnout<<<1024, 256, SMEM_FO>>>(gt, wo2, x2, out);
}